// round 2
// baseline (speedup 1.0000x reference)
#include <cuda_runtime.h>
#include <math.h>

// Problem dims
#define BSZ 64
#define NAG 512
#define OBS 128
#define HID 256
#define MSG 128
#define NACT 16
#define ROWS (BSZ*NAG)   // 32768

// ---------------- scratch (device globals; no allocation allowed) ----------------
__device__ float g_encoded[(size_t)ROWS*HID];
__device__ float g_messages[(size_t)ROWS*MSG];
__device__ float g_Q[(size_t)ROWS*MSG];
__device__ float g_K[(size_t)ROWS*MSG];
__device__ float g_V[(size_t)ROWS*MSG];
__device__ float g_imp[ROWS];
__device__ float g_nrm[ROWS];
__device__ float g_scores[(size_t)BSZ*NAG*NAG];
__device__ float g_agg[(size_t)ROWS*MSG];
__device__ float g_comb[(size_t)ROWS*(HID+MSG)];
__device__ float g_x[(size_t)ROWS*HID];

// ---------------- generic tiled GEMM: C = act(A[M,K] @ B[K,N] + bias) ----------------
// 64x64 tile, BK=16, block (16,16), each thread 4x4. Optional batching via blockIdx.z.
#define TBM 64
#define TBN 64
#define TBK 16

__global__ void gemm_kernel(const float* __restrict__ A,
                            const float* __restrict__ B,
                            const float* __restrict__ bias,
                            float* __restrict__ C,
                            int M, int N, int K, int ldc,
                            long long sA, long long sB, long long sC,
                            int act /*0=none,1=relu*/)
{
    A += (long long)blockIdx.z * sA;
    B += (long long)blockIdx.z * sB;
    C += (long long)blockIdx.z * sC;

    __shared__ float As[TBK][TBM + 4];
    __shared__ float Bs[TBK][TBN + 4];

    const int tx = threadIdx.x, ty = threadIdx.y;
    const int tid = ty * 16 + tx;
    const int row0 = blockIdx.y * TBM;
    const int col0 = blockIdx.x * TBN;

    float acc[4][4] = {};

    for (int k0 = 0; k0 < K; k0 += TBK) {
        // load A tile: [TBM][TBK] -> As[c][r]
        #pragma unroll
        for (int i = tid; i < TBM * TBK; i += 256) {
            int r = i >> 4, c = i & 15;
            int gr = row0 + r;
            As[c][r] = (gr < M) ? A[(long long)gr * K + (k0 + c)] : 0.f;
        }
        // load B tile: [TBK][TBN] -> Bs[r][c]
        #pragma unroll
        for (int i = tid; i < TBK * TBN; i += 256) {
            int r = i >> 6, c = i & 63;
            int gc = col0 + c;
            Bs[r][c] = (gc < N) ? B[(long long)(k0 + r) * N + gc] : 0.f;
        }
        __syncthreads();

        #pragma unroll
        for (int kk = 0; kk < TBK; kk++) {
            float a[4], b[4];
            #pragma unroll
            for (int i = 0; i < 4; i++) a[i] = As[kk][ty * 4 + i];
            #pragma unroll
            for (int j = 0; j < 4; j++) b[j] = Bs[kk][tx * 4 + j];
            #pragma unroll
            for (int i = 0; i < 4; i++)
                #pragma unroll
                for (int j = 0; j < 4; j++)
                    acc[i][j] += a[i] * b[j];
        }
        __syncthreads();
    }

    #pragma unroll
    for (int i = 0; i < 4; i++) {
        int gr = row0 + ty * 4 + i;
        if (gr >= M) continue;
        #pragma unroll
        for (int j = 0; j < 4; j++) {
            int gc = col0 + tx * 4 + j;
            if (gc >= N) continue;
            float v = acc[i][j];
            if (bias) v += bias[gc];
            if (act == 1) v = fmaxf(v, 0.f);
            C[(long long)gr * ldc + gc] = v;
        }
    }
}

// ---------------- importance + obs norm (warp per row) ----------------
__global__ void impnorm_kernel(const float* __restrict__ enc,
                               const float* __restrict__ obs,
                               const float* __restrict__ Wi,
                               const float* __restrict__ bi,
                               float* __restrict__ imp,
                               float* __restrict__ nrm)
{
    int row = blockIdx.x * 8 + threadIdx.y;
    int lane = threadIdx.x;
    const float* e = enc + (long long)row * HID;
    const float* o = obs + (long long)row * OBS;
    float d = 0.f, ss = 0.f;
    #pragma unroll
    for (int i = 0; i < HID / 32; i++) d += e[lane + 32 * i] * Wi[lane + 32 * i];
    #pragma unroll
    for (int i = 0; i < OBS / 32; i++) { float v = o[lane + 32 * i]; ss += v * v; }
    #pragma unroll
    for (int off = 16; off; off >>= 1) {
        d  += __shfl_down_sync(0xffffffffu, d, off);
        ss += __shfl_down_sync(0xffffffffu, ss, off);
    }
    if (lane == 0) {
        imp[row] = 1.f / (1.f + expf(-(d + bi[0])));
        nrm[row] = sqrtf(ss);
    }
}

// ---------------- fused scores: S = QK^T/sqrt(128)*imp_q*imp_k + 0.5*cos_sim(obs) ----------------
__global__ void scores_kernel(const float* __restrict__ Q,
                              const float* __restrict__ Kf,
                              const float* __restrict__ obs,
                              const float* __restrict__ imp,
                              const float* __restrict__ nrm,
                              float* __restrict__ S)
{
    const int b = blockIdx.z;
    const float* Qb = Q   + (long long)b * NAG * MSG;
    const float* Kb = Kf  + (long long)b * NAG * MSG;
    const float* Ob = obs + (long long)b * NAG * OBS;
    float* Sb = S + (long long)b * NAG * NAG;

    const int row0 = blockIdx.y * 64;
    const int col0 = blockIdx.x * 64;
    const int tx = threadIdx.x, ty = threadIdx.y;
    const int tid = ty * 16 + tx;

    __shared__ float As[16][68];
    __shared__ float Bs[16][68];

    float aQK[4][4] = {};
    float aO[4][4]  = {};

    // phase 1: Q @ K^T
    for (int k0 = 0; k0 < MSG; k0 += 16) {
        #pragma unroll
        for (int i = tid; i < 64 * 16; i += 256) {
            int r = i >> 4, c = i & 15;
            As[c][r] = Qb[(long long)(row0 + r) * MSG + k0 + c];
        }
        #pragma unroll
        for (int i = tid; i < 64 * 16; i += 256) {
            int r = i >> 4, c = i & 15;
            Bs[c][r] = Kb[(long long)(col0 + r) * MSG + k0 + c];
        }
        __syncthreads();
        #pragma unroll
        for (int kk = 0; kk < 16; kk++) {
            float a[4], bb[4];
            #pragma unroll
            for (int i = 0; i < 4; i++) a[i] = As[kk][ty * 4 + i];
            #pragma unroll
            for (int j = 0; j < 4; j++) bb[j] = Bs[kk][tx * 4 + j];
            #pragma unroll
            for (int i = 0; i < 4; i++)
                #pragma unroll
                for (int j = 0; j < 4; j++)
                    aQK[i][j] += a[i] * bb[j];
        }
        __syncthreads();
    }

    // phase 2: obs @ obs^T
    for (int k0 = 0; k0 < OBS; k0 += 16) {
        #pragma unroll
        for (int i = tid; i < 64 * 16; i += 256) {
            int r = i >> 4, c = i & 15;
            As[c][r] = Ob[(long long)(row0 + r) * OBS + k0 + c];
        }
        #pragma unroll
        for (int i = tid; i < 64 * 16; i += 256) {
            int r = i >> 4, c = i & 15;
            Bs[c][r] = Ob[(long long)(col0 + r) * OBS + k0 + c];
        }
        __syncthreads();
        #pragma unroll
        for (int kk = 0; kk < 16; kk++) {
            float a[4], bb[4];
            #pragma unroll
            for (int i = 0; i < 4; i++) a[i] = As[kk][ty * 4 + i];
            #pragma unroll
            for (int j = 0; j < 4; j++) bb[j] = Bs[kk][tx * 4 + j];
            #pragma unroll
            for (int i = 0; i < 4; i++)
                #pragma unroll
                for (int j = 0; j < 4; j++)
                    aO[i][j] += a[i] * bb[j];
        }
        __syncthreads();
    }

    const float inv_sqrt = 0.08838834764831845f;  // 1/sqrt(128)
    float impR[4], impC[4], nR[4], nC[4];
    #pragma unroll
    for (int i = 0; i < 4; i++) {
        impR[i] = imp[b * NAG + row0 + ty * 4 + i];
        nR[i]   = nrm[b * NAG + row0 + ty * 4 + i] + 1e-8f;
    }
    #pragma unroll
    for (int j = 0; j < 4; j++) {
        impC[j] = imp[b * NAG + col0 + tx * 4 + j];
        nC[j]   = nrm[b * NAG + col0 + tx * 4 + j] + 1e-8f;
    }
    #pragma unroll
    for (int i = 0; i < 4; i++) {
        int q = row0 + ty * 4 + i;
        #pragma unroll
        for (int j = 0; j < 4; j++) {
            int k = col0 + tx * 4 + j;
            float v = aQK[i][j] * inv_sqrt * impR[i] * impC[j]
                    + 0.5f * aO[i][j] / (nR[i] * nC[j]);
            Sb[(long long)q * NAG + k] = v;
        }
    }
}

// ---------------- row softmax over 512 ----------------
__global__ void softmax_kernel(float* __restrict__ S)
{
    long long row = blockIdx.x;
    float* p = S + row * NAG;
    int t = threadIdx.x;  // 256
    float v0 = p[t], v1 = p[t + 256];

    __shared__ float red[256];
    red[t] = fmaxf(v0, v1);
    __syncthreads();
    for (int s = 128; s > 0; s >>= 1) {
        if (t < s) red[t] = fmaxf(red[t], red[t + s]);
        __syncthreads();
    }
    float m = red[0];
    __syncthreads();

    float e0 = expf(v0 - m), e1 = expf(v1 - m);
    red[t] = e0 + e1;
    __syncthreads();
    for (int s = 128; s > 0; s >>= 1) {
        if (t < s) red[t] += red[t + s];
        __syncthreads();
    }
    float inv = 1.f / red[0];
    p[t] = e0 * inv;
    p[t + 256] = e1 * inv;
}

// ---------------- concat [encoded | aggregated] ----------------
__global__ void concat_kernel(const float* __restrict__ enc,
                              const float* __restrict__ agg,
                              float* __restrict__ comb)
{
    long long i = (long long)blockIdx.x * blockDim.x + threadIdx.x;
    if (i >= (long long)ROWS * 384) return;
    long long row = i / 384;
    int c = (int)(i % 384);
    comb[i] = (c < 256) ? enc[row * 256 + c] : agg[row * 128 + (c - 256)];
}

// ---------------- head: logits (16) + value (1), warp per row ----------------
__global__ void head_kernel(const float* __restrict__ x,
                            const float* __restrict__ Wa,
                            const float* __restrict__ ba,
                            const float* __restrict__ Wcr,
                            const float* __restrict__ bcr,
                            float* __restrict__ out)
{
    int row = blockIdx.x * 8 + threadIdx.y;
    int lane = threadIdx.x;
    const float* xr = x + (long long)row * HID;
    float xv[8];
    #pragma unroll
    for (int i = 0; i < 8; i++) xv[i] = xr[lane + 32 * i];
    #pragma unroll
    for (int j = 0; j < 17; j++) {
        float p = 0.f;
        #pragma unroll
        for (int i = 0; i < 8; i++) {
            int k = lane + 32 * i;
            float w = (j < 16) ? Wa[(long long)k * NACT + j] : Wcr[k];
            p += xv[i] * w;
        }
        #pragma unroll
        for (int off = 16; off; off >>= 1) p += __shfl_down_sync(0xffffffffu, p, off);
        if (lane == 0) {
            if (j < 16) out[(long long)row * NACT + j] = p + ba[j];
            else        out[(long long)ROWS * NACT + row] = p + bcr[0];
        }
    }
}

// ---------------- launch ----------------
static inline void launch_gemm(const float* A, const float* B, const float* bias, float* C,
                               int M, int N, int K, int ldc,
                               long long sA, long long sB, long long sC, int batch, int act)
{
    dim3 grid((N + TBN - 1) / TBN, (M + TBM - 1) / TBM, batch);
    dim3 blk(16, 16);
    gemm_kernel<<<grid, blk>>>(A, B, bias, C, M, N, K, ldc, sA, sB, sC, act);
}

extern "C" void kernel_launch(void* const* d_in, const int* in_sizes, int n_in,
                              void* d_out, int out_size)
{
    const float* obs = (const float*)d_in[0];
    // d_in[1] = dones (unused)
    const float* We  = (const float*)d_in[2];   const float* be  = (const float*)d_in[3];
    const float* Wc  = (const float*)d_in[4];   const float* bc  = (const float*)d_in[5];
    const float* Wn  = (const float*)d_in[6];   const float* bn  = (const float*)d_in[7];
    const float* Wb  = (const float*)d_in[8];   const float* bb  = (const float*)d_in[9];
    const float* Wi  = (const float*)d_in[10];  const float* bi  = (const float*)d_in[11];
    const float* Wq  = (const float*)d_in[12];  const float* bq  = (const float*)d_in[13];
    const float* Wk  = (const float*)d_in[14];  const float* bk  = (const float*)d_in[15];
    const float* Wv  = (const float*)d_in[16];  const float* bv  = (const float*)d_in[17];
    const float* Wp  = (const float*)d_in[18];  const float* bp  = (const float*)d_in[19];
    const float* Wa  = (const float*)d_in[20];  const float* ba  = (const float*)d_in[21];
    const float* Wcr = (const float*)d_in[22];  const float* bcr = (const float*)d_in[23];
    float* out = (float*)d_out;

    float *enc, *msg, *Qb, *Kb, *Vb, *imp, *nrm, *sc, *agg, *comb, *xb;
    cudaGetSymbolAddress((void**)&enc,  g_encoded);
    cudaGetSymbolAddress((void**)&msg,  g_messages);
    cudaGetSymbolAddress((void**)&Qb,   g_Q);
    cudaGetSymbolAddress((void**)&Kb,   g_K);
    cudaGetSymbolAddress((void**)&Vb,   g_V);
    cudaGetSymbolAddress((void**)&imp,  g_imp);
    cudaGetSymbolAddress((void**)&nrm,  g_nrm);
    cudaGetSymbolAddress((void**)&sc,   g_scores);
    cudaGetSymbolAddress((void**)&agg,  g_agg);
    cudaGetSymbolAddress((void**)&comb, g_comb);
    cudaGetSymbolAddress((void**)&xb,   g_x);

    // 1. encoded = relu(obs @ We + be)
    launch_gemm(obs, We, be, enc, ROWS, HID, OBS, HID, 0, 0, 0, 1, 1);

    // 2-4. messages = [enc@Wc+bc | enc@Wn+bn | enc@Wb+bb]
    launch_gemm(enc, Wc, bc, msg + 0,  ROWS, 32, HID, MSG, 0, 0, 0, 1, 0);
    launch_gemm(enc, Wn, bn, msg + 32, ROWS, 64, HID, MSG, 0, 0, 0, 1, 0);
    launch_gemm(enc, Wb, bb, msg + 96, ROWS, 32, HID, MSG, 0, 0, 0, 1, 0);

    // 5. Q = enc @ Wq + bq
    launch_gemm(enc, Wq, bq, Qb, ROWS, MSG, HID, MSG, 0, 0, 0, 1, 0);

    // 6. importance + obs norms
    impnorm_kernel<<<ROWS / 8, dim3(32, 8)>>>(enc, obs, Wi, bi, imp, nrm);

    // 7-8. K, V from messages
    launch_gemm(msg, Wk, bk, Kb, ROWS, MSG, MSG, MSG, 0, 0, 0, 1, 0);
    launch_gemm(msg, Wv, bv, Vb, ROWS, MSG, MSG, MSG, 0, 0, 0, 1, 0);

    // 9. fused scores
    scores_kernel<<<dim3(NAG / 64, NAG / 64, BSZ), dim3(16, 16)>>>(Qb, Kb, obs, imp, nrm, sc);

    // 10. softmax
    softmax_kernel<<<ROWS, 256>>>(sc);

    // 11. aggregated = attn @ V (batched)
    launch_gemm(sc, Vb, nullptr, agg, NAG, MSG, NAG, MSG,
                (long long)NAG * NAG, (long long)NAG * MSG, (long long)NAG * MSG, BSZ, 0);

    // 12. combined = [enc | agg]
    {
        long long tot = (long long)ROWS * 384;
        concat_kernel<<<(unsigned)((tot + 255) / 256), 256>>>(enc, agg, comb);
    }

    // 13. x = relu(combined @ Wp + bp)
    launch_gemm(comb, Wp, bp, xb, ROWS, HID, HID + MSG, HID, 0, 0, 0, 1, 1);

    // 14. heads
    head_kernel<<<ROWS / 8, dim3(32, 8)>>>(xb, Wa, ba, Wcr, bcr, out);
}

// round 3
// speedup vs baseline: 1.7203x; 1.7203x over previous
#include <cuda_runtime.h>
#include <math.h>

// Problem dims
#define BSZ 64
#define NAG 512
#define OBS 128
#define HID 256
#define MSG 128
#define NACT 16
#define ROWS (BSZ*NAG)   // 32768

// ---------------- scratch (device globals) ----------------
__device__ float g_encoded[(size_t)ROWS*HID];
__device__ float g_msgq[(size_t)ROWS*256];     // cols 0-127 messages, 128-255 Q
__device__ float g_kv[(size_t)ROWS*256];       // cols 0-127 K, 128-255 V
__device__ float g_imp[ROWS];
__device__ float g_nrm[ROWS];
__device__ float g_scores[(size_t)BSZ*NAG*NAG];
__device__ float g_agg[(size_t)ROWS*MSG];
__device__ float g_x[(size_t)ROWS*HID];
__device__ float g_Wcat[256*256];
__device__ float g_bcat[256];
__device__ float g_Wkv[128*256];
__device__ float g_bkv[256];

// ---------------- f32x2 helpers ----------------
__device__ __forceinline__ unsigned long long pack2(float x){
    unsigned long long r; asm("mov.b64 %0, {%1, %1};" : "=l"(r) : "f"(x)); return r;
}
__device__ __forceinline__ float2 unpack2(unsigned long long v){
    float2 r; asm("mov.b64 {%0, %1}, %2;" : "=f"(r.x), "=f"(r.y) : "l"(v)); return r;
}
__device__ __forceinline__ void ffma2(unsigned long long &d, unsigned long long a, unsigned long long b){
    asm("fma.rn.f32x2 %0, %1, %2, %0;" : "+l"(d) : "l"(a), "l"(b));
}

// ---------------- weight packing ----------------
__global__ void pack_wcat(const float* __restrict__ Wc, const float* __restrict__ Wn,
                          const float* __restrict__ Wb, const float* __restrict__ Wq,
                          const float* __restrict__ bc, const float* __restrict__ bn,
                          const float* __restrict__ bb, const float* __restrict__ bq,
                          float* __restrict__ Wcat, float* __restrict__ bcat)
{
    int i = blockIdx.x * 256 + threadIdx.x;   // 256*256
    int r = i >> 8, c = i & 255;
    float v;
    if (c < 32)        v = Wc[r*32 + c];
    else if (c < 96)   v = Wn[r*64 + (c-32)];
    else if (c < 128)  v = Wb[r*32 + (c-96)];
    else               v = Wq[r*128 + (c-128)];
    Wcat[i] = v;
    if (r == 0) {
        float bvv;
        if (c < 32)       bvv = bc[c];
        else if (c < 96)  bvv = bn[c-32];
        else if (c < 128) bvv = bb[c-96];
        else              bvv = bq[c-128];
        bcat[c] = bvv;
    }
}

__global__ void pack_wkv(const float* __restrict__ Wk, const float* __restrict__ Wv,
                         const float* __restrict__ bk, const float* __restrict__ bv,
                         float* __restrict__ Wkv, float* __restrict__ bkv)
{
    int i = blockIdx.x * 256 + threadIdx.x;   // 128*256
    int r = i >> 8, c = i & 255;
    Wkv[i] = (c < 128) ? Wk[r*128 + c] : Wv[r*128 + (c-128)];
    if (r == 0) bkv[c] = (c < 128) ? bk[c] : bv[c-128];
}

// ---------------- 128x128x16 f32x2 GEMM with split-A, batching, bias+relu ----------------
#define BM 128
#define BN 128
#define BK 16
#define AST 132

__global__ __launch_bounds__(256, 2)
void gemm128(const float* __restrict__ A1, int lda1, int K1,
             const float* __restrict__ A2, int lda2, int K2,
             const float* __restrict__ B, int ldb,
             const float* __restrict__ bias,
             float* __restrict__ C, int ldc,
             long long sA1, long long sA2, long long sB, long long sC,
             int act)
{
    __shared__ float As[2][BK][AST];
    __shared__ float Bs[2][BK][BN];

    const int z = blockIdx.z;
    A1 += (long long)z * sA1;
    if (A2) A2 += (long long)z * sA2;
    B  += (long long)z * sB;
    C  += (long long)z * sC;

    const int row0 = blockIdx.y * BM;
    const int col0 = blockIdx.x * BN;
    const int tid = threadIdx.x;
    const int tx = tid & 15, ty = tid >> 4;
    const int T = (K1 + K2) / BK;

    const int ar = tid >> 2, ac4 = tid & 3;       // A loads: 2x (64 rows x 4 col-groups)
    const int br = tid >> 5, bc4 = tid & 31;      // B loads: 2x (8 rows x 32 col-groups)

    float4 pa[2], pb[2];

    auto fetch = [&](int t){
        int k0 = t * BK;
        #pragma unroll
        for (int u = 0; u < 2; u++){
            int r = ar + u*64;
            int gk = k0 + ac4*4;
            const float* src; int ld;
            if (gk < K1){ src = A1; ld = lda1; }
            else        { src = A2; ld = lda2; gk -= K1; }
            pa[u] = *(const float4*)(src + (long long)(row0 + r)*ld + gk);
            int rb = br + u*8;
            pb[u] = *(const float4*)(B + (long long)(k0 + rb)*ldb + col0 + bc4*4);
        }
    };
    auto stage = [&](int buf){
        #pragma unroll
        for (int u = 0; u < 2; u++){
            int r = ar + u*64;
            As[buf][ac4*4+0][r] = pa[u].x;
            As[buf][ac4*4+1][r] = pa[u].y;
            As[buf][ac4*4+2][r] = pa[u].z;
            As[buf][ac4*4+3][r] = pa[u].w;
            int rb = br + u*8;
            *(float4*)(&Bs[buf][rb][bc4*4]) = pb[u];
        }
    };

    unsigned long long acc[8][4];
    #pragma unroll
    for (int i = 0; i < 8; i++)
        #pragma unroll
        for (int j = 0; j < 4; j++) acc[i][j] = 0ull;

    fetch(0); stage(0); __syncthreads();
    for (int t = 0; t < T; t++){
        int cb = t & 1;
        if (t + 1 < T) fetch(t + 1);
        #pragma unroll
        for (int kk = 0; kk < BK; kk++){
            const float* asr = &As[cb][kk][ty*8];
            const float* bsr = &Bs[cb][kk][tx*8];
            float4 a0 = *(const float4*)(asr);
            float4 a1 = *(const float4*)(asr + 4);
            ulonglong2 b0 = *(const ulonglong2*)(bsr);
            ulonglong2 b1 = *(const ulonglong2*)(bsr + 4);
            unsigned long long bp[4] = {b0.x, b0.y, b1.x, b1.y};
            float av[8] = {a0.x,a0.y,a0.z,a0.w,a1.x,a1.y,a1.z,a1.w};
            #pragma unroll
            for (int i = 0; i < 8; i++){
                unsigned long long ap = pack2(av[i]);
                #pragma unroll
                for (int j = 0; j < 4; j++) ffma2(acc[i][j], ap, bp[j]);
            }
        }
        if (t + 1 < T) stage((t + 1) & 1);
        __syncthreads();
    }

    float bv[8];
    #pragma unroll
    for (int j = 0; j < 8; j++) bv[j] = bias ? bias[col0 + tx*8 + j] : 0.f;

    #pragma unroll
    for (int i = 0; i < 8; i++){
        long long gr = row0 + ty*8 + i;
        float o[8];
        #pragma unroll
        for (int j = 0; j < 4; j++){
            float2 v = unpack2(acc[i][j]);
            o[2*j]   = v.x + bv[2*j];
            o[2*j+1] = v.y + bv[2*j+1];
        }
        if (act){
            #pragma unroll
            for (int j = 0; j < 8; j++) o[j] = fmaxf(o[j], 0.f);
        }
        float4* cp = (float4*)(C + gr*ldc + col0 + tx*8);
        cp[0] = make_float4(o[0],o[1],o[2],o[3]);
        cp[1] = make_float4(o[4],o[5],o[6],o[7]);
    }
}

// ---------------- fused scores: scaling folded into smem loads, one accumulator ----------------
__global__ __launch_bounds__(256, 2)
void scores128(const float* __restrict__ Qm,   // g_msgq + 128, ld 256
               const float* __restrict__ Km,   // g_kv, ld 256
               const float* __restrict__ obs,  // ld 128
               const float* __restrict__ imp,
               const float* __restrict__ nrm,
               float* __restrict__ S)
{
    __shared__ float As[2][BK][AST];
    __shared__ float Bs[2][BK][AST];

    const int b = blockIdx.z;
    const int row0 = blockIdx.y * BM;
    const int col0 = blockIdx.x * BN;
    const int tid = threadIdx.x;
    const int tx = tid & 15, ty = tid >> 4;
    const int ar = tid >> 2, ac4 = tid & 3;
    const long long base = (long long)b * NAG;
    const int T = 16;  // 8 tiles QK + 8 tiles obs

    float4 pa[2], pb[2];
    float sa[2], sb[2];

    auto fetch = [&](int t){
        int k0 = t * BK;
        #pragma unroll
        for (int u = 0; u < 2; u++){
            int rA = row0 + ar + u*64;
            int rB = col0 + ar + u*64;
            int gk = k0 + ac4*4;
            if (gk < 128){
                pa[u] = *(const float4*)(Qm + (base + rA)*256 + gk);
                pb[u] = *(const float4*)(Km + (base + rB)*256 + gk);
                sa[u] = imp[base + rA] * 0.08838834764831845f;  // 1/sqrt(128)
                sb[u] = imp[base + rB];
            } else {
                pa[u] = *(const float4*)(obs + (base + rA)*128 + (gk - 128));
                pb[u] = *(const float4*)(obs + (base + rB)*128 + (gk - 128));
                sa[u] = 0.7071067811865476f / (nrm[base + rA] + 1e-8f);  // sqrt(0.5)
                sb[u] = 0.7071067811865476f / (nrm[base + rB] + 1e-8f);
            }
        }
    };
    auto stage = [&](int buf){
        #pragma unroll
        for (int u = 0; u < 2; u++){
            int r = ar + u*64;
            As[buf][ac4*4+0][r] = pa[u].x * sa[u];
            As[buf][ac4*4+1][r] = pa[u].y * sa[u];
            As[buf][ac4*4+2][r] = pa[u].z * sa[u];
            As[buf][ac4*4+3][r] = pa[u].w * sa[u];
            Bs[buf][ac4*4+0][r] = pb[u].x * sb[u];
            Bs[buf][ac4*4+1][r] = pb[u].y * sb[u];
            Bs[buf][ac4*4+2][r] = pb[u].z * sb[u];
            Bs[buf][ac4*4+3][r] = pb[u].w * sb[u];
        }
    };

    unsigned long long acc[8][4];
    #pragma unroll
    for (int i = 0; i < 8; i++)
        #pragma unroll
        for (int j = 0; j < 4; j++) acc[i][j] = 0ull;

    fetch(0); stage(0); __syncthreads();
    for (int t = 0; t < T; t++){
        int cb = t & 1;
        if (t + 1 < T) fetch(t + 1);
        #pragma unroll
        for (int kk = 0; kk < BK; kk++){
            const float* asr = &As[cb][kk][ty*8];
            const float* bsr = &Bs[cb][kk][tx*8];
            float4 a0 = *(const float4*)(asr);
            float4 a1 = *(const float4*)(asr + 4);
            ulonglong2 b0 = *(const ulonglong2*)(bsr);
            ulonglong2 b1 = *(const ulonglong2*)(bsr + 4);
            unsigned long long bp[4] = {b0.x, b0.y, b1.x, b1.y};
            float av[8] = {a0.x,a0.y,a0.z,a0.w,a1.x,a1.y,a1.z,a1.w};
            #pragma unroll
            for (int i = 0; i < 8; i++){
                unsigned long long ap = pack2(av[i]);
                #pragma unroll
                for (int j = 0; j < 4; j++) ffma2(acc[i][j], ap, bp[j]);
            }
        }
        if (t + 1 < T) stage((t + 1) & 1);
        __syncthreads();
    }

    float* Sb = S + (long long)b * NAG * NAG;
    #pragma unroll
    for (int i = 0; i < 8; i++){
        long long gr = row0 + ty*8 + i;
        float o[8];
        #pragma unroll
        for (int j = 0; j < 4; j++){
            float2 v = unpack2(acc[i][j]);
            o[2*j] = v.x; o[2*j+1] = v.y;
        }
        float4* cp = (float4*)(Sb + gr*NAG + col0 + tx*8);
        cp[0] = make_float4(o[0],o[1],o[2],o[3]);
        cp[1] = make_float4(o[4],o[5],o[6],o[7]);
    }
}

// ---------------- importance + obs norm (warp per row) ----------------
__global__ void impnorm_kernel(const float* __restrict__ enc,
                               const float* __restrict__ obs,
                               const float* __restrict__ Wi,
                               const float* __restrict__ bi,
                               float* __restrict__ imp,
                               float* __restrict__ nrm)
{
    int row = blockIdx.x * 8 + threadIdx.y;
    int lane = threadIdx.x;
    const float* e = enc + (long long)row * HID;
    const float* o = obs + (long long)row * OBS;
    float d = 0.f, ss = 0.f;
    #pragma unroll
    for (int i = 0; i < HID / 32; i++) d += e[lane + 32*i] * Wi[lane + 32*i];
    #pragma unroll
    for (int i = 0; i < OBS / 32; i++) { float v = o[lane + 32*i]; ss += v*v; }
    #pragma unroll
    for (int off = 16; off; off >>= 1) {
        d  += __shfl_down_sync(0xffffffffu, d, off);
        ss += __shfl_down_sync(0xffffffffu, ss, off);
    }
    if (lane == 0) {
        imp[row] = 1.f / (1.f + expf(-(d + bi[0])));
        nrm[row] = sqrtf(ss);
    }
}

// ---------------- row softmax over 512 (warp shuffles) ----------------
__global__ void softmax_kernel(float* __restrict__ S)
{
    long long row = blockIdx.x;
    float* p = S + row * NAG;
    int t = threadIdx.x;  // 256
    float v0 = p[t], v1 = p[t + 256];

    float m = fmaxf(v0, v1);
    #pragma unroll
    for (int o = 16; o; o >>= 1) m = fmaxf(m, __shfl_xor_sync(0xffffffffu, m, o));
    __shared__ float sm[8], ssum[8];
    int w = t >> 5, l = t & 31;
    if (l == 0) sm[w] = m;
    __syncthreads();
    m = sm[0];
    #pragma unroll
    for (int i = 1; i < 8; i++) m = fmaxf(m, sm[i]);

    float e0 = __expf(v0 - m), e1 = __expf(v1 - m);
    float s = e0 + e1;
    #pragma unroll
    for (int o = 16; o; o >>= 1) s += __shfl_xor_sync(0xffffffffu, s, o);
    if (l == 0) ssum[w] = s;
    __syncthreads();
    s = ssum[0];
    #pragma unroll
    for (int i = 1; i < 8; i++) s += ssum[i];

    float inv = 1.f / s;
    p[t] = e0 * inv;
    p[t + 256] = e1 * inv;
}

// ---------------- head: logits (16) + value (1), warp per row ----------------
__global__ void head_kernel(const float* __restrict__ x,
                            const float* __restrict__ Wa,
                            const float* __restrict__ ba,
                            const float* __restrict__ Wcr,
                            const float* __restrict__ bcr,
                            float* __restrict__ out)
{
    int row = blockIdx.x * 8 + threadIdx.y;
    int lane = threadIdx.x;
    const float* xr = x + (long long)row * HID;
    float xv[8];
    #pragma unroll
    for (int i = 0; i < 8; i++) xv[i] = xr[lane + 32*i];
    #pragma unroll
    for (int j = 0; j < 17; j++) {
        float p = 0.f;
        #pragma unroll
        for (int i = 0; i < 8; i++) {
            int k = lane + 32*i;
            float w = (j < 16) ? Wa[(long long)k * NACT + j] : Wcr[k];
            p += xv[i] * w;
        }
        #pragma unroll
        for (int off = 16; off; off >>= 1) p += __shfl_down_sync(0xffffffffu, p, off);
        if (lane == 0) {
            if (j < 16) out[(long long)row * NACT + j] = p + ba[j];
            else        out[(long long)ROWS * NACT + row] = p + bcr[0];
        }
    }
}

// ---------------- launch ----------------
extern "C" void kernel_launch(void* const* d_in, const int* in_sizes, int n_in,
                              void* d_out, int out_size)
{
    const float* obs = (const float*)d_in[0];
    const float* We  = (const float*)d_in[2];   const float* be  = (const float*)d_in[3];
    const float* Wc  = (const float*)d_in[4];   const float* bc  = (const float*)d_in[5];
    const float* Wn  = (const float*)d_in[6];   const float* bn  = (const float*)d_in[7];
    const float* Wb  = (const float*)d_in[8];   const float* bb  = (const float*)d_in[9];
    const float* Wi  = (const float*)d_in[10];  const float* bi  = (const float*)d_in[11];
    const float* Wq  = (const float*)d_in[12];  const float* bq  = (const float*)d_in[13];
    const float* Wk  = (const float*)d_in[14];  const float* bk  = (const float*)d_in[15];
    const float* Wv  = (const float*)d_in[16];  const float* bv  = (const float*)d_in[17];
    const float* Wp  = (const float*)d_in[18];  const float* bp  = (const float*)d_in[19];
    const float* Wa  = (const float*)d_in[20];  const float* ba  = (const float*)d_in[21];
    const float* Wcr = (const float*)d_in[22];  const float* bcr = (const float*)d_in[23];
    float* out = (float*)d_out;

    float *enc, *msgq, *kv, *imp, *nrm, *sc, *agg, *xb, *Wcat, *bcat, *Wkv, *bkv;
    cudaGetSymbolAddress((void**)&enc,  g_encoded);
    cudaGetSymbolAddress((void**)&msgq, g_msgq);
    cudaGetSymbolAddress((void**)&kv,   g_kv);
    cudaGetSymbolAddress((void**)&imp,  g_imp);
    cudaGetSymbolAddress((void**)&nrm,  g_nrm);
    cudaGetSymbolAddress((void**)&sc,   g_scores);
    cudaGetSymbolAddress((void**)&agg,  g_agg);
    cudaGetSymbolAddress((void**)&xb,   g_x);
    cudaGetSymbolAddress((void**)&Wcat, g_Wcat);
    cudaGetSymbolAddress((void**)&bcat, g_bcat);
    cudaGetSymbolAddress((void**)&Wkv,  g_Wkv);
    cudaGetSymbolAddress((void**)&bkv,  g_bkv);

    // 0. pack combined weights
    pack_wcat<<<256, 256>>>(Wc, Wn, Wb, Wq, bc, bn, bb, bq, Wcat, bcat);
    pack_wkv<<<128, 256>>>(Wk, Wv, bk, bv, Wkv, bkv);

    // 1. encoded = relu(obs @ We + be)   [32768,128]x[128,256]
    gemm128<<<dim3(2, 256, 1), 256>>>(obs, OBS, OBS, nullptr, 0, 0,
                                      We, HID, be, enc, HID, 0, 0, 0, 0, 1);

    // 2. importance + obs norms
    impnorm_kernel<<<ROWS / 8, dim3(32, 8)>>>(enc, obs, Wi, bi, imp, nrm);

    // 3. msgq = enc @ [Wc|Wn|Wb|Wq] + bcat   [32768,256]x[256,256]
    gemm128<<<dim3(2, 256, 1), 256>>>(enc, HID, HID, nullptr, 0, 0,
                                      Wcat, 256, bcat, msgq, 256, 0, 0, 0, 0, 0);

    // 4. kv = messages @ [Wk|Wv] + bkv   [32768,128]x[128,256]  (messages = msgq cols 0..127)
    gemm128<<<dim3(2, 256, 1), 256>>>(msgq, 256, MSG, nullptr, 0, 0,
                                      Wkv, 256, bkv, kv, 256, 0, 0, 0, 0, 0);

    // 5. fused scores (scaling folded into loads)
    scores128<<<dim3(4, 4, BSZ), 256>>>(msgq + 128, kv, obs, imp, nrm, sc);

    // 6. softmax
    softmax_kernel<<<ROWS, 256>>>(sc);

    // 7. aggregated = attn @ V (batched)   [512,512]x[512,128] x64
    gemm128<<<dim3(1, 4, BSZ), 256>>>(sc, NAG, NAG, nullptr, 0, 0,
                                      kv + 128, 256, nullptr, agg, MSG,
                                      (long long)NAG * NAG, 0, (long long)NAG * 256,
                                      (long long)NAG * MSG, 0);

    // 8. x = relu(enc @ Wp_top + agg @ Wp_bot + bp)  (split-A, no concat)
    gemm128<<<dim3(2, 256, 1), 256>>>(enc, HID, HID, agg, MSG, MSG,
                                      Wp, HID, bp, xb, HID, 0, 0, 0, 0, 1);

    // 9. heads
    head_kernel<<<ROWS / 8, dim3(32, 8)>>>(xb, Wa, ba, Wcr, bcr, out);
}

// round 5
// speedup vs baseline: 2.1077x; 1.2252x over previous
#include <cuda_runtime.h>
#include <cuda_bf16.h>
#include <stdint.h>
#include <math.h>

// Problem dims
#define BSZ 64
#define NAG 512
#define OBS 128
#define HID 256
#define MSG 128
#define NACT 16
#define ROWS (BSZ*NAG)   // 32768

// ---------------- scratch (device globals) ----------------
__device__ float g_encoded[(size_t)ROWS*HID];
__device__ float g_msgq[(size_t)ROWS*256];     // cols 0-127 messages, 128-255 Q
__device__ float g_kv[(size_t)ROWS*256];       // cols 0-127 K, 128-255 V
__device__ float g_imp[ROWS];
__device__ float g_nrm[ROWS];
__device__ float g_scores[(size_t)BSZ*NAG*NAG];
__device__ float g_agg[(size_t)ROWS*MSG];
__device__ float g_x[(size_t)ROWS*HID];
__device__ float g_bcat[256];
__device__ float g_bkv[256];
// packed transposed bf16 weights [N][K], hi/lo split
__device__ __nv_bfloat16 g_WeT_h[256*128],  g_WeT_l[256*128];
__device__ __nv_bfloat16 g_WcatT_h[256*256],g_WcatT_l[256*256];
__device__ __nv_bfloat16 g_WkvT_h[256*128], g_WkvT_l[256*128];
__device__ __nv_bfloat16 g_WpT_h[256*384],  g_WpT_l[256*384];
__device__ __nv_bfloat16 g_vT_h[(size_t)BSZ*128*512], g_vT_l[(size_t)BSZ*128*512];

// smem byte offsets inside dynamic smem (each tile: 128 rows x 64 k bf16 = 16KB)
#define S_A_HI 0
#define S_A_LO 16384
#define S_B_HI 32768
#define S_B_LO 49152
#define SMEM_DYN 65536

__device__ __forceinline__ void bsplit(float x, __nv_bfloat16& h, __nv_bfloat16& l){
    h = __float2bfloat16(x);
    l = __float2bfloat16(x - __bfloat162float(h));
}

// swizzled smem word load: tile layout [r][k], 128 B/row, XOR swizzle on bytes 4-6 by row
__device__ __forceinline__ uint32_t lds32(const char* sm, int r, int k){
    uint32_t off = (uint32_t)(r*128 + k*2);
    uint32_t sw = off ^ ((off >> 3) & 0x70u);
    return *(const uint32_t*)(sm + sw);
}

__device__ __forceinline__ void mma16816(float* d, const uint32_t* a, const uint32_t* b){
    asm volatile(
        "mma.sync.aligned.m16n8k16.row.col.f32.bf16.bf16.f32 "
        "{%0,%1,%2,%3}, {%4,%5,%6,%7}, {%8,%9}, {%0,%1,%2,%3};"
        : "+f"(d[0]), "+f"(d[1]), "+f"(d[2]), "+f"(d[3])
        : "r"(a[0]), "r"(a[1]), "r"(a[2]), "r"(a[3]), "r"(b[0]), "r"(b[1]));
}

// stage fp32 [128 rows][64 k] -> bf16 hi/lo swizzled tiles (256 threads, optional row scale)
__device__ __forceinline__ void stage_f32(char* sm, int offH, int offL,
                                          const float* src, int ld, int row0, int k0, float scale)
{
    int tid = threadIdx.x;
    int r = tid >> 1, c0 = (tid & 1) * 32;
    const float* p = src + (long long)(row0 + r) * ld + k0 + c0;
    #pragma unroll
    for (int j = 0; j < 8; j++){
        float4 v = *(const float4*)(p + 4*j);
        v.x *= scale; v.y *= scale; v.z *= scale; v.w *= scale;
        __nv_bfloat16 h0,h1,h2,h3,l0,l1,l2,l3;
        bsplit(v.x,h0,l0); bsplit(v.y,h1,l1); bsplit(v.z,h2,l2); bsplit(v.w,h3,l3);
        uint32_t off = r*128 + (c0 + 4*j)*2;
        uint32_t sw = off ^ ((off>>3)&0x70);
        __nv_bfloat162 a0; a0.x=h0; a0.y=h1;
        __nv_bfloat162 a1; a1.x=h2; a1.y=h3;
        __nv_bfloat162 b0; b0.x=l0; b0.y=l1;
        __nv_bfloat162 b1; b1.x=l2; b1.y=l3;
        *(__nv_bfloat162*)(sm + offH + sw)     = a0;
        *(__nv_bfloat162*)(sm + offH + sw + 4) = a1;
        *(__nv_bfloat162*)(sm + offL + sw)     = b0;
        *(__nv_bfloat162*)(sm + offL + sw + 4) = b1;
    }
}

// stage prepacked bf16 [128 rows][64 k] -> swizzled tile
__device__ __forceinline__ void stage_bf16(char* sm, int soff,
                                           const __nv_bfloat16* src, int ldb, int n0, int k0)
{
    int tid = threadIdx.x;
    int r = tid >> 1, u0 = (tid & 1) * 4;
    const uint4* p = (const uint4*)((const char*)(src + (long long)(n0 + r)*ldb + k0) + (size_t)u0*16);
    #pragma unroll
    for (int j = 0; j < 4; j++){
        uint4 v = p[j];
        uint32_t off = r*128 + (u0 + j)*16;
        uint32_t sw = off ^ ((off>>3)&0x70);
        *(uint4*)(sm + soff + sw) = v;
    }
}

// compute one 64-wide K chunk from staged tiles; warp computes 64x32 of 128x128 block
__device__ __forceinline__ void mma_chunk(const char* smc, float acc[4][4][4], int wm, int wn, int lane)
{
    const int lq = lane >> 2;      // 0..7
    const int le = (lane & 3) * 2; // 0,2,4,6
    #pragma unroll
    for (int ks = 0; ks < 4; ks++){
        const int k0 = ks * 16;
        uint32_t ah[4][4], al[4][4], bh[4][2], bl[4][2];
        #pragma unroll
        for (int mt = 0; mt < 4; mt++){
            int r0 = wm*64 + mt*16;
            ah[mt][0] = lds32(smc + S_A_HI, r0 + lq,     k0 + le);
            ah[mt][1] = lds32(smc + S_A_HI, r0 + 8 + lq, k0 + le);
            ah[mt][2] = lds32(smc + S_A_HI, r0 + lq,     k0 + 8 + le);
            ah[mt][3] = lds32(smc + S_A_HI, r0 + 8 + lq, k0 + 8 + le);
            al[mt][0] = lds32(smc + S_A_LO, r0 + lq,     k0 + le);
            al[mt][1] = lds32(smc + S_A_LO, r0 + 8 + lq, k0 + le);
            al[mt][2] = lds32(smc + S_A_LO, r0 + lq,     k0 + 8 + le);
            al[mt][3] = lds32(smc + S_A_LO, r0 + 8 + lq, k0 + 8 + le);
        }
        #pragma unroll
        for (int nt = 0; nt < 4; nt++){
            int n0 = wn*32 + nt*8;
            bh[nt][0] = lds32(smc + S_B_HI, n0 + lq, k0 + le);
            bh[nt][1] = lds32(smc + S_B_HI, n0 + lq, k0 + 8 + le);
            bl[nt][0] = lds32(smc + S_B_LO, n0 + lq, k0 + le);
            bl[nt][1] = lds32(smc + S_B_LO, n0 + lq, k0 + 8 + le);
        }
        #pragma unroll
        for (int mt = 0; mt < 4; mt++)
            #pragma unroll
            for (int nt = 0; nt < 4; nt++){
                mma16816(acc[mt][nt], ah[mt], bh[nt]);
                mma16816(acc[mt][nt], ah[mt], bl[nt]);
                mma16816(acc[mt][nt], al[mt], bh[nt]);
            }
    }
}

__device__ __forceinline__ void epilogue_reg(float acc[4][4][4], float* C, int ldc,
                                             int row0, int col0, const float* bias, int act,
                                             int wm, int wn, int lane)
{
    const int lq = lane >> 2;
    const int le = (lane & 3) * 2;
    #pragma unroll
    for (int mt = 0; mt < 4; mt++){
        long long gr = row0 + wm*64 + mt*16 + lq;
        #pragma unroll
        for (int nt = 0; nt < 4; nt++){
            int gc = col0 + wn*32 + nt*8 + le;
            float b0 = bias ? bias[gc]   : 0.f;
            float b1 = bias ? bias[gc+1] : 0.f;
            float2 v0, v1;
            v0.x = acc[mt][nt][0] + b0; v0.y = acc[mt][nt][1] + b1;
            v1.x = acc[mt][nt][2] + b0; v1.y = acc[mt][nt][3] + b1;
            if (act){
                v0.x = fmaxf(v0.x, 0.f); v0.y = fmaxf(v0.y, 0.f);
                v1.x = fmaxf(v1.x, 0.f); v1.y = fmaxf(v1.y, 0.f);
            }
            *(float2*)(C + gr*ldc + gc)     = v0;
            *(float2*)(C + (gr+8)*ldc + gc) = v1;
        }
    }
}

// ---------------- generic mma GEMM: C = act(A @ B^T + bias) ----------------
// A fp32 (split A1/A2 along K), B prepacked bf16 hi/lo [N][K]. Batch via blockIdx.z.
__global__ __launch_bounds__(256, 1)
void mm_gemm(const float* __restrict__ A1, int lda1, int K1,
             const float* __restrict__ A2, int lda2, int Ktot,
             const __nv_bfloat16* __restrict__ Bhi, const __nv_bfloat16* __restrict__ Blo, int ldb,
             const float* __restrict__ bias, float* __restrict__ C, int ldc,
             long long sA1, long long sB, long long sC, int act)
{
    extern __shared__ char smc[];
    const int tid = threadIdx.x, wid = tid >> 5, lane = tid & 31;
    const int wm = wid >> 2, wn = wid & 3;
    const int z = blockIdx.z;
    A1  += (long long)z * sA1;
    Bhi += (long long)z * sB;
    Blo += (long long)z * sB;
    C   += (long long)z * sC;

    const int row0 = blockIdx.y * 128;
    const int col0 = blockIdx.x * 128;
    const int T = Ktot / 64;

    float acc[4][4][4];
    #pragma unroll
    for (int i = 0; i < 4; i++)
        #pragma unroll
        for (int j = 0; j < 4; j++)
            #pragma unroll
            for (int k = 0; k < 4; k++) acc[i][j][k] = 0.f;

    for (int t = 0; t < T; t++){
        int k0 = t * 64;
        const float* As; int lda, ka;
        if (k0 < K1){ As = A1; lda = lda1; ka = k0; }
        else        { As = A2; lda = lda2; ka = k0 - K1; }
        stage_f32(smc, S_A_HI, S_A_LO, As, lda, row0, ka, 1.0f);
        stage_bf16(smc, S_B_HI, Bhi, ldb, col0, k0);
        stage_bf16(smc, S_B_LO, Blo, ldb, col0, k0);
        __syncthreads();
        mma_chunk(smc, acc, wm, wn, lane);
        __syncthreads();
    }

    epilogue_reg(acc, C, ldc, row0, col0, bias, act, wm, wn, lane);
}

// ---------------- fused scores: scaling folded into bf16 conversion ----------------
__global__ __launch_bounds__(256, 1)
void mm_scores(const float* __restrict__ Qm,   // g_msgq + 128, ld 256
               const float* __restrict__ Km,   // g_kv, ld 256
               const float* __restrict__ obs,  // ld 128
               const float* __restrict__ imp,
               const float* __restrict__ nrm,
               float* __restrict__ S)
{
    extern __shared__ char smc[];
    const int tid = threadIdx.x, wid = tid >> 5, lane = tid & 31;
    const int wm = wid >> 2, wn = wid & 3;
    const int b = blockIdx.z;
    const long long base = (long long)b * NAG;
    const int row0 = blockIdx.y * 128;
    const int col0 = blockIdx.x * 128;
    const int r = tid >> 1;

    float acc[4][4][4];
    #pragma unroll
    for (int i = 0; i < 4; i++)
        #pragma unroll
        for (int j = 0; j < 4; j++)
            #pragma unroll
            for (int k = 0; k < 4; k++) acc[i][j][k] = 0.f;

    for (int t = 0; t < 4; t++){
        const float *As, *Bs; int ld, k0; float sA, sB2;
        if (t < 2){
            As = Qm + base * 256; Bs = Km + base * 256; ld = 256; k0 = t * 64;
            sA  = imp[base + row0 + r] * 0.08838834764831845f;  // 1/sqrt(128)
            sB2 = imp[base + col0 + r];
        } else {
            As = obs + base * 128; Bs = obs + base * 128; ld = 128; k0 = (t - 2) * 64;
            sA  = 0.7071067811865476f / (nrm[base + row0 + r] + 1e-8f);  // sqrt(0.5)
            sB2 = 0.7071067811865476f / (nrm[base + col0 + r] + 1e-8f);
        }
        stage_f32(smc, S_A_HI, S_A_LO, As, ld, row0, k0, sA);
        stage_f32(smc, S_B_HI, S_B_LO, Bs, ld, col0, k0, sB2);
        __syncthreads();
        mma_chunk(smc, acc, wm, wn, lane);
        __syncthreads();
    }

    epilogue_reg(acc, S + (long long)b * NAG * NAG, NAG, row0, col0, nullptr, 0, wm, wn, lane);
}

// ---------------- weight pack kernels (fp32 [K,N] -> bf16 hi/lo [N,K]) ----------------
__global__ void pack_we(const float* __restrict__ We,
                        __nv_bfloat16* __restrict__ hi, __nv_bfloat16* __restrict__ lo)
{
    int i = blockIdx.x * 256 + threadIdx.x;  // 256*128
    int n = i >> 7, k = i & 127;
    float v = We[k * 256 + n];
    __nv_bfloat16 h, l; bsplit(v, h, l);
    hi[i] = h; lo[i] = l;
}
__global__ void pack_wcat(const float* __restrict__ Wc, const float* __restrict__ Wn,
                          const float* __restrict__ Wb, const float* __restrict__ Wq,
                          const float* __restrict__ bc, const float* __restrict__ bn,
                          const float* __restrict__ bbp, const float* __restrict__ bq,
                          __nv_bfloat16* __restrict__ hi, __nv_bfloat16* __restrict__ lo,
                          float* __restrict__ bcat)
{
    int i = blockIdx.x * 256 + threadIdx.x;  // 256*256
    int n = i >> 8, k = i & 255;
    float v;
    if (n < 32)       v = Wc[k*32 + n];
    else if (n < 96)  v = Wn[k*64 + (n-32)];
    else if (n < 128) v = Wb[k*32 + (n-96)];
    else              v = Wq[k*128 + (n-128)];
    __nv_bfloat16 h, l; bsplit(v, h, l);
    hi[i] = h; lo[i] = l;
    if (k == 0)
        bcat[n] = (n < 32) ? bc[n] : (n < 96) ? bn[n-32] : (n < 128) ? bbp[n-96] : bq[n-128];
}
__global__ void pack_wkv(const float* __restrict__ Wk, const float* __restrict__ Wv,
                         const float* __restrict__ bk, const float* __restrict__ bv,
                         __nv_bfloat16* __restrict__ hi, __nv_bfloat16* __restrict__ lo,
                         float* __restrict__ bkv)
{
    int i = blockIdx.x * 256 + threadIdx.x;  // 256*128
    int n = i >> 7, k = i & 127;
    float v = (n < 128) ? Wk[k*128 + n] : Wv[k*128 + (n-128)];
    __nv_bfloat16 h, l; bsplit(v, h, l);
    hi[i] = h; lo[i] = l;
    if (k == 0) bkv[n] = (n < 128) ? bk[n] : bv[n-128];
}
__global__ void pack_wp(const float* __restrict__ Wp,
                        __nv_bfloat16* __restrict__ hi, __nv_bfloat16* __restrict__ lo)
{
    int i = blockIdx.x * 256 + threadIdx.x;  // 256*384
    int n = i / 384, k = i % 384;
    float v = Wp[k * 256 + n];
    __nv_bfloat16 h, l; bsplit(v, h, l);
    hi[i] = h; lo[i] = l;
}

// ---------------- V transpose+split: kv cols [128,256) -> vT [b][d][k] bf16 hi/lo ----------------
__global__ void pack_vT(const float* __restrict__ kv,
                        __nv_bfloat16* __restrict__ hi, __nv_bfloat16* __restrict__ lo)
{
    __shared__ float t[32][33];
    int b = blockIdx.z;
    int k0 = blockIdx.x * 32, d0 = blockIdx.y * 32;
    for (int i = threadIdx.y; i < 32; i += 8)
        t[i][threadIdx.x] = kv[((long long)(b*512 + k0 + i))*256 + 128 + d0 + threadIdx.x];
    __syncthreads();
    for (int i = threadIdx.y; i < 32; i += 8){
        float v = t[threadIdx.x][i];
        __nv_bfloat16 h, l; bsplit(v, h, l);
        long long o = ((long long)(b*128 + d0 + i))*512 + k0 + threadIdx.x;
        hi[o] = h; lo[o] = l;
    }
}

// ---------------- importance + obs norm ----------------
__global__ void impnorm_kernel(const float* __restrict__ enc,
                               const float* __restrict__ obs,
                               const float* __restrict__ Wi,
                               const float* __restrict__ bi,
                               float* __restrict__ imp,
                               float* __restrict__ nrm)
{
    int row = blockIdx.x * 8 + threadIdx.y;
    int lane = threadIdx.x;
    const float* e = enc + (long long)row * HID;
    const float* o = obs + (long long)row * OBS;
    float d = 0.f, ss = 0.f;
    #pragma unroll
    for (int i = 0; i < HID/32; i++) d += e[lane + 32*i] * Wi[lane + 32*i];
    #pragma unroll
    for (int i = 0; i < OBS/32; i++){ float v = o[lane + 32*i]; ss += v*v; }
    #pragma unroll
    for (int off = 16; off; off >>= 1){
        d  += __shfl_down_sync(0xffffffffu, d, off);
        ss += __shfl_down_sync(0xffffffffu, ss, off);
    }
    if (lane == 0){
        imp[row] = 1.f / (1.f + expf(-(d + bi[0])));
        nrm[row] = sqrtf(ss);
    }
}

// ---------------- row softmax over 512 ----------------
__global__ void softmax_kernel(float* __restrict__ S)
{
    long long row = blockIdx.x;
    float* p = S + row * NAG;
    int t = threadIdx.x;  // 256
    float v0 = p[t], v1 = p[t + 256];

    float m = fmaxf(v0, v1);
    #pragma unroll
    for (int o = 16; o; o >>= 1) m = fmaxf(m, __shfl_xor_sync(0xffffffffu, m, o));
    __shared__ float sm[8], ssum[8];
    int w = t >> 5, l = t & 31;
    if (l == 0) sm[w] = m;
    __syncthreads();
    m = sm[0];
    #pragma unroll
    for (int i = 1; i < 8; i++) m = fmaxf(m, sm[i]);

    float e0 = __expf(v0 - m), e1 = __expf(v1 - m);
    float s = e0 + e1;
    #pragma unroll
    for (int o = 16; o; o >>= 1) s += __shfl_xor_sync(0xffffffffu, s, o);
    if (l == 0) ssum[w] = s;
    __syncthreads();
    s = ssum[0];
    #pragma unroll
    for (int i = 1; i < 8; i++) s += ssum[i];

    float inv = 1.f / s;
    p[t] = e0 * inv;
    p[t + 256] = e1 * inv;
}

// ---------------- head ----------------
__global__ void head_kernel(const float* __restrict__ x,
                            const float* __restrict__ Wa,
                            const float* __restrict__ ba,
                            const float* __restrict__ Wcr,
                            const float* __restrict__ bcr,
                            float* __restrict__ out)
{
    int row = blockIdx.x * 8 + threadIdx.y;
    int lane = threadIdx.x;
    const float* xr = x + (long long)row * HID;
    float xv[8];
    #pragma unroll
    for (int i = 0; i < 8; i++) xv[i] = xr[lane + 32*i];
    #pragma unroll
    for (int j = 0; j < 17; j++){
        float p = 0.f;
        #pragma unroll
        for (int i = 0; i < 8; i++){
            int k = lane + 32*i;
            float w = (j < 16) ? Wa[(long long)k * NACT + j] : Wcr[k];
            p += xv[i] * w;
        }
        #pragma unroll
        for (int off = 16; off; off >>= 1) p += __shfl_down_sync(0xffffffffu, p, off);
        if (lane == 0){
            if (j < 16) out[(long long)row * NACT + j] = p + ba[j];
            else        out[(long long)ROWS * NACT + row] = p + bcr[0];
        }
    }
}

// ---------------- launch ----------------
extern "C" void kernel_launch(void* const* d_in, const int* in_sizes, int n_in,
                              void* d_out, int out_size)
{
    const float* obs = (const float*)d_in[0];
    const float* We  = (const float*)d_in[2];   const float* be  = (const float*)d_in[3];
    const float* Wc  = (const float*)d_in[4];   const float* bc  = (const float*)d_in[5];
    const float* Wn  = (const float*)d_in[6];   const float* bn  = (const float*)d_in[7];
    const float* Wb  = (const float*)d_in[8];   const float* bbp = (const float*)d_in[9];
    const float* Wi  = (const float*)d_in[10];  const float* bi  = (const float*)d_in[11];
    const float* Wq  = (const float*)d_in[12];  const float* bq  = (const float*)d_in[13];
    const float* Wk  = (const float*)d_in[14];  const float* bk  = (const float*)d_in[15];
    const float* Wv  = (const float*)d_in[16];  const float* bv  = (const float*)d_in[17];
    const float* Wp  = (const float*)d_in[18];  const float* bp  = (const float*)d_in[19];
    const float* Wa  = (const float*)d_in[20];  const float* ba  = (const float*)d_in[21];
    const float* Wcr = (const float*)d_in[22];  const float* bcr = (const float*)d_in[23];
    float* out = (float*)d_out;

    float *enc, *msgq, *kv, *imp, *nrm, *sc, *agg, *xb, *bcat, *bkv;
    __nv_bfloat16 *WeTh, *WeTl, *WcTh, *WcTl, *WkvTh, *WkvTl, *WpTh, *WpTl, *vTh, *vTl;
    cudaGetSymbolAddress((void**)&enc,  g_encoded);
    cudaGetSymbolAddress((void**)&msgq, g_msgq);
    cudaGetSymbolAddress((void**)&kv,   g_kv);
    cudaGetSymbolAddress((void**)&imp,  g_imp);
    cudaGetSymbolAddress((void**)&nrm,  g_nrm);
    cudaGetSymbolAddress((void**)&sc,   g_scores);
    cudaGetSymbolAddress((void**)&agg,  g_agg);
    cudaGetSymbolAddress((void**)&xb,   g_x);
    cudaGetSymbolAddress((void**)&bcat, g_bcat);
    cudaGetSymbolAddress((void**)&bkv,  g_bkv);
    cudaGetSymbolAddress((void**)&WeTh, g_WeT_h);   cudaGetSymbolAddress((void**)&WeTl, g_WeT_l);
    cudaGetSymbolAddress((void**)&WcTh, g_WcatT_h); cudaGetSymbolAddress((void**)&WcTl, g_WcatT_l);
    cudaGetSymbolAddress((void**)&WkvTh, g_WkvT_h); cudaGetSymbolAddress((void**)&WkvTl, g_WkvT_l);
    cudaGetSymbolAddress((void**)&WpTh, g_WpT_h);   cudaGetSymbolAddress((void**)&WpTl, g_WpT_l);
    cudaGetSymbolAddress((void**)&vTh,  g_vT_h);    cudaGetSymbolAddress((void**)&vTl,  g_vT_l);

    cudaFuncSetAttribute(mm_gemm,   cudaFuncAttributeMaxDynamicSharedMemorySize, SMEM_DYN);
    cudaFuncSetAttribute(mm_scores, cudaFuncAttributeMaxDynamicSharedMemorySize, SMEM_DYN);

    // 0. pack weights (transposed bf16 hi/lo)
    pack_we  <<<128, 256>>>(We, WeTh, WeTl);
    pack_wcat<<<256, 256>>>(Wc, Wn, Wb, Wq, bc, bn, bbp, bq, WcTh, WcTl, bcat);
    pack_wkv <<<128, 256>>>(Wk, Wv, bk, bv, WkvTh, WkvTl, bkv);
    pack_wp  <<<384, 256>>>(Wp, WpTh, WpTl);

    // 1. encoded = relu(obs @ We + be)
    mm_gemm<<<dim3(2, 256, 1), 256, SMEM_DYN>>>(obs, OBS, OBS, nullptr, 0, OBS,
                                                WeTh, WeTl, OBS, be, enc, HID, 0, 0, 0, 1);

    // 2. importance + obs norms
    impnorm_kernel<<<ROWS/8, dim3(32, 8)>>>(enc, obs, Wi, bi, imp, nrm);

    // 3. msgq = enc @ [Wc|Wn|Wb|Wq] + bcat
    mm_gemm<<<dim3(2, 256, 1), 256, SMEM_DYN>>>(enc, HID, HID, nullptr, 0, HID,
                                                WcTh, WcTl, HID, bcat, msgq, 256, 0, 0, 0, 0);

    // 4. kv = messages @ [Wk|Wv] + bkv
    mm_gemm<<<dim3(2, 256, 1), 256, SMEM_DYN>>>(msgq, 256, MSG, nullptr, 0, MSG,
                                                WkvTh, WkvTl, MSG, bkv, kv, 256, 0, 0, 0, 0);

    // 5. V transpose+split for attn@V
    pack_vT<<<dim3(16, 4, BSZ), dim3(32, 8)>>>(kv, vTh, vTl);

    // 6. fused scores
    mm_scores<<<dim3(4, 4, BSZ), 256, SMEM_DYN>>>(msgq + 128, kv, obs, imp, nrm, sc);

    // 7. softmax
    softmax_kernel<<<ROWS, 256>>>(sc);

    // 8. aggregated = attn @ V (batched)
    mm_gemm<<<dim3(1, 4, BSZ), 256, SMEM_DYN>>>(sc, NAG, NAG, nullptr, 0, NAG,
                                                vTh, vTl, NAG, nullptr, agg, MSG,
                                                (long long)NAG*NAG, (long long)128*512,
                                                (long long)NAG*MSG, 0);

    // 9. x = relu(enc @ Wp_top + agg @ Wp_bot + bp)
    mm_gemm<<<dim3(2, 256, 1), 256, SMEM_DYN>>>(enc, HID, HID, agg, MSG, HID + MSG,
                                                WpTh, WpTl, HID + MSG, bp, xb, HID, 0, 0, 0, 1);

    // 10. heads
    head_kernel<<<ROWS/8, dim3(32, 8)>>>(xb, Wa, ba, Wcr, bcr, out);
}

// round 6
// speedup vs baseline: 2.4960x; 1.1842x over previous
#include <cuda_runtime.h>
#include <cuda_bf16.h>
#include <stdint.h>
#include <math.h>

#define BSZ 64
#define NAG 512
#define OBS 128
#define HID 256
#define MSG 128
#define NACT 16
#define ROWS (BSZ*NAG)   // 32768

// ---------------- scratch (device globals) ----------------
__device__ __align__(16) __nv_bfloat16 g_enc_h[(size_t)ROWS*HID],  g_enc_l[(size_t)ROWS*HID];
__device__ __align__(16) __nv_bfloat16 g_msgq_h[(size_t)ROWS*256], g_msgq_l[(size_t)ROWS*256]; // 0-127 msg, 128-255 Q(scaled)
__device__ __align__(16) __nv_bfloat16 g_ks_h[(size_t)ROWS*MSG],   g_ks_l[(size_t)ROWS*MSG];   // K scaled by imp
__device__ float g_v[(size_t)ROWS*MSG];
__device__ __align__(16) __nv_bfloat16 g_obs_h[(size_t)ROWS*OBS],  g_obs_l[(size_t)ROWS*OBS];
__device__ __align__(16) __nv_bfloat16 g_obss_h[(size_t)ROWS*OBS], g_obss_l[(size_t)ROWS*OBS]; // scaled sqrt(.5)/nrm
__device__ float g_imp[ROWS];
__device__ float g_nrm[ROWS];
__device__ float g_scores[(size_t)BSZ*NAG*NAG];
__device__ __align__(16) __nv_bfloat16 g_attn_h[(size_t)BSZ*NAG*NAG], g_attn_l[(size_t)BSZ*NAG*NAG];
__device__ __align__(16) __nv_bfloat16 g_vT_h[(size_t)BSZ*MSG*NAG],   g_vT_l[(size_t)BSZ*MSG*NAG];
__device__ __align__(16) __nv_bfloat16 g_agg_h[(size_t)ROWS*MSG],  g_agg_l[(size_t)ROWS*MSG];
__device__ float g_x[(size_t)ROWS*HID];
__device__ float g_bcat[256];
__device__ float g_bkv[256];
__device__ __align__(16) __nv_bfloat16 g_WeT_h[256*128],  g_WeT_l[256*128];
__device__ __align__(16) __nv_bfloat16 g_WcatT_h[256*256],g_WcatT_l[256*256];
__device__ __align__(16) __nv_bfloat16 g_WkvT_h[256*128], g_WkvT_l[256*128];
__device__ __align__(16) __nv_bfloat16 g_WpT_h[256*384],  g_WpT_l[256*384];

// ---------------- helpers ----------------
__device__ __forceinline__ void bsplit(float x, __nv_bfloat16& h, __nv_bfloat16& l){
    h = __float2bfloat16(x);
    l = __float2bfloat16(x - __bfloat162float(h));
}
__device__ __forceinline__ uint32_t smem_u32(const void* p){
    uint32_t a;
    asm("{ .reg .u64 t; cvta.to.shared.u64 t, %1; cvt.u32.u64 %0, t; }" : "=r"(a) : "l"(p));
    return a;
}
__device__ __forceinline__ void cpa16(uint32_t d, const void* s){
    asm volatile("cp.async.cg.shared.global [%0], [%1], 16;" :: "r"(d), "l"(s));
}
__device__ __forceinline__ void cpa_commit(){ asm volatile("cp.async.commit_group;" ::: "memory"); }
__device__ __forceinline__ void cpa_wait1(){ asm volatile("cp.async.wait_group 1;" ::: "memory"); }
__device__ __forceinline__ void cpa_wait0(){ asm volatile("cp.async.wait_group 0;" ::: "memory"); }
__device__ __forceinline__ void ldsm4(uint32_t* r, uint32_t a){
    asm volatile("ldmatrix.sync.aligned.m8n8.x4.shared.b16 {%0,%1,%2,%3}, [%4];"
        : "=r"(r[0]), "=r"(r[1]), "=r"(r[2]), "=r"(r[3]) : "r"(a));
}
__device__ __forceinline__ void mma16816(float* d, const uint32_t* a, const uint32_t* b){
    asm volatile(
        "mma.sync.aligned.m16n8k16.row.col.f32.bf16.bf16.f32 "
        "{%0,%1,%2,%3}, {%4,%5,%6,%7}, {%8,%9}, {%0,%1,%2,%3};"
        : "+f"(d[0]), "+f"(d[1]), "+f"(d[2]), "+f"(d[3])
        : "r"(a[0]), "r"(a[1]), "r"(a[2]), "r"(a[3]), "r"(b[0]), "r"(b[1]));
}

// stage one [128 rows][64 k] bf16 tile with SW128 swizzle via cp.async (256 threads)
__device__ __forceinline__ void stage_tile(uint32_t smA, const __nv_bfloat16* g, int ld,
                                           int row0, int k0, int tid)
{
    int r = tid >> 1, s0 = (tid & 1) * 4;
    const __nv_bfloat16* src = g + (long long)(row0 + r) * ld + k0 + s0 * 8;
    uint32_t offb = (uint32_t)(r * 128 + s0 * 16);
    #pragma unroll
    for (int j = 0; j < 4; j++){
        uint32_t off = offb + j * 16;
        uint32_t sw = off ^ ((off >> 3) & 0x70u);
        cpa16(smA + sw, src + j * 8);
    }
}

// mma on one staged chunk (A/B hi+lo tiles at sm+0/16384/32768/49152); 3 passes
__device__ __forceinline__ void mma_chunk(uint32_t sm, float acc[4][4][4], int wm, int wn, int lane)
{
    const int arow = ((lane >> 3) & 1) * 8 + (lane & 7);
    const int ak8  = ((lane >> 4) & 1) * 8;
    const int brow = ((lane >> 4) & 1) * 8 + (lane & 7);
    const int bk8  = ((lane >> 3) & 1) * 8;
    #pragma unroll
    for (int ks = 0; ks < 4; ks++){
        const int k0 = ks * 16;
        uint32_t ah[4][4], al[4][4], bh[4][2], bl[4][2], t4[4];
        #pragma unroll
        for (int mt = 0; mt < 4; mt++){
            uint32_t off = (uint32_t)((wm*64 + mt*16 + arow) * 128 + (k0 + ak8) * 2);
            uint32_t sw = off ^ ((off >> 3) & 0x70u);
            ldsm4(ah[mt], sm + 0     + sw);
            ldsm4(al[mt], sm + 16384 + sw);
        }
        #pragma unroll
        for (int np = 0; np < 2; np++){
            uint32_t off = (uint32_t)((wn*32 + np*16 + brow) * 128 + (k0 + bk8) * 2);
            uint32_t sw = off ^ ((off >> 3) & 0x70u);
            ldsm4(t4, sm + 32768 + sw);
            bh[np*2][0]=t4[0]; bh[np*2][1]=t4[1]; bh[np*2+1][0]=t4[2]; bh[np*2+1][1]=t4[3];
            ldsm4(t4, sm + 49152 + sw);
            bl[np*2][0]=t4[0]; bl[np*2][1]=t4[1]; bl[np*2+1][0]=t4[2]; bl[np*2+1][1]=t4[3];
        }
        #pragma unroll
        for (int mt = 0; mt < 4; mt++)
            #pragma unroll
            for (int nt = 0; nt < 4; nt++){
                mma16816(acc[mt][nt], ah[mt], bh[nt]);
                mma16816(acc[mt][nt], ah[mt], bl[nt]);
                mma16816(acc[mt][nt], al[mt], bh[nt]);
            }
    }
}

// per-colblock output descriptor
struct OutD {
    float* f;                 // fp32 out (or null)
    __nv_bfloat16* h;         // bf16 hi out (or null)
    __nv_bfloat16* l;         // bf16 lo out
    const float* rowscale;    // null -> 1 (non-batched only)
    float factor;
    int ldc;
    int colsub;
    int relu;
    long long sC;             // batch stride for outputs
};

__device__ __forceinline__ void epi(float acc[4][4][4], const OutD& od, const float* bias,
                                    int row0, int col0, int z, int wm, int wn, int lane)
{
    const int lq = lane >> 2, le = (lane & 3) * 2;
    #pragma unroll
    for (int mt = 0; mt < 4; mt++){
        int gr0 = row0 + wm*64 + mt*16 + lq;
        float rs0 = od.rowscale ? od.rowscale[gr0]   * od.factor : od.factor;
        float rs1 = od.rowscale ? od.rowscale[gr0+8] * od.factor : od.factor;
        #pragma unroll
        for (int nt = 0; nt < 4; nt++){
            int gc = col0 + wn*32 + nt*8 + le;
            float b0 = bias ? bias[gc] : 0.f, b1 = bias ? bias[gc+1] : 0.f;
            float v00 = (acc[mt][nt][0] + b0) * rs0, v01 = (acc[mt][nt][1] + b1) * rs0;
            float v10 = (acc[mt][nt][2] + b0) * rs1, v11 = (acc[mt][nt][3] + b1) * rs1;
            if (od.relu){
                v00 = fmaxf(v00, 0.f); v01 = fmaxf(v01, 0.f);
                v10 = fmaxf(v10, 0.f); v11 = fmaxf(v11, 0.f);
            }
            long long i0 = od.sC * z + (long long)gr0 * od.ldc + (gc - od.colsub);
            long long i1 = od.sC * z + (long long)(gr0 + 8) * od.ldc + (gc - od.colsub);
            if (od.f){
                *(float2*)(od.f + i0) = make_float2(v00, v01);
                *(float2*)(od.f + i1) = make_float2(v10, v11);
            }
            if (od.h){
                __nv_bfloat162 ph, pl;
                bsplit(v00, ph.x, pl.x); bsplit(v01, ph.y, pl.y);
                *(__nv_bfloat162*)(od.h + i0) = ph; *(__nv_bfloat162*)(od.l + i0) = pl;
                bsplit(v10, ph.x, pl.x); bsplit(v11, ph.y, pl.y);
                *(__nv_bfloat162*)(od.h + i1) = ph; *(__nv_bfloat162*)(od.l + i1) = pl;
            }
        }
    }
}

#define SMEM_DYN 131072   // 2 stages x (A h/l + B h/l) x 16KB

// ---------------- generic bf16 hi/lo GEMM: C = epi(A @ B^T) ----------------
__global__ __launch_bounds__(256, 1)
void bf_gemm(const __nv_bfloat16* __restrict__ Ah1, const __nv_bfloat16* __restrict__ Al1, int lda1, int K1,
             const __nv_bfloat16* __restrict__ Ah2, const __nv_bfloat16* __restrict__ Al2, int lda2, int Ktot,
             const __nv_bfloat16* __restrict__ Bh,  const __nv_bfloat16* __restrict__ Bl,  int ldb,
             const float* __restrict__ bias, long long sA1, long long sB,
             OutD o0, OutD o1)
{
    extern __shared__ __align__(1024) char smraw[];
    const uint32_t smb = smem_u32(smraw);
    const int tid = threadIdx.x, wid = tid >> 5, lane = tid & 31;
    const int wm = wid >> 2, wn = wid & 3;
    const int row0 = blockIdx.y * 128, col0 = blockIdx.x * 128;
    const int z = blockIdx.z;
    Ah1 += (long long)z * sA1; Al1 += (long long)z * sA1;
    Bh  += (long long)z * sB;  Bl  += (long long)z * sB;

    float acc[4][4][4];
    #pragma unroll
    for (int i = 0; i < 4; i++)
        #pragma unroll
        for (int j = 0; j < 4; j++)
            #pragma unroll
            for (int k = 0; k < 4; k++) acc[i][j][k] = 0.f;

    const int T = Ktot / 64;
    auto do_stage = [&](int t, int buf){
        int k0 = t * 64;
        const __nv_bfloat16 *h, *l; int ld, ka;
        if (k0 < K1){ h = Ah1; l = Al1; ld = lda1; ka = k0; }
        else        { h = Ah2; l = Al2; ld = lda2; ka = k0 - K1; }
        uint32_t sb = smb + buf * 65536;
        stage_tile(sb + 0,     h,  ld,  row0, ka, tid);
        stage_tile(sb + 16384, l,  ld,  row0, ka, tid);
        stage_tile(sb + 32768, Bh, ldb, col0, k0, tid);
        stage_tile(sb + 49152, Bl, ldb, col0, k0, tid);
        cpa_commit();
    };

    do_stage(0, 0);
    for (int t = 0; t < T; t++){
        if (t + 1 < T){ do_stage(t + 1, (t + 1) & 1); cpa_wait1(); }
        else          { cpa_wait0(); }
        __syncthreads();
        mma_chunk(smb + (t & 1) * 65536, acc, wm, wn, lane);
        __syncthreads();
    }

    const OutD& od = (blockIdx.x == 0) ? o0 : o1;
    epi(acc, od, bias, row0, col0, z, wm, wn, lane);
}

// ---------------- scores GEMM: S = Qs·Ks^T + obss·obss^T (all scaling pre-folded) ----------------
__global__ __launch_bounds__(256, 1)
void bf_scores(const __nv_bfloat16* __restrict__ Qh, const __nv_bfloat16* __restrict__ Ql,   // +128 offset, ld 256
               const __nv_bfloat16* __restrict__ Kh, const __nv_bfloat16* __restrict__ Kl,   // ld 128
               const __nv_bfloat16* __restrict__ Oh, const __nv_bfloat16* __restrict__ Ol,   // ld 128
               float* __restrict__ S)
{
    extern __shared__ __align__(1024) char smraw[];
    const uint32_t smb = smem_u32(smraw);
    const int tid = threadIdx.x, wid = tid >> 5, lane = tid & 31;
    const int wm = wid >> 2, wn = wid & 3;
    const int b = blockIdx.z;
    const int row0 = blockIdx.y * 128, col0 = blockIdx.x * 128;
    const int gr = b * NAG;

    float acc[4][4][4];
    #pragma unroll
    for (int i = 0; i < 4; i++)
        #pragma unroll
        for (int j = 0; j < 4; j++)
            #pragma unroll
            for (int k = 0; k < 4; k++) acc[i][j][k] = 0.f;

    auto do_stage = [&](int t, int buf){
        uint32_t sb = smb + buf * 65536;
        if (t < 2){
            stage_tile(sb + 0,     Qh, 256, gr + row0, t*64, tid);
            stage_tile(sb + 16384, Ql, 256, gr + row0, t*64, tid);
            stage_tile(sb + 32768, Kh, 128, gr + col0, t*64, tid);
            stage_tile(sb + 49152, Kl, 128, gr + col0, t*64, tid);
        } else {
            stage_tile(sb + 0,     Oh, 128, gr + row0, (t-2)*64, tid);
            stage_tile(sb + 16384, Ol, 128, gr + row0, (t-2)*64, tid);
            stage_tile(sb + 32768, Oh, 128, gr + col0, (t-2)*64, tid);
            stage_tile(sb + 49152, Ol, 128, gr + col0, (t-2)*64, tid);
        }
        cpa_commit();
    };

    do_stage(0, 0);
    for (int t = 0; t < 4; t++){
        if (t + 1 < 4){ do_stage(t + 1, (t + 1) & 1); cpa_wait1(); }
        else          { cpa_wait0(); }
        __syncthreads();
        mma_chunk(smb + (t & 1) * 65536, acc, wm, wn, lane);
        __syncthreads();
    }

    float* Sb = S + (long long)b * NAG * NAG;
    const int lq = lane >> 2, le = (lane & 3) * 2;
    #pragma unroll
    for (int mt = 0; mt < 4; mt++){
        long long r0 = row0 + wm*64 + mt*16 + lq;
        #pragma unroll
        for (int nt = 0; nt < 4; nt++){
            int gc = col0 + wn*32 + nt*8 + le;
            *(float2*)(Sb + r0*NAG + gc)     = make_float2(acc[mt][nt][0], acc[mt][nt][1]);
            *(float2*)(Sb + (r0+8)*NAG + gc) = make_float2(acc[mt][nt][2], acc[mt][nt][3]);
        }
    }
}

// ---------------- packing kernels ----------------
__global__ void pack_obs(const float* __restrict__ obs,
                         __nv_bfloat16* __restrict__ h, __nv_bfloat16* __restrict__ l)
{
    long long i = (long long)blockIdx.x * 256 + threadIdx.x;
    __nv_bfloat16 hh, ll; bsplit(obs[i], hh, ll);
    h[i] = hh; l[i] = ll;
}
__global__ void pack_obss(const float* __restrict__ obs, const float* __restrict__ nrm,
                          __nv_bfloat16* __restrict__ h, __nv_bfloat16* __restrict__ l)
{
    long long i = (long long)blockIdx.x * 256 + threadIdx.x;
    int row = (int)(i >> 7);
    float s = 0.7071067811865476f / (nrm[row] + 1e-8f);
    __nv_bfloat16 hh, ll; bsplit(obs[i] * s, hh, ll);
    h[i] = hh; l[i] = ll;
}
__global__ void pack_we(const float* __restrict__ We,
                        __nv_bfloat16* __restrict__ hi, __nv_bfloat16* __restrict__ lo)
{
    int i = blockIdx.x * 256 + threadIdx.x;
    int n = i >> 7, k = i & 127;
    __nv_bfloat16 h, l; bsplit(We[k*256 + n], h, l);
    hi[i] = h; lo[i] = l;
}
__global__ void pack_wcat(const float* __restrict__ Wc, const float* __restrict__ Wn,
                          const float* __restrict__ Wb, const float* __restrict__ Wq,
                          const float* __restrict__ bc, const float* __restrict__ bn,
                          const float* __restrict__ bbp, const float* __restrict__ bq,
                          __nv_bfloat16* __restrict__ hi, __nv_bfloat16* __restrict__ lo,
                          float* __restrict__ bcat)
{
    int i = blockIdx.x * 256 + threadIdx.x;
    int n = i >> 8, k = i & 255;
    float v;
    if (n < 32)       v = Wc[k*32 + n];
    else if (n < 96)  v = Wn[k*64 + (n-32)];
    else if (n < 128) v = Wb[k*32 + (n-96)];
    else              v = Wq[k*128 + (n-128)];
    __nv_bfloat16 h, l; bsplit(v, h, l);
    hi[i] = h; lo[i] = l;
    if (k == 0)
        bcat[n] = (n < 32) ? bc[n] : (n < 96) ? bn[n-32] : (n < 128) ? bbp[n-96] : bq[n-128];
}
__global__ void pack_wkv(const float* __restrict__ Wk, const float* __restrict__ Wv,
                         const float* __restrict__ bk, const float* __restrict__ bv,
                         __nv_bfloat16* __restrict__ hi, __nv_bfloat16* __restrict__ lo,
                         float* __restrict__ bkv)
{
    int i = blockIdx.x * 256 + threadIdx.x;
    int n = i >> 7, k = i & 127;
    float v = (n < 128) ? Wk[k*128 + n] : Wv[k*128 + (n-128)];
    __nv_bfloat16 h, l; bsplit(v, h, l);
    hi[i] = h; lo[i] = l;
    if (k == 0) bkv[n] = (n < 128) ? bk[n] : bv[n-128];
}
__global__ void pack_wp(const float* __restrict__ Wp,
                        __nv_bfloat16* __restrict__ hi, __nv_bfloat16* __restrict__ lo)
{
    int i = blockIdx.x * 256 + threadIdx.x;
    int n = i / 384, k = i % 384;
    __nv_bfloat16 h, l; bsplit(Wp[k*256 + n], h, l);
    hi[i] = h; lo[i] = l;
}

// V transpose+split: g_v [b*512+k][128] -> vT [b][d][k] bf16 hi/lo
__global__ void pack_vT(const float* __restrict__ v,
                        __nv_bfloat16* __restrict__ hi, __nv_bfloat16* __restrict__ lo)
{
    __shared__ float t[32][33];
    int b = blockIdx.z;
    int k0 = blockIdx.x * 32, d0 = blockIdx.y * 32;
    for (int i = threadIdx.y; i < 32; i += 8)
        t[i][threadIdx.x] = v[((long long)(b*512 + k0 + i))*128 + d0 + threadIdx.x];
    __syncthreads();
    for (int i = threadIdx.y; i < 32; i += 8){
        __nv_bfloat16 h, l; bsplit(t[threadIdx.x][i], h, l);
        long long o = ((long long)(b*128 + d0 + i))*512 + k0 + threadIdx.x;
        hi[o] = h; lo[o] = l;
    }
}

// ---------------- importance + obs norm (enc from hi/lo) ----------------
__global__ void impnorm_kernel(const __nv_bfloat16* __restrict__ eh,
                               const __nv_bfloat16* __restrict__ el,
                               const float* __restrict__ obs,
                               const float* __restrict__ Wi,
                               const float* __restrict__ bi,
                               float* __restrict__ imp,
                               float* __restrict__ nrm)
{
    int row = blockIdx.x * 8 + threadIdx.y;
    int lane = threadIdx.x;
    const __nv_bfloat16* ph = eh + (long long)row * HID;
    const __nv_bfloat16* pl = el + (long long)row * HID;
    const float* o = obs + (long long)row * OBS;
    float d = 0.f, ss = 0.f;
    #pragma unroll
    for (int i = 0; i < HID/32; i++){
        int k = lane + 32*i;
        float e = __bfloat162float(ph[k]) + __bfloat162float(pl[k]);
        d += e * Wi[k];
    }
    #pragma unroll
    for (int i = 0; i < OBS/32; i++){ float v = o[lane + 32*i]; ss += v*v; }
    #pragma unroll
    for (int off = 16; off; off >>= 1){
        d  += __shfl_down_sync(0xffffffffu, d, off);
        ss += __shfl_down_sync(0xffffffffu, ss, off);
    }
    if (lane == 0){
        imp[row] = 1.f / (1.f + expf(-(d + bi[0])));
        nrm[row] = sqrtf(ss);
    }
}

// ---------------- softmax over 512; writes attn bf16 hi/lo ----------------
__global__ void softmax_kernel(const float* __restrict__ S,
                               __nv_bfloat16* __restrict__ ah, __nv_bfloat16* __restrict__ al)
{
    long long row = blockIdx.x;
    const float* p = S + row * NAG;
    int t = threadIdx.x;  // 256
    float v0 = p[t], v1 = p[t + 256];

    float m = fmaxf(v0, v1);
    #pragma unroll
    for (int o = 16; o; o >>= 1) m = fmaxf(m, __shfl_xor_sync(0xffffffffu, m, o));
    __shared__ float sm[8], ssum[8];
    int w = t >> 5, l = t & 31;
    if (l == 0) sm[w] = m;
    __syncthreads();
    m = sm[0];
    #pragma unroll
    for (int i = 1; i < 8; i++) m = fmaxf(m, sm[i]);

    float e0 = __expf(v0 - m), e1 = __expf(v1 - m);
    float s = e0 + e1;
    #pragma unroll
    for (int o = 16; o; o >>= 1) s += __shfl_xor_sync(0xffffffffu, s, o);
    if (l == 0) ssum[w] = s;
    __syncthreads();
    s = ssum[0];
    #pragma unroll
    for (int i = 1; i < 8; i++) s += ssum[i];

    float inv = 1.f / s;
    __nv_bfloat16 h, lo;
    bsplit(e0 * inv, h, lo); ah[row*NAG + t] = h;       al[row*NAG + t] = lo;
    bsplit(e1 * inv, h, lo); ah[row*NAG + t + 256] = h; al[row*NAG + t + 256] = lo;
}

// ---------------- head ----------------
__global__ void head_kernel(const float* __restrict__ x,
                            const float* __restrict__ Wa,
                            const float* __restrict__ ba,
                            const float* __restrict__ Wcr,
                            const float* __restrict__ bcr,
                            float* __restrict__ out)
{
    int row = blockIdx.x * 8 + threadIdx.y;
    int lane = threadIdx.x;
    const float* xr = x + (long long)row * HID;
    float xv[8];
    #pragma unroll
    for (int i = 0; i < 8; i++) xv[i] = xr[lane + 32*i];
    #pragma unroll
    for (int j = 0; j < 17; j++){
        float p = 0.f;
        #pragma unroll
        for (int i = 0; i < 8; i++){
            int k = lane + 32*i;
            float w = (j < 16) ? Wa[(long long)k * NACT + j] : Wcr[k];
            p += xv[i] * w;
        }
        #pragma unroll
        for (int off = 16; off; off >>= 1) p += __shfl_down_sync(0xffffffffu, p, off);
        if (lane == 0){
            if (j < 16) out[(long long)row * NACT + j] = p + ba[j];
            else        out[(long long)ROWS * NACT + row] = p + bcr[0];
        }
    }
}

// ---------------- launch ----------------
extern "C" void kernel_launch(void* const* d_in, const int* in_sizes, int n_in,
                              void* d_out, int out_size)
{
    const float* obs = (const float*)d_in[0];
    const float* We  = (const float*)d_in[2];   const float* be  = (const float*)d_in[3];
    const float* Wc  = (const float*)d_in[4];   const float* bc  = (const float*)d_in[5];
    const float* Wn  = (const float*)d_in[6];   const float* bn  = (const float*)d_in[7];
    const float* Wb  = (const float*)d_in[8];   const float* bbp = (const float*)d_in[9];
    const float* Wi  = (const float*)d_in[10];  const float* bi  = (const float*)d_in[11];
    const float* Wq  = (const float*)d_in[12];  const float* bq  = (const float*)d_in[13];
    const float* Wk  = (const float*)d_in[14];  const float* bk  = (const float*)d_in[15];
    const float* Wv  = (const float*)d_in[16];  const float* bv  = (const float*)d_in[17];
    const float* Wp  = (const float*)d_in[18];  const float* bp  = (const float*)d_in[19];
    const float* Wa  = (const float*)d_in[20];  const float* ba  = (const float*)d_in[21];
    const float* Wcr = (const float*)d_in[22];  const float* bcr = (const float*)d_in[23];
    float* out = (float*)d_out;

    #define GA(p, sym) cudaGetSymbolAddress((void**)&p, sym)
    __nv_bfloat16 *ench,*encl,*mqh,*mql,*ksh,*ksl,*obh,*obl,*osh,*osl,*ath,*atl,*vth,*vtl,*agh,*agl;
    __nv_bfloat16 *WeTh,*WeTl,*WcTh,*WcTl,*WkvTh,*WkvTl,*WpTh,*WpTl;
    float *vbuf,*imp,*nrm,*sc,*xb,*bcat,*bkv;
    GA(ench,g_enc_h); GA(encl,g_enc_l); GA(mqh,g_msgq_h); GA(mql,g_msgq_l);
    GA(ksh,g_ks_h); GA(ksl,g_ks_l); GA(obh,g_obs_h); GA(obl,g_obs_l);
    GA(osh,g_obss_h); GA(osl,g_obss_l); GA(ath,g_attn_h); GA(atl,g_attn_l);
    GA(vth,g_vT_h); GA(vtl,g_vT_l); GA(agh,g_agg_h); GA(agl,g_agg_l);
    GA(vbuf,g_v); GA(imp,g_imp); GA(nrm,g_nrm); GA(sc,g_scores); GA(xb,g_x);
    GA(bcat,g_bcat); GA(bkv,g_bkv);
    GA(WeTh,g_WeT_h); GA(WeTl,g_WeT_l); GA(WcTh,g_WcatT_h); GA(WcTl,g_WcatT_l);
    GA(WkvTh,g_WkvT_h); GA(WkvTl,g_WkvT_l); GA(WpTh,g_WpT_h); GA(WpTl,g_WpT_l);
    #undef GA

    cudaFuncSetAttribute(bf_gemm,   cudaFuncAttributeMaxDynamicSharedMemorySize, SMEM_DYN);
    cudaFuncSetAttribute(bf_scores, cudaFuncAttributeMaxDynamicSharedMemorySize, SMEM_DYN);

    OutD z = {}; // zero template

    // 0. packs
    pack_we  <<<128, 256>>>(We, WeTh, WeTl);
    pack_wcat<<<256, 256>>>(Wc, Wn, Wb, Wq, bc, bn, bbp, bq, WcTh, WcTl, bcat);
    pack_wkv <<<128, 256>>>(Wk, Wv, bk, bv, WkvTh, WkvTl, bkv);
    pack_wp  <<<384, 256>>>(Wp, WpTh, WpTl);
    pack_obs <<<ROWS*OBS/256, 256>>>(obs, obh, obl);

    // 1. enc = relu(obs @ We + be) -> hi/lo
    {
        OutD o = z; o.h = ench; o.l = encl; o.factor = 1.f; o.ldc = 256; o.relu = 1;
        bf_gemm<<<dim3(2,256,1), 256, SMEM_DYN>>>(obh, obl, OBS, OBS, nullptr, nullptr, 0, OBS,
                                                  WeTh, WeTl, OBS, be, 0, 0, o, o);
    }
    // 2. imp + nrm
    impnorm_kernel<<<ROWS/8, dim3(32,8)>>>(ench, encl, obs, Wi, bi, imp, nrm);
    // 3. obs scaled pack
    pack_obss<<<ROWS*OBS/256, 256>>>(obs, nrm, osh, osl);
    // 4. msgq = enc @ Wcat + bcat; Q block scaled by imp/sqrt(128)
    {
        OutD o0 = z; o0.h = mqh; o0.l = mql; o0.factor = 1.f; o0.ldc = 256;
        OutD o1 = o0; o1.rowscale = imp; o1.factor = 0.08838834764831845f;
        bf_gemm<<<dim3(2,256,1), 256, SMEM_DYN>>>(ench, encl, 256, 256, nullptr, nullptr, 0, 256,
                                                  WcTh, WcTl, 256, bcat, 0, 0, o0, o1);
    }
    // 5. kv: K block scaled by imp -> hi/lo; V block -> fp32
    {
        OutD o0 = z; o0.h = ksh; o0.l = ksl; o0.rowscale = imp; o0.factor = 1.f; o0.ldc = 128;
        OutD o1 = z; o1.f = vbuf; o1.factor = 1.f; o1.ldc = 128; o1.colsub = 128;
        bf_gemm<<<dim3(2,256,1), 256, SMEM_DYN>>>(mqh, mql, 256, 128, nullptr, nullptr, 0, 128,
                                                  WkvTh, WkvTl, 128, bkv, 0, 0, o0, o1);
    }
    // 6. V transpose + split
    pack_vT<<<dim3(16,4,BSZ), dim3(32,8)>>>(vbuf, vth, vtl);
    // 7. scores
    bf_scores<<<dim3(4,4,BSZ), 256, SMEM_DYN>>>(mqh + 128, mql + 128, ksh, ksl, osh, osl, sc);
    // 8. softmax -> attn hi/lo
    softmax_kernel<<<ROWS, 256>>>(sc, ath, atl);
    // 9. agg = attn @ V -> hi/lo (batched)
    {
        OutD o = z; o.h = agh; o.l = agl; o.factor = 1.f; o.ldc = 128; o.sC = (long long)NAG*MSG;
        bf_gemm<<<dim3(1,4,BSZ), 256, SMEM_DYN>>>(ath, atl, NAG, NAG, nullptr, nullptr, 0, NAG,
                                                  vth, vtl, NAG, nullptr,
                                                  (long long)NAG*NAG, (long long)MSG*NAG, o, o);
    }
    // 10. x = relu([enc|agg] @ Wp + bp) -> fp32
    {
        OutD o = z; o.f = xb; o.factor = 1.f; o.ldc = 256; o.relu = 1;
        bf_gemm<<<dim3(2,256,1), 256, SMEM_DYN>>>(ench, encl, 256, 256, agh, agl, 128, 384,
                                                  WpTh, WpTl, 384, bp, 0, 0, o, o);
    }
    // 11. heads
    head_kernel<<<ROWS/8, dim3(32,8)>>>(xb, Wa, ba, Wcr, bcr, out);
}

// round 7
// speedup vs baseline: 2.6669x; 1.0685x over previous
#include <cuda_runtime.h>
#include <cuda_bf16.h>
#include <stdint.h>
#include <math.h>

#define BSZ 64
#define NAG 512
#define OBS 128
#define HID 256
#define MSG 128
#define NACT 16
#define ROWS (BSZ*NAG)   // 32768

// ---------------- scratch (device globals) ----------------
__device__ __align__(16) __nv_bfloat16 g_enc_h[(size_t)ROWS*HID],  g_enc_l[(size_t)ROWS*HID];
__device__ __align__(16) __nv_bfloat16 g_msgq_h[(size_t)ROWS*256], g_msgq_l[(size_t)ROWS*256]; // 0-127 msg, 128-255 Q(scaled)
__device__ __align__(16) __nv_bfloat16 g_ks_h[(size_t)ROWS*MSG],   g_ks_l[(size_t)ROWS*MSG];   // K scaled by imp
__device__ float g_v[(size_t)ROWS*MSG];
__device__ __align__(16) __nv_bfloat16 g_obs_h[(size_t)ROWS*OBS],  g_obs_l[(size_t)ROWS*OBS];
__device__ __align__(16) __nv_bfloat16 g_obss_h[(size_t)ROWS*OBS], g_obss_l[(size_t)ROWS*OBS]; // scaled sqrt(.5)/nrm
__device__ float g_imp[ROWS];
__device__ float g_nrm[ROWS];
__device__ __align__(16) __nv_bfloat16 g_vT_h[(size_t)BSZ*MSG*NAG], g_vT_l[(size_t)BSZ*MSG*NAG];
__device__ __align__(16) __nv_bfloat16 g_agg_h[(size_t)ROWS*MSG],  g_agg_l[(size_t)ROWS*MSG];
__device__ float g_x[(size_t)ROWS*HID];
__device__ float g_bcat[256];
__device__ float g_bkv[256];
__device__ __align__(16) __nv_bfloat16 g_WeT_h[256*128],  g_WeT_l[256*128];
__device__ __align__(16) __nv_bfloat16 g_WcatT_h[256*256],g_WcatT_l[256*256];
__device__ __align__(16) __nv_bfloat16 g_WkvT_h[256*128], g_WkvT_l[256*128];
__device__ __align__(16) __nv_bfloat16 g_WpT_h[256*384],  g_WpT_l[256*384];

// ---------------- helpers ----------------
__device__ __forceinline__ void bsplit(float x, __nv_bfloat16& h, __nv_bfloat16& l){
    h = __float2bfloat16(x);
    l = __float2bfloat16(x - __bfloat162float(h));
}
__device__ __forceinline__ uint32_t smem_u32(const void* p){
    uint32_t a;
    asm("{ .reg .u64 t; cvta.to.shared.u64 t, %1; cvt.u32.u64 %0, t; }" : "=r"(a) : "l"(p));
    return a;
}
__device__ __forceinline__ void cpa16(uint32_t d, const void* s){
    asm volatile("cp.async.cg.shared.global [%0], [%1], 16;" :: "r"(d), "l"(s));
}
__device__ __forceinline__ void cpa_commit(){ asm volatile("cp.async.commit_group;" ::: "memory"); }
__device__ __forceinline__ void cpa_wait1(){ asm volatile("cp.async.wait_group 1;" ::: "memory"); }
__device__ __forceinline__ void cpa_wait0(){ asm volatile("cp.async.wait_group 0;" ::: "memory"); }
__device__ __forceinline__ void ldsm4(uint32_t* r, uint32_t a){
    asm volatile("ldmatrix.sync.aligned.m8n8.x4.shared.b16 {%0,%1,%2,%3}, [%4];"
        : "=r"(r[0]), "=r"(r[1]), "=r"(r[2]), "=r"(r[3]) : "r"(a));
}
__device__ __forceinline__ void mma16816(float* d, const uint32_t* a, const uint32_t* b){
    asm volatile(
        "mma.sync.aligned.m16n8k16.row.col.f32.bf16.bf16.f32 "
        "{%0,%1,%2,%3}, {%4,%5,%6,%7}, {%8,%9}, {%0,%1,%2,%3};"
        : "+f"(d[0]), "+f"(d[1]), "+f"(d[2]), "+f"(d[3])
        : "r"(a[0]), "r"(a[1]), "r"(a[2]), "r"(a[3]), "r"(b[0]), "r"(b[1]));
}
__device__ __forceinline__ uint32_t packbf2(float x, float y){
    __nv_bfloat162 p; p.x = __float2bfloat16(x); p.y = __float2bfloat16(y);
    return *(uint32_t*)&p;
}

// stage one [128 rows][64 k] bf16 tile with SW128 swizzle via cp.async (256 threads)
__device__ __forceinline__ void stage_tile(uint32_t smA, const __nv_bfloat16* g, int ld,
                                           int row0, int k0, int tid)
{
    int r = tid >> 1, s0 = (tid & 1) * 4;
    const __nv_bfloat16* src = g + (long long)(row0 + r) * ld + k0 + s0 * 8;
    uint32_t offb = (uint32_t)(r * 128 + s0 * 16);
    #pragma unroll
    for (int j = 0; j < 4; j++){
        uint32_t off = offb + j * 16;
        uint32_t sw = off ^ ((off >> 3) & 0x70u);
        cpa16(smA + sw, src + j * 8);
    }
}

// ================= generic GEMM (128x128 block, warp 64x32) =================
// mma on one staged chunk (A/B hi+lo tiles at sm+0/16384/32768/49152); 3 passes
__device__ __forceinline__ void mma_chunk(uint32_t sm, float acc[4][4][4], int wm, int wn, int lane)
{
    const int arow = ((lane >> 3) & 1) * 8 + (lane & 7);
    const int ak8  = ((lane >> 4) & 1) * 8;
    const int brow = ((lane >> 4) & 1) * 8 + (lane & 7);
    const int bk8  = ((lane >> 3) & 1) * 8;
    #pragma unroll
    for (int ks = 0; ks < 4; ks++){
        const int k0 = ks * 16;
        uint32_t ah[4][4], al[4][4], bh[4][2], bl[4][2], t4[4];
        #pragma unroll
        for (int mt = 0; mt < 4; mt++){
            uint32_t off = (uint32_t)((wm*64 + mt*16 + arow) * 128 + (k0 + ak8) * 2);
            uint32_t sw = off ^ ((off >> 3) & 0x70u);
            ldsm4(ah[mt], sm + 0     + sw);
            ldsm4(al[mt], sm + 16384 + sw);
        }
        #pragma unroll
        for (int np = 0; np < 2; np++){
            uint32_t off = (uint32_t)((wn*32 + np*16 + brow) * 128 + (k0 + bk8) * 2);
            uint32_t sw = off ^ ((off >> 3) & 0x70u);
            ldsm4(t4, sm + 32768 + sw);
            bh[np*2][0]=t4[0]; bh[np*2][1]=t4[1]; bh[np*2+1][0]=t4[2]; bh[np*2+1][1]=t4[3];
            ldsm4(t4, sm + 49152 + sw);
            bl[np*2][0]=t4[0]; bl[np*2][1]=t4[1]; bl[np*2+1][0]=t4[2]; bl[np*2+1][1]=t4[3];
        }
        #pragma unroll
        for (int mt = 0; mt < 4; mt++)
            #pragma unroll
            for (int nt = 0; nt < 4; nt++){
                mma16816(acc[mt][nt], ah[mt], bh[nt]);
                mma16816(acc[mt][nt], ah[mt], bl[nt]);
                mma16816(acc[mt][nt], al[mt], bh[nt]);
            }
    }
}

struct OutD {
    float* f;
    __nv_bfloat16* h;
    __nv_bfloat16* l;
    const float* rowscale;
    float factor;
    int ldc;
    int colsub;
    int relu;
    long long sC;
};

__device__ __forceinline__ void epi(float acc[4][4][4], const OutD& od, const float* bias,
                                    int row0, int col0, int z, int wm, int wn, int lane)
{
    const int lq = lane >> 2, le = (lane & 3) * 2;
    #pragma unroll
    for (int mt = 0; mt < 4; mt++){
        int gr0 = row0 + wm*64 + mt*16 + lq;
        float rs0 = od.rowscale ? od.rowscale[gr0]   * od.factor : od.factor;
        float rs1 = od.rowscale ? od.rowscale[gr0+8] * od.factor : od.factor;
        #pragma unroll
        for (int nt = 0; nt < 4; nt++){
            int gc = col0 + wn*32 + nt*8 + le;
            float b0 = bias ? bias[gc] : 0.f, b1 = bias ? bias[gc+1] : 0.f;
            float v00 = (acc[mt][nt][0] + b0) * rs0, v01 = (acc[mt][nt][1] + b1) * rs0;
            float v10 = (acc[mt][nt][2] + b0) * rs1, v11 = (acc[mt][nt][3] + b1) * rs1;
            if (od.relu){
                v00 = fmaxf(v00, 0.f); v01 = fmaxf(v01, 0.f);
                v10 = fmaxf(v10, 0.f); v11 = fmaxf(v11, 0.f);
            }
            long long i0 = od.sC * z + (long long)gr0 * od.ldc + (gc - od.colsub);
            long long i1 = od.sC * z + (long long)(gr0 + 8) * od.ldc + (gc - od.colsub);
            if (od.f){
                *(float2*)(od.f + i0) = make_float2(v00, v01);
                *(float2*)(od.f + i1) = make_float2(v10, v11);
            }
            if (od.h){
                __nv_bfloat162 ph, pl;
                bsplit(v00, ph.x, pl.x); bsplit(v01, ph.y, pl.y);
                *(__nv_bfloat162*)(od.h + i0) = ph; *(__nv_bfloat162*)(od.l + i0) = pl;
                bsplit(v10, ph.x, pl.x); bsplit(v11, ph.y, pl.y);
                *(__nv_bfloat162*)(od.h + i1) = ph; *(__nv_bfloat162*)(od.l + i1) = pl;
            }
        }
    }
}

#define SMEM_DYN 131072

__global__ __launch_bounds__(256, 1)
void bf_gemm(const __nv_bfloat16* __restrict__ Ah1, const __nv_bfloat16* __restrict__ Al1, int lda1, int K1,
             const __nv_bfloat16* __restrict__ Ah2, const __nv_bfloat16* __restrict__ Al2, int lda2, int Ktot,
             const __nv_bfloat16* __restrict__ Bh,  const __nv_bfloat16* __restrict__ Bl,  int ldb,
             const float* __restrict__ bias, long long sA1, long long sB,
             OutD o0, OutD o1)
{
    extern __shared__ __align__(1024) char smraw[];
    const uint32_t smb = smem_u32(smraw);
    const int tid = threadIdx.x, wid = tid >> 5, lane = tid & 31;
    const int wm = wid >> 2, wn = wid & 3;
    const int row0 = blockIdx.y * 128, col0 = blockIdx.x * 128;
    const int z = blockIdx.z;
    Ah1 += (long long)z * sA1; Al1 += (long long)z * sA1;
    Bh  += (long long)z * sB;  Bl  += (long long)z * sB;

    float acc[4][4][4];
    #pragma unroll
    for (int i = 0; i < 4; i++)
        #pragma unroll
        for (int j = 0; j < 4; j++)
            #pragma unroll
            for (int k = 0; k < 4; k++) acc[i][j][k] = 0.f;

    const int T = Ktot / 64;
    auto do_stage = [&](int t, int buf){
        int k0 = t * 64;
        const __nv_bfloat16 *h, *l; int ld, ka;
        if (k0 < K1){ h = Ah1; l = Al1; ld = lda1; ka = k0; }
        else        { h = Ah2; l = Al2; ld = lda2; ka = k0 - K1; }
        uint32_t sb = smb + buf * 65536;
        stage_tile(sb + 0,     h,  ld,  row0, ka, tid);
        stage_tile(sb + 16384, l,  ld,  row0, ka, tid);
        stage_tile(sb + 32768, Bh, ldb, col0, k0, tid);
        stage_tile(sb + 49152, Bl, ldb, col0, k0, tid);
        cpa_commit();
    };

    do_stage(0, 0);
    for (int t = 0; t < T; t++){
        if (t + 1 < T){ do_stage(t + 1, (t + 1) & 1); cpa_wait1(); }
        else          { cpa_wait0(); }
        __syncthreads();
        mma_chunk(smb + (t & 1) * 65536, acc, wm, wn, lane);
        __syncthreads();
    }

    const OutD& od = (blockIdx.x == 0) ? o0 : o1;
    epi(acc, od, bias, row0, col0, z, wm, wn, lane);
}

// ================= flash attention: S = Qs·Ks^T + obss·obss^T, softmax, O = P·V =================
// 8 warps, warp w owns q-rows [w*16, w*16+16). grid (4 qtiles, 64 batches).
__global__ __launch_bounds__(256, 1)
void flash_kernel(const __nv_bfloat16* __restrict__ Qh, const __nv_bfloat16* __restrict__ Ql,   // +128 offset, ld 256
                  const __nv_bfloat16* __restrict__ Kh, const __nv_bfloat16* __restrict__ Kl,   // ld 128
                  const __nv_bfloat16* __restrict__ Oh, const __nv_bfloat16* __restrict__ Ol,   // ld 128
                  const __nv_bfloat16* __restrict__ Vh, const __nv_bfloat16* __restrict__ Vl,   // [b][128 d][512 k]
                  __nv_bfloat16* __restrict__ aggh, __nv_bfloat16* __restrict__ aggl)
{
    extern __shared__ __align__(1024) char smraw[];
    const uint32_t smb = smem_u32(smraw);
    const int tid = threadIdx.x, w = tid >> 5, lane = tid & 31;
    const int q0 = blockIdx.x * 128;
    const int b = blockIdx.y;
    const int gr = b * NAG;
    const long long vbase = (long long)b * MSG * NAG;

    const int arow = ((lane >> 3) & 1) * 8 + (lane & 7);
    const int ak8  = ((lane >> 4) & 1) * 8;
    const int brow = ((lane >> 4) & 1) * 8 + (lane & 7);
    const int bk8  = ((lane >> 3) & 1) * 8;
    const int lq = lane >> 2;

    float O[16][4];
    #pragma unroll
    for (int nt = 0; nt < 16; nt++)
        #pragma unroll
        for (int j = 0; j < 4; j++) O[nt][j] = 0.f;
    float m0 = -1e30f, m1 = -1e30f, sum0 = 0.f, sum1 = 0.f;

    for (int kt = 0; kt < 4; kt++){
        const int k0 = kt * 128;

        // ---- S phase: 4 feature chunks of 64 ----
        float S[16][4];
        #pragma unroll
        for (int nt = 0; nt < 16; nt++)
            #pragma unroll
            for (int j = 0; j < 4; j++) S[nt][j] = 0.f;

        auto do_stage = [&](int t, int buf){
            uint32_t sb = smb + buf * 65536;
            if (t < 2){
                stage_tile(sb + 0,     Qh, 256, gr + q0, t*64, tid);
                stage_tile(sb + 16384, Ql, 256, gr + q0, t*64, tid);
                stage_tile(sb + 32768, Kh, 128, gr + k0, t*64, tid);
                stage_tile(sb + 49152, Kl, 128, gr + k0, t*64, tid);
            } else {
                stage_tile(sb + 0,     Oh, 128, gr + q0, (t-2)*64, tid);
                stage_tile(sb + 16384, Ol, 128, gr + q0, (t-2)*64, tid);
                stage_tile(sb + 32768, Oh, 128, gr + k0, (t-2)*64, tid);
                stage_tile(sb + 49152, Ol, 128, gr + k0, (t-2)*64, tid);
            }
            cpa_commit();
        };

        do_stage(0, 0);
        for (int t = 0; t < 4; t++){
            if (t + 1 < 4){ do_stage(t + 1, (t + 1) & 1); cpa_wait1(); }
            else          { cpa_wait0(); }
            __syncthreads();
            uint32_t sm = smb + (t & 1) * 65536;
            #pragma unroll
            for (int ks = 0; ks < 4; ks++){
                const int kk = ks * 16;
                uint32_t ah[4], al[4], th[4], tl[4];
                {
                    uint32_t off = (uint32_t)((w*16 + arow) * 128 + (kk + ak8) * 2);
                    uint32_t sw = off ^ ((off >> 3) & 0x70u);
                    ldsm4(ah, sm + 0     + sw);
                    ldsm4(al, sm + 16384 + sw);
                }
                #pragma unroll
                for (int np = 0; np < 8; np++){
                    uint32_t off = (uint32_t)((np*16 + brow) * 128 + (kk + bk8) * 2);
                    uint32_t sw = off ^ ((off >> 3) & 0x70u);
                    ldsm4(th, sm + 32768 + sw);
                    ldsm4(tl, sm + 49152 + sw);
                    uint32_t b0[2] = {th[0], th[1]}, b1[2] = {th[2], th[3]};
                    uint32_t c0[2] = {tl[0], tl[1]}, c1[2] = {tl[2], tl[3]};
                    mma16816(S[np*2],   ah, b0);
                    mma16816(S[np*2],   ah, c0);
                    mma16816(S[np*2],   al, b0);
                    mma16816(S[np*2+1], ah, b1);
                    mma16816(S[np*2+1], ah, c1);
                    mma16816(S[np*2+1], al, b1);
                }
            }
            __syncthreads();
        }

        // ---- online softmax ----
        float mx0 = -1e30f, mx1 = -1e30f;
        #pragma unroll
        for (int nt = 0; nt < 16; nt++){
            mx0 = fmaxf(mx0, fmaxf(S[nt][0], S[nt][1]));
            mx1 = fmaxf(mx1, fmaxf(S[nt][2], S[nt][3]));
        }
        mx0 = fmaxf(mx0, __shfl_xor_sync(0xffffffffu, mx0, 1));
        mx0 = fmaxf(mx0, __shfl_xor_sync(0xffffffffu, mx0, 2));
        mx1 = fmaxf(mx1, __shfl_xor_sync(0xffffffffu, mx1, 1));
        mx1 = fmaxf(mx1, __shfl_xor_sync(0xffffffffu, mx1, 2));
        float M0 = fmaxf(m0, mx0), M1 = fmaxf(m1, mx1);
        float f0 = __expf(m0 - M0), f1 = __expf(m1 - M1);
        float rs0 = 0.f, rs1 = 0.f;
        #pragma unroll
        for (int nt = 0; nt < 16; nt++){
            float p0 = __expf(S[nt][0] - M0); S[nt][0] = p0; rs0 += p0;
            float p1 = __expf(S[nt][1] - M0); S[nt][1] = p1; rs0 += p1;
            float p2 = __expf(S[nt][2] - M1); S[nt][2] = p2; rs1 += p2;
            float p3 = __expf(S[nt][3] - M1); S[nt][3] = p3; rs1 += p3;
        }
        rs0 += __shfl_xor_sync(0xffffffffu, rs0, 1);
        rs0 += __shfl_xor_sync(0xffffffffu, rs0, 2);
        rs1 += __shfl_xor_sync(0xffffffffu, rs1, 1);
        rs1 += __shfl_xor_sync(0xffffffffu, rs1, 2);
        sum0 = sum0 * f0 + rs0;
        sum1 = sum1 * f1 + rs1;
        m0 = M0; m1 = M1;
        #pragma unroll
        for (int nt = 0; nt < 16; nt++){
            O[nt][0] *= f0; O[nt][1] *= f0; O[nt][2] *= f1; O[nt][3] *= f1;
        }

        // ---- V phase: stage V^T [128 d][128 kpos] hi/lo (two 64-col tiles each) ----
        stage_tile(smb + 0,     Vh + vbase, NAG, 0, k0,      tid);
        stage_tile(smb + 16384, Vl + vbase, NAG, 0, k0,      tid);
        stage_tile(smb + 32768, Vh + vbase, NAG, 0, k0 + 64, tid);
        stage_tile(smb + 49152, Vl + vbase, NAG, 0, k0 + 64, tid);
        cpa_commit(); cpa_wait0();
        __syncthreads();

        #pragma unroll
        for (int ks = 0; ks < 8; ks++){
            // build P a-frags (hi/lo) from S regs: kpos group 16*ks -> S tiles 2ks, 2ks+1
            uint32_t aph[4], apl[4];
            {
                float p00 = S[2*ks][0],   p01 = S[2*ks][1];
                float p10 = S[2*ks][2],   p11 = S[2*ks][3];
                float p20 = S[2*ks+1][0], p21 = S[2*ks+1][1];
                float p30 = S[2*ks+1][2], p31 = S[2*ks+1][3];
                aph[0] = packbf2(p00, p01);
                aph[1] = packbf2(p10, p11);
                aph[2] = packbf2(p20, p21);
                aph[3] = packbf2(p30, p31);
                __nv_bfloat162 h0 = *(__nv_bfloat162*)&aph[0];
                __nv_bfloat162 h1 = *(__nv_bfloat162*)&aph[1];
                __nv_bfloat162 h2 = *(__nv_bfloat162*)&aph[2];
                __nv_bfloat162 h3 = *(__nv_bfloat162*)&aph[3];
                apl[0] = packbf2(p00 - __bfloat162float(h0.x), p01 - __bfloat162float(h0.y));
                apl[1] = packbf2(p10 - __bfloat162float(h1.x), p11 - __bfloat162float(h1.y));
                apl[2] = packbf2(p20 - __bfloat162float(h2.x), p21 - __bfloat162float(h2.y));
                apl[3] = packbf2(p30 - __bfloat162float(h3.x), p31 - __bfloat162float(h3.y));
            }
            uint32_t base = (ks < 4) ? smb : smb + 32768;
            uint32_t basl = base + 16384;
            const int kk = (ks & 3) * 16;
            #pragma unroll
            for (int np = 0; np < 8; np++){
                uint32_t off = (uint32_t)((np*16 + brow) * 128 + (kk + bk8) * 2);
                uint32_t sw = off ^ ((off >> 3) & 0x70u);
                uint32_t th[4], tl[4];
                ldsm4(th, base + sw);
                ldsm4(tl, basl + sw);
                uint32_t b0[2] = {th[0], th[1]}, b1[2] = {th[2], th[3]};
                uint32_t c0[2] = {tl[0], tl[1]}, c1[2] = {tl[2], tl[3]};
                mma16816(O[np*2],   aph, b0);
                mma16816(O[np*2],   aph, c0);
                mma16816(O[np*2],   apl, b0);
                mma16816(O[np*2+1], aph, b1);
                mma16816(O[np*2+1], aph, c1);
                mma16816(O[np*2+1], apl, b1);
            }
        }
        __syncthreads();
    }

    // ---- epilogue: O /= sum, write agg hi/lo ----
    float inv0 = 1.f / sum0, inv1 = 1.f / sum1;
    long long r0 = (long long)(gr + q0 + w*16 + lq) * MSG;
    long long r1 = r0 + 8 * MSG;
    #pragma unroll
    for (int nt = 0; nt < 16; nt++){
        int d = nt*8 + (lane & 3)*2;
        __nv_bfloat162 ph, pl;
        bsplit(O[nt][0] * inv0, ph.x, pl.x);
        bsplit(O[nt][1] * inv0, ph.y, pl.y);
        *(__nv_bfloat162*)(aggh + r0 + d) = ph;
        *(__nv_bfloat162*)(aggl + r0 + d) = pl;
        bsplit(O[nt][2] * inv1, ph.x, pl.x);
        bsplit(O[nt][3] * inv1, ph.y, pl.y);
        *(__nv_bfloat162*)(aggh + r1 + d) = ph;
        *(__nv_bfloat162*)(aggl + r1 + d) = pl;
    }
}

// ---------------- packing kernels ----------------
__global__ void pack_obs(const float* __restrict__ obs,
                         __nv_bfloat16* __restrict__ h, __nv_bfloat16* __restrict__ l)
{
    long long i = (long long)blockIdx.x * 256 + threadIdx.x;
    __nv_bfloat16 hh, ll; bsplit(obs[i], hh, ll);
    h[i] = hh; l[i] = ll;
}
__global__ void pack_obss(const float* __restrict__ obs, const float* __restrict__ nrm,
                          __nv_bfloat16* __restrict__ h, __nv_bfloat16* __restrict__ l)
{
    long long i = (long long)blockIdx.x * 256 + threadIdx.x;
    int row = (int)(i >> 7);
    float s = 0.7071067811865476f / (nrm[row] + 1e-8f);
    __nv_bfloat16 hh, ll; bsplit(obs[i] * s, hh, ll);
    h[i] = hh; l[i] = ll;
}
__global__ void pack_we(const float* __restrict__ We,
                        __nv_bfloat16* __restrict__ hi, __nv_bfloat16* __restrict__ lo)
{
    int i = blockIdx.x * 256 + threadIdx.x;
    int n = i >> 7, k = i & 127;
    __nv_bfloat16 h, l; bsplit(We[k*256 + n], h, l);
    hi[i] = h; lo[i] = l;
}
__global__ void pack_wcat(const float* __restrict__ Wc, const float* __restrict__ Wn,
                          const float* __restrict__ Wb, const float* __restrict__ Wq,
                          const float* __restrict__ bc, const float* __restrict__ bn,
                          const float* __restrict__ bbp, const float* __restrict__ bq,
                          __nv_bfloat16* __restrict__ hi, __nv_bfloat16* __restrict__ lo,
                          float* __restrict__ bcat)
{
    int i = blockIdx.x * 256 + threadIdx.x;
    int n = i >> 8, k = i & 255;
    float v;
    if (n < 32)       v = Wc[k*32 + n];
    else if (n < 96)  v = Wn[k*64 + (n-32)];
    else if (n < 128) v = Wb[k*32 + (n-96)];
    else              v = Wq[k*128 + (n-128)];
    __nv_bfloat16 h, l; bsplit(v, h, l);
    hi[i] = h; lo[i] = l;
    if (k == 0)
        bcat[n] = (n < 32) ? bc[n] : (n < 96) ? bn[n-32] : (n < 128) ? bbp[n-96] : bq[n-128];
}
__global__ void pack_wkv(const float* __restrict__ Wk, const float* __restrict__ Wv,
                         const float* __restrict__ bk, const float* __restrict__ bv,
                         __nv_bfloat16* __restrict__ hi, __nv_bfloat16* __restrict__ lo,
                         float* __restrict__ bkv)
{
    int i = blockIdx.x * 256 + threadIdx.x;
    int n = i >> 7, k = i & 127;
    float v = (n < 128) ? Wk[k*128 + n] : Wv[k*128 + (n-128)];
    __nv_bfloat16 h, l; bsplit(v, h, l);
    hi[i] = h; lo[i] = l;
    if (k == 0) bkv[n] = (n < 128) ? bk[n] : bv[n-128];
}
__global__ void pack_wp(const float* __restrict__ Wp,
                        __nv_bfloat16* __restrict__ hi, __nv_bfloat16* __restrict__ lo)
{
    int i = blockIdx.x * 256 + threadIdx.x;
    int n = i / 384, k = i % 384;
    __nv_bfloat16 h, l; bsplit(Wp[k*256 + n], h, l);
    hi[i] = h; lo[i] = l;
}

// V transpose+split: g_v [b*512+k][128] -> vT [b][d][k] bf16 hi/lo
__global__ void pack_vT(const float* __restrict__ v,
                        __nv_bfloat16* __restrict__ hi, __nv_bfloat16* __restrict__ lo)
{
    __shared__ float t[32][33];
    int b = blockIdx.z;
    int k0 = blockIdx.x * 32, d0 = blockIdx.y * 32;
    for (int i = threadIdx.y; i < 32; i += 8)
        t[i][threadIdx.x] = v[((long long)(b*512 + k0 + i))*128 + d0 + threadIdx.x];
    __syncthreads();
    for (int i = threadIdx.y; i < 32; i += 8){
        __nv_bfloat16 h, l; bsplit(t[threadIdx.x][i], h, l);
        long long o = ((long long)(b*128 + d0 + i))*512 + k0 + threadIdx.x;
        hi[o] = h; lo[o] = l;
    }
}

// ---------------- importance + obs norm (enc from hi/lo) ----------------
__global__ void impnorm_kernel(const __nv_bfloat16* __restrict__ eh,
                               const __nv_bfloat16* __restrict__ el,
                               const float* __restrict__ obs,
                               const float* __restrict__ Wi,
                               const float* __restrict__ bi,
                               float* __restrict__ imp,
                               float* __restrict__ nrm)
{
    int row = blockIdx.x * 8 + threadIdx.y;
    int lane = threadIdx.x;
    const __nv_bfloat16* ph = eh + (long long)row * HID;
    const __nv_bfloat16* pl = el + (long long)row * HID;
    const float* o = obs + (long long)row * OBS;
    float d = 0.f, ss = 0.f;
    #pragma unroll
    for (int i = 0; i < HID/32; i++){
        int k = lane + 32*i;
        float e = __bfloat162float(ph[k]) + __bfloat162float(pl[k]);
        d += e * Wi[k];
    }
    #pragma unroll
    for (int i = 0; i < OBS/32; i++){ float v = o[lane + 32*i]; ss += v*v; }
    #pragma unroll
    for (int off = 16; off; off >>= 1){
        d  += __shfl_down_sync(0xffffffffu, d, off);
        ss += __shfl_down_sync(0xffffffffu, ss, off);
    }
    if (lane == 0){
        imp[row] = 1.f / (1.f + expf(-(d + bi[0])));
        nrm[row] = sqrtf(ss);
    }
}

// ---------------- head ----------------
__global__ void head_kernel(const float* __restrict__ x,
                            const float* __restrict__ Wa,
                            const float* __restrict__ ba,
                            const float* __restrict__ Wcr,
                            const float* __restrict__ bcr,
                            float* __restrict__ out)
{
    int row = blockIdx.x * 8 + threadIdx.y;
    int lane = threadIdx.x;
    const float* xr = x + (long long)row * HID;
    float xv[8];
    #pragma unroll
    for (int i = 0; i < 8; i++) xv[i] = xr[lane + 32*i];
    #pragma unroll
    for (int j = 0; j < 17; j++){
        float p = 0.f;
        #pragma unroll
        for (int i = 0; i < 8; i++){
            int k = lane + 32*i;
            float w = (j < 16) ? Wa[(long long)k * NACT + j] : Wcr[k];
            p += xv[i] * w;
        }
        #pragma unroll
        for (int off = 16; off; off >>= 1) p += __shfl_down_sync(0xffffffffu, p, off);
        if (lane == 0){
            if (j < 16) out[(long long)row * NACT + j] = p + ba[j];
            else        out[(long long)ROWS * NACT + row] = p + bcr[0];
        }
    }
}

// ---------------- launch ----------------
extern "C" void kernel_launch(void* const* d_in, const int* in_sizes, int n_in,
                              void* d_out, int out_size)
{
    const float* obs = (const float*)d_in[0];
    const float* We  = (const float*)d_in[2];   const float* be  = (const float*)d_in[3];
    const float* Wc  = (const float*)d_in[4];   const float* bc  = (const float*)d_in[5];
    const float* Wn  = (const float*)d_in[6];   const float* bn  = (const float*)d_in[7];
    const float* Wb  = (const float*)d_in[8];   const float* bbp = (const float*)d_in[9];
    const float* Wi  = (const float*)d_in[10];  const float* bi  = (const float*)d_in[11];
    const float* Wq  = (const float*)d_in[12];  const float* bq  = (const float*)d_in[13];
    const float* Wk  = (const float*)d_in[14];  const float* bk  = (const float*)d_in[15];
    const float* Wv  = (const float*)d_in[16];  const float* bv  = (const float*)d_in[17];
    const float* Wp  = (const float*)d_in[18];  const float* bp  = (const float*)d_in[19];
    const float* Wa  = (const float*)d_in[20];  const float* ba  = (const float*)d_in[21];
    const float* Wcr = (const float*)d_in[22];  const float* bcr = (const float*)d_in[23];
    float* out = (float*)d_out;

    #define GA(p, sym) cudaGetSymbolAddress((void**)&p, sym)
    __nv_bfloat16 *ench,*encl,*mqh,*mql,*ksh,*ksl,*obh,*obl,*osh,*osl,*vth,*vtl,*agh,*agl;
    __nv_bfloat16 *WeTh,*WeTl,*WcTh,*WcTl,*WkvTh,*WkvTl,*WpTh,*WpTl;
    float *vbuf,*imp,*nrm,*xb,*bcat,*bkv;
    GA(ench,g_enc_h); GA(encl,g_enc_l); GA(mqh,g_msgq_h); GA(mql,g_msgq_l);
    GA(ksh,g_ks_h); GA(ksl,g_ks_l); GA(obh,g_obs_h); GA(obl,g_obs_l);
    GA(osh,g_obss_h); GA(osl,g_obss_l);
    GA(vth,g_vT_h); GA(vtl,g_vT_l); GA(agh,g_agg_h); GA(agl,g_agg_l);
    GA(vbuf,g_v); GA(imp,g_imp); GA(nrm,g_nrm); GA(xb,g_x);
    GA(bcat,g_bcat); GA(bkv,g_bkv);
    GA(WeTh,g_WeT_h); GA(WeTl,g_WeT_l); GA(WcTh,g_WcatT_h); GA(WcTl,g_WcatT_l);
    GA(WkvTh,g_WkvT_h); GA(WkvTl,g_WkvT_l); GA(WpTh,g_WpT_h); GA(WpTl,g_WpT_l);
    #undef GA

    cudaFuncSetAttribute(bf_gemm,      cudaFuncAttributeMaxDynamicSharedMemorySize, SMEM_DYN);
    cudaFuncSetAttribute(flash_kernel, cudaFuncAttributeMaxDynamicSharedMemorySize, SMEM_DYN);

    OutD z = {};

    // 0. packs
    pack_we  <<<128, 256>>>(We, WeTh, WeTl);
    pack_wcat<<<256, 256>>>(Wc, Wn, Wb, Wq, bc, bn, bbp, bq, WcTh, WcTl, bcat);
    pack_wkv <<<128, 256>>>(Wk, Wv, bk, bv, WkvTh, WkvTl, bkv);
    pack_wp  <<<384, 256>>>(Wp, WpTh, WpTl);
    pack_obs <<<ROWS*OBS/256, 256>>>(obs, obh, obl);

    // 1. enc = relu(obs @ We + be) -> hi/lo
    {
        OutD o = z; o.h = ench; o.l = encl; o.factor = 1.f; o.ldc = 256; o.relu = 1;
        bf_gemm<<<dim3(2,256,1), 256, SMEM_DYN>>>(obh, obl, OBS, OBS, nullptr, nullptr, 0, OBS,
                                                  WeTh, WeTl, OBS, be, 0, 0, o, o);
    }
    // 2. imp + nrm
    impnorm_kernel<<<ROWS/8, dim3(32,8)>>>(ench, encl, obs, Wi, bi, imp, nrm);
    // 3. obs scaled pack
    pack_obss<<<ROWS*OBS/256, 256>>>(obs, nrm, osh, osl);
    // 4. msgq = enc @ Wcat + bcat; Q block scaled by imp/sqrt(128)
    {
        OutD o0 = z; o0.h = mqh; o0.l = mql; o0.factor = 1.f; o0.ldc = 256;
        OutD o1 = o0; o1.rowscale = imp; o1.factor = 0.08838834764831845f;
        bf_gemm<<<dim3(2,256,1), 256, SMEM_DYN>>>(ench, encl, 256, 256, nullptr, nullptr, 0, 256,
                                                  WcTh, WcTl, 256, bcat, 0, 0, o0, o1);
    }
    // 5. kv: K scaled by imp -> hi/lo; V -> fp32
    {
        OutD o0 = z; o0.h = ksh; o0.l = ksl; o0.rowscale = imp; o0.factor = 1.f; o0.ldc = 128;
        OutD o1 = z; o1.f = vbuf; o1.factor = 1.f; o1.ldc = 128; o1.colsub = 128;
        bf_gemm<<<dim3(2,256,1), 256, SMEM_DYN>>>(mqh, mql, 256, 128, nullptr, nullptr, 0, 128,
                                                  WkvTh, WkvTl, 128, bkv, 0, 0, o0, o1);
    }
    // 6. V transpose + split
    pack_vT<<<dim3(16,4,BSZ), dim3(32,8)>>>(vbuf, vth, vtl);
    // 7. flash attention: scores + softmax + attn@V fused -> agg hi/lo
    flash_kernel<<<dim3(4, BSZ), 256, SMEM_DYN>>>(mqh + 128, mql + 128, ksh, ksl,
                                                  osh, osl, vth, vtl, agh, agl);
    // 8. x = relu([enc|agg] @ Wp + bp) -> fp32
    {
        OutD o = z; o.f = xb; o.factor = 1.f; o.ldc = 256; o.relu = 1;
        bf_gemm<<<dim3(2,256,1), 256, SMEM_DYN>>>(ench, encl, 256, 256, agh, agl, 128, 384,
                                                  WpTh, WpTl, 384, bp, 0, 0, o, o);
    }
    // 9. heads
    head_kernel<<<ROWS/8, dim3(32,8)>>>(xb, Wa, ba, Wcr, bcr, out);
}

// round 8
// speedup vs baseline: 2.6776x; 1.0040x over previous
#include <cuda_runtime.h>
#include <cuda_bf16.h>
#include <stdint.h>
#include <math.h>

#define BSZ 64
#define NAG 512
#define OBS 128
#define HID 256
#define MSG 128
#define NACT 16
#define ROWS (BSZ*NAG)   // 32768

// ---------------- scratch (device globals) ----------------
__device__ __align__(16) __nv_bfloat16 g_enc_h[(size_t)ROWS*HID],  g_enc_l[(size_t)ROWS*HID];
__device__ __align__(16) __nv_bfloat16 g_msgq_h[(size_t)ROWS*256], g_msgq_l[(size_t)ROWS*256]; // 0-127 msg, 128-255 Q(scaled)
__device__ __align__(16) __nv_bfloat16 g_ks_h[(size_t)ROWS*MSG],   g_ks_l[(size_t)ROWS*MSG];   // K scaled by imp
__device__ float g_v[(size_t)ROWS*MSG];
__device__ __align__(16) __nv_bfloat16 g_obs_h[(size_t)ROWS*OBS],  g_obs_l[(size_t)ROWS*OBS];
__device__ __align__(16) __nv_bfloat16 g_obss_h[(size_t)ROWS*OBS], g_obss_l[(size_t)ROWS*OBS]; // scaled sqrt(.5)/nrm
__device__ float g_imp[ROWS];
__device__ float g_nrm[ROWS];
__device__ __align__(16) __nv_bfloat16 g_vT_h[(size_t)BSZ*MSG*NAG], g_vT_l[(size_t)BSZ*MSG*NAG];
__device__ __align__(16) __nv_bfloat16 g_agg_h[(size_t)ROWS*MSG],  g_agg_l[(size_t)ROWS*MSG];
__device__ float g_x[(size_t)ROWS*HID];
__device__ float g_bcat[256];
__device__ float g_bkv[256];
__device__ __align__(16) __nv_bfloat16 g_WeT_h[256*128],  g_WeT_l[256*128];
__device__ __align__(16) __nv_bfloat16 g_WcatT_h[256*256],g_WcatT_l[256*256];
__device__ __align__(16) __nv_bfloat16 g_WkvT_h[256*128], g_WkvT_l[256*128];
__device__ __align__(16) __nv_bfloat16 g_WpT_h[256*384],  g_WpT_l[256*384];

// ---------------- helpers ----------------
__device__ __forceinline__ void bsplit(float x, __nv_bfloat16& h, __nv_bfloat16& l){
    h = __float2bfloat16(x);
    l = __float2bfloat16(x - __bfloat162float(h));
}
__device__ __forceinline__ uint32_t smem_u32(const void* p){
    uint32_t a;
    asm("{ .reg .u64 t; cvta.to.shared.u64 t, %1; cvt.u32.u64 %0, t; }" : "=r"(a) : "l"(p));
    return a;
}
__device__ __forceinline__ void cpa16(uint32_t d, const void* s){
    asm volatile("cp.async.cg.shared.global [%0], [%1], 16;" :: "r"(d), "l"(s));
}
__device__ __forceinline__ void cpa_commit(){ asm volatile("cp.async.commit_group;" ::: "memory"); }
__device__ __forceinline__ void cpa_wait1(){ asm volatile("cp.async.wait_group 1;" ::: "memory"); }
__device__ __forceinline__ void cpa_wait0(){ asm volatile("cp.async.wait_group 0;" ::: "memory"); }
__device__ __forceinline__ void ldsm4(uint32_t* r, uint32_t a){
    asm volatile("ldmatrix.sync.aligned.m8n8.x4.shared.b16 {%0,%1,%2,%3}, [%4];"
        : "=r"(r[0]), "=r"(r[1]), "=r"(r[2]), "=r"(r[3]) : "r"(a));
}
__device__ __forceinline__ void mma16816(float* d, const uint32_t* a, const uint32_t* b){
    asm volatile(
        "mma.sync.aligned.m16n8k16.row.col.f32.bf16.bf16.f32 "
        "{%0,%1,%2,%3}, {%4,%5,%6,%7}, {%8,%9}, {%0,%1,%2,%3};"
        : "+f"(d[0]), "+f"(d[1]), "+f"(d[2]), "+f"(d[3])
        : "r"(a[0]), "r"(a[1]), "r"(a[2]), "r"(a[3]), "r"(b[0]), "r"(b[1]));
}
__device__ __forceinline__ uint32_t packbf2(float x, float y){
    __nv_bfloat162 p; p.x = __float2bfloat16(x); p.y = __float2bfloat16(y);
    return *(uint32_t*)&p;
}

// stage one [128 rows][64 k] bf16 tile, SW128 swizzle, cp.async — 256-thread version
__device__ __forceinline__ void stage_tile(uint32_t smA, const __nv_bfloat16* g, int ld,
                                           int row0, int k0, int tid)
{
    int r = tid >> 1, s0 = (tid & 1) * 4;
    const __nv_bfloat16* src = g + (long long)(row0 + r) * ld + k0 + s0 * 8;
    uint32_t offb = (uint32_t)(r * 128 + s0 * 16);
    #pragma unroll
    for (int j = 0; j < 4; j++){
        uint32_t off = offb + j * 16;
        uint32_t sw = off ^ ((off >> 3) & 0x70u);
        cpa16(smA + sw, src + j * 8);
    }
}
// 512-thread version (4 threads per row, 2x16B each)
__device__ __forceinline__ void stage_tile512(uint32_t smA, const __nv_bfloat16* g, int ld,
                                              int row0, int k0, int tid)
{
    int r = tid >> 2, s0 = (tid & 3) * 2;
    const __nv_bfloat16* src = g + (long long)(row0 + r) * ld + k0 + s0 * 8;
    uint32_t offb = (uint32_t)(r * 128 + s0 * 16);
    #pragma unroll
    for (int j = 0; j < 2; j++){
        uint32_t off = offb + j * 16;
        uint32_t sw = off ^ ((off >> 3) & 0x70u);
        cpa16(smA + sw, src + j * 8);
    }
}

struct OutD {
    float* f;
    __nv_bfloat16* h;
    __nv_bfloat16* l;
    const float* rowscale;
    float factor;
    int ldc;
    int colsub;
    int relu;
    long long sC;
};

#define SMEM_DYN 131072

// ================= dense GEMM: 512 threads, 16 warps, warp 32x32, block 128x128 =================
__global__ __launch_bounds__(512, 1)
void bf_gemm(const __nv_bfloat16* __restrict__ Ah1, const __nv_bfloat16* __restrict__ Al1, int lda1, int K1,
             const __nv_bfloat16* __restrict__ Ah2, const __nv_bfloat16* __restrict__ Al2, int lda2, int Ktot,
             const __nv_bfloat16* __restrict__ Bh,  const __nv_bfloat16* __restrict__ Bl,  int ldb,
             const float* __restrict__ bias, long long sA1, long long sB,
             OutD o0, OutD o1)
{
    extern __shared__ __align__(1024) char smraw[];
    const uint32_t smb = smem_u32(smraw);
    const int tid = threadIdx.x, wid = tid >> 5, lane = tid & 31;
    const int wm = wid >> 2, wn = wid & 3;
    const int row0 = blockIdx.y * 128, col0 = blockIdx.x * 128;
    const int z = blockIdx.z;
    Ah1 += (long long)z * sA1; Al1 += (long long)z * sA1;
    Bh  += (long long)z * sB;  Bl  += (long long)z * sB;

    const int arow = ((lane >> 3) & 1) * 8 + (lane & 7);
    const int ak8  = ((lane >> 4) & 1) * 8;
    const int brow = ((lane >> 4) & 1) * 8 + (lane & 7);
    const int bk8  = ((lane >> 3) & 1) * 8;

    float acc[2][4][4];
    #pragma unroll
    for (int i = 0; i < 2; i++)
        #pragma unroll
        for (int j = 0; j < 4; j++)
            #pragma unroll
            for (int k = 0; k < 4; k++) acc[i][j][k] = 0.f;

    const int T = Ktot / 64;
    auto do_stage = [&](int t, int buf){
        int k0 = t * 64;
        const __nv_bfloat16 *h, *l; int ld, ka;
        if (k0 < K1){ h = Ah1; l = Al1; ld = lda1; ka = k0; }
        else        { h = Ah2; l = Al2; ld = lda2; ka = k0 - K1; }
        uint32_t sb = smb + buf * 65536;
        stage_tile512(sb + 0,     h,  ld,  row0, ka, tid);
        stage_tile512(sb + 16384, l,  ld,  row0, ka, tid);
        stage_tile512(sb + 32768, Bh, ldb, col0, k0, tid);
        stage_tile512(sb + 49152, Bl, ldb, col0, k0, tid);
        cpa_commit();
    };

    do_stage(0, 0);
    for (int t = 0; t < T; t++){
        if (t + 1 < T){ do_stage(t + 1, (t + 1) & 1); cpa_wait1(); }
        else          { cpa_wait0(); }
        __syncthreads();
        uint32_t sm = smb + (t & 1) * 65536;
        #pragma unroll
        for (int ks = 0; ks < 4; ks++){
            const int kk = ks * 16;
            uint32_t ah[2][4], al[2][4], bh[4][2], bl[4][2], t4[4];
            #pragma unroll
            for (int mt = 0; mt < 2; mt++){
                uint32_t off = (uint32_t)((wm*32 + mt*16 + arow) * 128 + (kk + ak8) * 2);
                uint32_t sw = off ^ ((off >> 3) & 0x70u);
                ldsm4(ah[mt], sm + 0     + sw);
                ldsm4(al[mt], sm + 16384 + sw);
            }
            #pragma unroll
            for (int np = 0; np < 2; np++){
                uint32_t off = (uint32_t)((wn*32 + np*16 + brow) * 128 + (kk + bk8) * 2);
                uint32_t sw = off ^ ((off >> 3) & 0x70u);
                ldsm4(t4, sm + 32768 + sw);
                bh[np*2][0]=t4[0]; bh[np*2][1]=t4[1]; bh[np*2+1][0]=t4[2]; bh[np*2+1][1]=t4[3];
                ldsm4(t4, sm + 49152 + sw);
                bl[np*2][0]=t4[0]; bl[np*2][1]=t4[1]; bl[np*2+1][0]=t4[2]; bl[np*2+1][1]=t4[3];
            }
            #pragma unroll
            for (int mt = 0; mt < 2; mt++)
                #pragma unroll
                for (int nt = 0; nt < 4; nt++){
                    mma16816(acc[mt][nt], ah[mt], bh[nt]);
                    mma16816(acc[mt][nt], ah[mt], bl[nt]);
                    mma16816(acc[mt][nt], al[mt], bh[nt]);
                }
        }
        __syncthreads();
    }

    const OutD& od = (blockIdx.x == 0) ? o0 : o1;
    const int lq = lane >> 2, le = (lane & 3) * 2;
    #pragma unroll
    for (int mt = 0; mt < 2; mt++){
        int gr0 = row0 + wm*32 + mt*16 + lq;
        float rs0 = od.rowscale ? od.rowscale[gr0]   * od.factor : od.factor;
        float rs1 = od.rowscale ? od.rowscale[gr0+8] * od.factor : od.factor;
        #pragma unroll
        for (int nt = 0; nt < 4; nt++){
            int gc = col0 + wn*32 + nt*8 + le;
            float b0 = bias ? bias[gc] : 0.f, b1 = bias ? bias[gc+1] : 0.f;
            float v00 = (acc[mt][nt][0] + b0) * rs0, v01 = (acc[mt][nt][1] + b1) * rs0;
            float v10 = (acc[mt][nt][2] + b0) * rs1, v11 = (acc[mt][nt][3] + b1) * rs1;
            if (od.relu){
                v00 = fmaxf(v00, 0.f); v01 = fmaxf(v01, 0.f);
                v10 = fmaxf(v10, 0.f); v11 = fmaxf(v11, 0.f);
            }
            long long i0 = od.sC * z + (long long)gr0 * od.ldc + (gc - od.colsub);
            long long i1 = od.sC * z + (long long)(gr0 + 8) * od.ldc + (gc - od.colsub);
            if (od.f){
                *(float2*)(od.f + i0) = make_float2(v00, v01);
                *(float2*)(od.f + i1) = make_float2(v10, v11);
            }
            if (od.h){
                __nv_bfloat162 ph, pl;
                bsplit(v00, ph.x, pl.x); bsplit(v01, ph.y, pl.y);
                *(__nv_bfloat162*)(od.h + i0) = ph; *(__nv_bfloat162*)(od.l + i0) = pl;
                bsplit(v10, ph.x, pl.x); bsplit(v11, ph.y, pl.y);
                *(__nv_bfloat162*)(od.h + i1) = ph; *(__nv_bfloat162*)(od.l + i1) = pl;
            }
        }
    }
}

// ================= flash attention (unchanged from R6): 256 threads =================
__global__ __launch_bounds__(256, 1)
void flash_kernel(const __nv_bfloat16* __restrict__ Qh, const __nv_bfloat16* __restrict__ Ql,
                  const __nv_bfloat16* __restrict__ Kh, const __nv_bfloat16* __restrict__ Kl,
                  const __nv_bfloat16* __restrict__ Oh, const __nv_bfloat16* __restrict__ Ol,
                  const __nv_bfloat16* __restrict__ Vh, const __nv_bfloat16* __restrict__ Vl,
                  __nv_bfloat16* __restrict__ aggh, __nv_bfloat16* __restrict__ aggl)
{
    extern __shared__ __align__(1024) char smraw[];
    const uint32_t smb = smem_u32(smraw);
    const int tid = threadIdx.x, w = tid >> 5, lane = tid & 31;
    const int q0 = blockIdx.x * 128;
    const int b = blockIdx.y;
    const int gr = b * NAG;
    const long long vbase = (long long)b * MSG * NAG;

    const int arow = ((lane >> 3) & 1) * 8 + (lane & 7);
    const int ak8  = ((lane >> 4) & 1) * 8;
    const int brow = ((lane >> 4) & 1) * 8 + (lane & 7);
    const int bk8  = ((lane >> 3) & 1) * 8;
    const int lq = lane >> 2;

    float O[16][4];
    #pragma unroll
    for (int nt = 0; nt < 16; nt++)
        #pragma unroll
        for (int j = 0; j < 4; j++) O[nt][j] = 0.f;
    float m0 = -1e30f, m1 = -1e30f, sum0 = 0.f, sum1 = 0.f;

    for (int kt = 0; kt < 4; kt++){
        const int k0 = kt * 128;

        float S[16][4];
        #pragma unroll
        for (int nt = 0; nt < 16; nt++)
            #pragma unroll
            for (int j = 0; j < 4; j++) S[nt][j] = 0.f;

        auto do_stage = [&](int t, int buf){
            uint32_t sb = smb + buf * 65536;
            if (t < 2){
                stage_tile(sb + 0,     Qh, 256, gr + q0, t*64, tid);
                stage_tile(sb + 16384, Ql, 256, gr + q0, t*64, tid);
                stage_tile(sb + 32768, Kh, 128, gr + k0, t*64, tid);
                stage_tile(sb + 49152, Kl, 128, gr + k0, t*64, tid);
            } else {
                stage_tile(sb + 0,     Oh, 128, gr + q0, (t-2)*64, tid);
                stage_tile(sb + 16384, Ol, 128, gr + q0, (t-2)*64, tid);
                stage_tile(sb + 32768, Oh, 128, gr + k0, (t-2)*64, tid);
                stage_tile(sb + 49152, Ol, 128, gr + k0, (t-2)*64, tid);
            }
            cpa_commit();
        };

        do_stage(0, 0);
        for (int t = 0; t < 4; t++){
            if (t + 1 < 4){ do_stage(t + 1, (t + 1) & 1); cpa_wait1(); }
            else          { cpa_wait0(); }
            __syncthreads();
            uint32_t sm = smb + (t & 1) * 65536;
            #pragma unroll
            for (int ks = 0; ks < 4; ks++){
                const int kk = ks * 16;
                uint32_t ah[4], al[4], th[4], tl[4];
                {
                    uint32_t off = (uint32_t)((w*16 + arow) * 128 + (kk + ak8) * 2);
                    uint32_t sw = off ^ ((off >> 3) & 0x70u);
                    ldsm4(ah, sm + 0     + sw);
                    ldsm4(al, sm + 16384 + sw);
                }
                #pragma unroll
                for (int np = 0; np < 8; np++){
                    uint32_t off = (uint32_t)((np*16 + brow) * 128 + (kk + bk8) * 2);
                    uint32_t sw = off ^ ((off >> 3) & 0x70u);
                    ldsm4(th, sm + 32768 + sw);
                    ldsm4(tl, sm + 49152 + sw);
                    uint32_t b0[2] = {th[0], th[1]}, b1[2] = {th[2], th[3]};
                    uint32_t c0[2] = {tl[0], tl[1]}, c1[2] = {tl[2], tl[3]};
                    mma16816(S[np*2],   ah, b0);
                    mma16816(S[np*2],   ah, c0);
                    mma16816(S[np*2],   al, b0);
                    mma16816(S[np*2+1], ah, b1);
                    mma16816(S[np*2+1], ah, c1);
                    mma16816(S[np*2+1], al, b1);
                }
            }
            __syncthreads();
        }

        float mx0 = -1e30f, mx1 = -1e30f;
        #pragma unroll
        for (int nt = 0; nt < 16; nt++){
            mx0 = fmaxf(mx0, fmaxf(S[nt][0], S[nt][1]));
            mx1 = fmaxf(mx1, fmaxf(S[nt][2], S[nt][3]));
        }
        mx0 = fmaxf(mx0, __shfl_xor_sync(0xffffffffu, mx0, 1));
        mx0 = fmaxf(mx0, __shfl_xor_sync(0xffffffffu, mx0, 2));
        mx1 = fmaxf(mx1, __shfl_xor_sync(0xffffffffu, mx1, 1));
        mx1 = fmaxf(mx1, __shfl_xor_sync(0xffffffffu, mx1, 2));
        float M0 = fmaxf(m0, mx0), M1 = fmaxf(m1, mx1);
        float f0 = __expf(m0 - M0), f1 = __expf(m1 - M1);
        float rs0 = 0.f, rs1 = 0.f;
        #pragma unroll
        for (int nt = 0; nt < 16; nt++){
            float p0 = __expf(S[nt][0] - M0); S[nt][0] = p0; rs0 += p0;
            float p1 = __expf(S[nt][1] - M0); S[nt][1] = p1; rs0 += p1;
            float p2 = __expf(S[nt][2] - M1); S[nt][2] = p2; rs1 += p2;
            float p3 = __expf(S[nt][3] - M1); S[nt][3] = p3; rs1 += p3;
        }
        rs0 += __shfl_xor_sync(0xffffffffu, rs0, 1);
        rs0 += __shfl_xor_sync(0xffffffffu, rs0, 2);
        rs1 += __shfl_xor_sync(0xffffffffu, rs1, 1);
        rs1 += __shfl_xor_sync(0xffffffffu, rs1, 2);
        sum0 = sum0 * f0 + rs0;
        sum1 = sum1 * f1 + rs1;
        m0 = M0; m1 = M1;
        #pragma unroll
        for (int nt = 0; nt < 16; nt++){
            O[nt][0] *= f0; O[nt][1] *= f0; O[nt][2] *= f1; O[nt][3] *= f1;
        }

        stage_tile(smb + 0,     Vh + vbase, NAG, 0, k0,      tid);
        stage_tile(smb + 16384, Vl + vbase, NAG, 0, k0,      tid);
        stage_tile(smb + 32768, Vh + vbase, NAG, 0, k0 + 64, tid);
        stage_tile(smb + 49152, Vl + vbase, NAG, 0, k0 + 64, tid);
        cpa_commit(); cpa_wait0();
        __syncthreads();

        #pragma unroll
        for (int ks = 0; ks < 8; ks++){
            uint32_t aph[4], apl[4];
            {
                float p00 = S[2*ks][0],   p01 = S[2*ks][1];
                float p10 = S[2*ks][2],   p11 = S[2*ks][3];
                float p20 = S[2*ks+1][0], p21 = S[2*ks+1][1];
                float p30 = S[2*ks+1][2], p31 = S[2*ks+1][3];
                aph[0] = packbf2(p00, p01);
                aph[1] = packbf2(p10, p11);
                aph[2] = packbf2(p20, p21);
                aph[3] = packbf2(p30, p31);
                __nv_bfloat162 h0 = *(__nv_bfloat162*)&aph[0];
                __nv_bfloat162 h1 = *(__nv_bfloat162*)&aph[1];
                __nv_bfloat162 h2 = *(__nv_bfloat162*)&aph[2];
                __nv_bfloat162 h3 = *(__nv_bfloat162*)&aph[3];
                apl[0] = packbf2(p00 - __bfloat162float(h0.x), p01 - __bfloat162float(h0.y));
                apl[1] = packbf2(p10 - __bfloat162float(h1.x), p11 - __bfloat162float(h1.y));
                apl[2] = packbf2(p20 - __bfloat162float(h2.x), p21 - __bfloat162float(h2.y));
                apl[3] = packbf2(p30 - __bfloat162float(h3.x), p31 - __bfloat162float(h3.y));
            }
            uint32_t base = (ks < 4) ? smb : smb + 32768;
            uint32_t basl = base + 16384;
            const int kk = (ks & 3) * 16;
            #pragma unroll
            for (int np = 0; np < 8; np++){
                uint32_t off = (uint32_t)((np*16 + brow) * 128 + (kk + bk8) * 2);
                uint32_t sw = off ^ ((off >> 3) & 0x70u);
                uint32_t th[4], tl[4];
                ldsm4(th, base + sw);
                ldsm4(tl, basl + sw);
                uint32_t b0[2] = {th[0], th[1]}, b1[2] = {th[2], th[3]};
                uint32_t c0[2] = {tl[0], tl[1]}, c1[2] = {tl[2], tl[3]};
                mma16816(O[np*2],   aph, b0);
                mma16816(O[np*2],   aph, c0);
                mma16816(O[np*2],   apl, b0);
                mma16816(O[np*2+1], aph, b1);
                mma16816(O[np*2+1], aph, c1);
                mma16816(O[np*2+1], apl, b1);
            }
        }
        __syncthreads();
    }

    float inv0 = 1.f / sum0, inv1 = 1.f / sum1;
    long long r0 = (long long)(gr + q0 + w*16 + lq) * MSG;
    long long r1 = r0 + 8 * MSG;
    #pragma unroll
    for (int nt = 0; nt < 16; nt++){
        int d = nt*8 + (lane & 3)*2;
        __nv_bfloat162 ph, pl;
        bsplit(O[nt][0] * inv0, ph.x, pl.x);
        bsplit(O[nt][1] * inv0, ph.y, pl.y);
        *(__nv_bfloat162*)(aggh + r0 + d) = ph;
        *(__nv_bfloat162*)(aggl + r0 + d) = pl;
        bsplit(O[nt][2] * inv1, ph.x, pl.x);
        bsplit(O[nt][3] * inv1, ph.y, pl.y);
        *(__nv_bfloat162*)(aggh + r1 + d) = ph;
        *(__nv_bfloat162*)(aggl + r1 + d) = pl;
    }
}

// ---------------- packing kernels ----------------
__global__ void pack_obs(const float* __restrict__ obs,
                         __nv_bfloat16* __restrict__ h, __nv_bfloat16* __restrict__ l)
{
    long long i = (long long)blockIdx.x * 256 + threadIdx.x;
    __nv_bfloat16 hh, ll; bsplit(obs[i], hh, ll);
    h[i] = hh; l[i] = ll;
}
__global__ void pack_obss(const float* __restrict__ obs, const float* __restrict__ nrm,
                          __nv_bfloat16* __restrict__ h, __nv_bfloat16* __restrict__ l)
{
    long long i = (long long)blockIdx.x * 256 + threadIdx.x;
    int row = (int)(i >> 7);
    float s = 0.7071067811865476f / (nrm[row] + 1e-8f);
    __nv_bfloat16 hh, ll; bsplit(obs[i] * s, hh, ll);
    h[i] = hh; l[i] = ll;
}
__global__ void pack_we(const float* __restrict__ We,
                        __nv_bfloat16* __restrict__ hi, __nv_bfloat16* __restrict__ lo)
{
    int i = blockIdx.x * 256 + threadIdx.x;
    int n = i >> 7, k = i & 127;
    __nv_bfloat16 h, l; bsplit(We[k*256 + n], h, l);
    hi[i] = h; lo[i] = l;
}
__global__ void pack_wcat(const float* __restrict__ Wc, const float* __restrict__ Wn,
                          const float* __restrict__ Wb, const float* __restrict__ Wq,
                          const float* __restrict__ bc, const float* __restrict__ bn,
                          const float* __restrict__ bbp, const float* __restrict__ bq,
                          __nv_bfloat16* __restrict__ hi, __nv_bfloat16* __restrict__ lo,
                          float* __restrict__ bcat)
{
    int i = blockIdx.x * 256 + threadIdx.x;
    int n = i >> 8, k = i & 255;
    float v;
    if (n < 32)       v = Wc[k*32 + n];
    else if (n < 96)  v = Wn[k*64 + (n-32)];
    else if (n < 128) v = Wb[k*32 + (n-96)];
    else              v = Wq[k*128 + (n-128)];
    __nv_bfloat16 h, l; bsplit(v, h, l);
    hi[i] = h; lo[i] = l;
    if (k == 0)
        bcat[n] = (n < 32) ? bc[n] : (n < 96) ? bn[n-32] : (n < 128) ? bbp[n-96] : bq[n-128];
}
__global__ void pack_wkv(const float* __restrict__ Wk, const float* __restrict__ Wv,
                         const float* __restrict__ bk, const float* __restrict__ bv,
                         __nv_bfloat16* __restrict__ hi, __nv_bfloat16* __restrict__ lo,
                         float* __restrict__ bkv)
{
    int i = blockIdx.x * 256 + threadIdx.x;
    int n = i >> 7, k = i & 127;
    float v = (n < 128) ? Wk[k*128 + n] : Wv[k*128 + (n-128)];
    __nv_bfloat16 h, l; bsplit(v, h, l);
    hi[i] = h; lo[i] = l;
    if (k == 0) bkv[n] = (n < 128) ? bk[n] : bv[n-128];
}
__global__ void pack_wp(const float* __restrict__ Wp,
                        __nv_bfloat16* __restrict__ hi, __nv_bfloat16* __restrict__ lo)
{
    int i = blockIdx.x * 256 + threadIdx.x;
    int n = i / 384, k = i % 384;
    __nv_bfloat16 h, l; bsplit(Wp[k*256 + n], h, l);
    hi[i] = h; lo[i] = l;
}
__global__ void pack_vT(const float* __restrict__ v,
                        __nv_bfloat16* __restrict__ hi, __nv_bfloat16* __restrict__ lo)
{
    __shared__ float t[32][33];
    int b = blockIdx.z;
    int k0 = blockIdx.x * 32, d0 = blockIdx.y * 32;
    for (int i = threadIdx.y; i < 32; i += 8)
        t[i][threadIdx.x] = v[((long long)(b*512 + k0 + i))*128 + d0 + threadIdx.x];
    __syncthreads();
    for (int i = threadIdx.y; i < 32; i += 8){
        __nv_bfloat16 h, l; bsplit(t[threadIdx.x][i], h, l);
        long long o = ((long long)(b*128 + d0 + i))*512 + k0 + threadIdx.x;
        hi[o] = h; lo[o] = l;
    }
}

// ---------------- importance + obs norm ----------------
__global__ void impnorm_kernel(const __nv_bfloat16* __restrict__ eh,
                               const __nv_bfloat16* __restrict__ el,
                               const float* __restrict__ obs,
                               const float* __restrict__ Wi,
                               const float* __restrict__ bi,
                               float* __restrict__ imp,
                               float* __restrict__ nrm)
{
    int row = blockIdx.x * 8 + threadIdx.y;
    int lane = threadIdx.x;
    const __nv_bfloat16* ph = eh + (long long)row * HID;
    const __nv_bfloat16* pl = el + (long long)row * HID;
    const float* o = obs + (long long)row * OBS;
    float d = 0.f, ss = 0.f;
    #pragma unroll
    for (int i = 0; i < HID/32; i++){
        int k = lane + 32*i;
        float e = __bfloat162float(ph[k]) + __bfloat162float(pl[k]);
        d += e * Wi[k];
    }
    #pragma unroll
    for (int i = 0; i < OBS/32; i++){ float v = o[lane + 32*i]; ss += v*v; }
    #pragma unroll
    for (int off = 16; off; off >>= 1){
        d  += __shfl_down_sync(0xffffffffu, d, off);
        ss += __shfl_down_sync(0xffffffffu, ss, off);
    }
    if (lane == 0){
        imp[row] = 1.f / (1.f + expf(-(d + bi[0])));
        nrm[row] = sqrtf(ss);
    }
}

// ---------------- head ----------------
__global__ void head_kernel(const float* __restrict__ x,
                            const float* __restrict__ Wa,
                            const float* __restrict__ ba,
                            const float* __restrict__ Wcr,
                            const float* __restrict__ bcr,
                            float* __restrict__ out)
{
    int row = blockIdx.x * 8 + threadIdx.y;
    int lane = threadIdx.x;
    const float* xr = x + (long long)row * HID;
    float xv[8];
    #pragma unroll
    for (int i = 0; i < 8; i++) xv[i] = xr[lane + 32*i];
    #pragma unroll
    for (int j = 0; j < 17; j++){
        float p = 0.f;
        #pragma unroll
        for (int i = 0; i < 8; i++){
            int k = lane + 32*i;
            float w = (j < 16) ? Wa[(long long)k * NACT + j] : Wcr[k];
            p += xv[i] * w;
        }
        #pragma unroll
        for (int off = 16; off; off >>= 1) p += __shfl_down_sync(0xffffffffu, p, off);
        if (lane == 0){
            if (j < 16) out[(long long)row * NACT + j] = p + ba[j];
            else        out[(long long)ROWS * NACT + row] = p + bcr[0];
        }
    }
}

// ---------------- launch ----------------
extern "C" void kernel_launch(void* const* d_in, const int* in_sizes, int n_in,
                              void* d_out, int out_size)
{
    const float* obs = (const float*)d_in[0];
    const float* We  = (const float*)d_in[2];   const float* be  = (const float*)d_in[3];
    const float* Wc  = (const float*)d_in[4];   const float* bc  = (const float*)d_in[5];
    const float* Wn  = (const float*)d_in[6];   const float* bn  = (const float*)d_in[7];
    const float* Wb  = (const float*)d_in[8];   const float* bbp = (const float*)d_in[9];
    const float* Wi  = (const float*)d_in[10];  const float* bi  = (const float*)d_in[11];
    const float* Wq  = (const float*)d_in[12];  const float* bq  = (const float*)d_in[13];
    const float* Wk  = (const float*)d_in[14];  const float* bk  = (const float*)d_in[15];
    const float* Wv  = (const float*)d_in[16];  const float* bv  = (const float*)d_in[17];
    const float* Wp  = (const float*)d_in[18];  const float* bp  = (const float*)d_in[19];
    const float* Wa  = (const float*)d_in[20];  const float* ba  = (const float*)d_in[21];
    const float* Wcr = (const float*)d_in[22];  const float* bcr = (const float*)d_in[23];
    float* out = (float*)d_out;

    #define GA(p, sym) cudaGetSymbolAddress((void**)&p, sym)
    __nv_bfloat16 *ench,*encl,*mqh,*mql,*ksh,*ksl,*obh,*obl,*osh,*osl,*vth,*vtl,*agh,*agl;
    __nv_bfloat16 *WeTh,*WeTl,*WcTh,*WcTl,*WkvTh,*WkvTl,*WpTh,*WpTl;
    float *vbuf,*imp,*nrm,*xb,*bcat,*bkv;
    GA(ench,g_enc_h); GA(encl,g_enc_l); GA(mqh,g_msgq_h); GA(mql,g_msgq_l);
    GA(ksh,g_ks_h); GA(ksl,g_ks_l); GA(obh,g_obs_h); GA(obl,g_obs_l);
    GA(osh,g_obss_h); GA(osl,g_obss_l);
    GA(vth,g_vT_h); GA(vtl,g_vT_l); GA(agh,g_agg_h); GA(agl,g_agg_l);
    GA(vbuf,g_v); GA(imp,g_imp); GA(nrm,g_nrm); GA(xb,g_x);
    GA(bcat,g_bcat); GA(bkv,g_bkv);
    GA(WeTh,g_WeT_h); GA(WeTl,g_WeT_l); GA(WcTh,g_WcatT_h); GA(WcTl,g_WcatT_l);
    GA(WkvTh,g_WkvT_h); GA(WkvTl,g_WkvT_l); GA(WpTh,g_WpT_h); GA(WpTl,g_WpT_l);
    #undef GA

    cudaFuncSetAttribute(bf_gemm,      cudaFuncAttributeMaxDynamicSharedMemorySize, SMEM_DYN);
    cudaFuncSetAttribute(flash_kernel, cudaFuncAttributeMaxDynamicSharedMemorySize, SMEM_DYN);

    OutD z = {};

    // 0. packs
    pack_we  <<<128, 256>>>(We, WeTh, WeTl);
    pack_wcat<<<256, 256>>>(Wc, Wn, Wb, Wq, bc, bn, bbp, bq, WcTh, WcTl, bcat);
    pack_wkv <<<128, 256>>>(Wk, Wv, bk, bv, WkvTh, WkvTl, bkv);
    pack_wp  <<<384, 256>>>(Wp, WpTh, WpTl);
    pack_obs <<<ROWS*OBS/256, 256>>>(obs, obh, obl);

    // 1. enc = relu(obs @ We + be) -> hi/lo
    {
        OutD o = z; o.h = ench; o.l = encl; o.factor = 1.f; o.ldc = 256; o.relu = 1;
        bf_gemm<<<dim3(2,256,1), 512, SMEM_DYN>>>(obh, obl, OBS, OBS, nullptr, nullptr, 0, OBS,
                                                  WeTh, WeTl, OBS, be, 0, 0, o, o);
    }
    // 2. imp + nrm
    impnorm_kernel<<<ROWS/8, dim3(32,8)>>>(ench, encl, obs, Wi, bi, imp, nrm);
    // 3. obs scaled pack
    pack_obss<<<ROWS*OBS/256, 256>>>(obs, nrm, osh, osl);
    // 4. msgq = enc @ Wcat + bcat; Q block scaled by imp/sqrt(128)
    {
        OutD o0 = z; o0.h = mqh; o0.l = mql; o0.factor = 1.f; o0.ldc = 256;
        OutD o1 = o0; o1.rowscale = imp; o1.factor = 0.08838834764831845f;
        bf_gemm<<<dim3(2,256,1), 512, SMEM_DYN>>>(ench, encl, 256, 256, nullptr, nullptr, 0, 256,
                                                  WcTh, WcTl, 256, bcat, 0, 0, o0, o1);
    }
    // 5. kv: K scaled by imp -> hi/lo; V -> fp32
    {
        OutD o0 = z; o0.h = ksh; o0.l = ksl; o0.rowscale = imp; o0.factor = 1.f; o0.ldc = 128;
        OutD o1 = z; o1.f = vbuf; o1.factor = 1.f; o1.ldc = 128; o1.colsub = 128;
        bf_gemm<<<dim3(2,256,1), 512, SMEM_DYN>>>(mqh, mql, 256, 128, nullptr, nullptr, 0, 128,
                                                  WkvTh, WkvTl, 128, bkv, 0, 0, o0, o1);
    }
    // 6. V transpose + split
    pack_vT<<<dim3(16,4,BSZ), dim3(32,8)>>>(vbuf, vth, vtl);
    // 7. flash attention -> agg hi/lo
    flash_kernel<<<dim3(4, BSZ), 256, SMEM_DYN>>>(mqh + 128, mql + 128, ksh, ksl,
                                                  osh, osl, vth, vtl, agh, agl);
    // 8. x = relu([enc|agg] @ Wp + bp) -> fp32
    {
        OutD o = z; o.f = xb; o.factor = 1.f; o.ldc = 256; o.relu = 1;
        bf_gemm<<<dim3(2,256,1), 512, SMEM_DYN>>>(ench, encl, 256, 256, agh, agl, 128, 384,
                                                  WpTh, WpTl, 384, bp, 0, 0, o, o);
    }
    // 9. heads
    head_kernel<<<ROWS/8, dim3(32,8)>>>(xb, Wa, ba, Wcr, bcr, out);
}

// round 9
// speedup vs baseline: 2.7931x; 1.0431x over previous
#include <cuda_runtime.h>
#include <cuda_bf16.h>
#include <stdint.h>
#include <math.h>

#define BSZ 64
#define NAG 512
#define OBS 128
#define HID 256
#define MSG 128
#define NACT 16
#define ROWS (BSZ*NAG)   // 32768

// ---------------- scratch (device globals) ----------------
__device__ __align__(16) __nv_bfloat16 g_enc_h[(size_t)ROWS*HID],  g_enc_l[(size_t)ROWS*HID];
__device__ __align__(16) __nv_bfloat16 g_msgq_h[(size_t)ROWS*256], g_msgq_l[(size_t)ROWS*256]; // 0-127 msg, 128-255 Q(scaled)
__device__ __align__(16) __nv_bfloat16 g_ks_h[(size_t)ROWS*MSG],   g_ks_l[(size_t)ROWS*MSG];   // K scaled by imp
__device__ float g_v[(size_t)ROWS*MSG];
__device__ __align__(16) __nv_bfloat16 g_obs_h[(size_t)ROWS*OBS],  g_obs_l[(size_t)ROWS*OBS];
__device__ __align__(16) __nv_bfloat16 g_obss_h[(size_t)ROWS*OBS], g_obss_l[(size_t)ROWS*OBS]; // scaled sqrt(.5)/nrm
__device__ float g_imp[ROWS];
__device__ __align__(16) __nv_bfloat16 g_vT_h[(size_t)BSZ*MSG*NAG], g_vT_l[(size_t)BSZ*MSG*NAG];
__device__ __align__(16) __nv_bfloat16 g_agg_h[(size_t)ROWS*MSG],  g_agg_l[(size_t)ROWS*MSG];
__device__ float g_x[(size_t)ROWS*HID];
__device__ float g_bcat[256];
__device__ float g_bkv[256];
__device__ __align__(16) __nv_bfloat16 g_WeT_h[256*128],  g_WeT_l[256*128];
__device__ __align__(16) __nv_bfloat16 g_WcatT_h[256*256],g_WcatT_l[256*256];
__device__ __align__(16) __nv_bfloat16 g_WkvT_h[256*128], g_WkvT_l[256*128];
__device__ __align__(16) __nv_bfloat16 g_WpT_h[256*384],  g_WpT_l[256*384];

// ---------------- helpers ----------------
__device__ __forceinline__ void bsplit(float x, __nv_bfloat16& h, __nv_bfloat16& l){
    h = __float2bfloat16(x);
    l = __float2bfloat16(x - __bfloat162float(h));
}
__device__ __forceinline__ uint32_t smem_u32(const void* p){
    uint32_t a;
    asm("{ .reg .u64 t; cvta.to.shared.u64 t, %1; cvt.u32.u64 %0, t; }" : "=r"(a) : "l"(p));
    return a;
}
__device__ __forceinline__ void cpa16(uint32_t d, const void* s){
    asm volatile("cp.async.cg.shared.global [%0], [%1], 16;" :: "r"(d), "l"(s));
}
__device__ __forceinline__ void cpa_commit(){ asm volatile("cp.async.commit_group;" ::: "memory"); }
__device__ __forceinline__ void cpa_wait0(){ asm volatile("cp.async.wait_group 0;" ::: "memory"); }
__device__ __forceinline__ void cpa_wait1(){ asm volatile("cp.async.wait_group 1;" ::: "memory"); }
__device__ __forceinline__ void cpa_wait2(){ asm volatile("cp.async.wait_group 2;" ::: "memory"); }
__device__ __forceinline__ void ldsm4(uint32_t* r, uint32_t a){
    asm volatile("ldmatrix.sync.aligned.m8n8.x4.shared.b16 {%0,%1,%2,%3}, [%4];"
        : "=r"(r[0]), "=r"(r[1]), "=r"(r[2]), "=r"(r[3]) : "r"(a));
}
__device__ __forceinline__ void mma16816(float* d, const uint32_t* a, const uint32_t* b){
    asm volatile(
        "mma.sync.aligned.m16n8k16.row.col.f32.bf16.bf16.f32 "
        "{%0,%1,%2,%3}, {%4,%5,%6,%7}, {%8,%9}, {%0,%1,%2,%3};"
        : "+f"(d[0]), "+f"(d[1]), "+f"(d[2]), "+f"(d[3])
        : "r"(a[0]), "r"(a[1]), "r"(a[2]), "r"(a[3]), "r"(b[0]), "r"(b[1]));
}
__device__ __forceinline__ uint32_t packbf2(float x, float y){
    __nv_bfloat162 p; p.x = __float2bfloat16(x); p.y = __float2bfloat16(y);
    return *(uint32_t*)&p;
}

// stage one [128 rows][64 k] bf16 tile, SW128 swizzle, cp.async — 256-thread version
__device__ __forceinline__ void stage_tile(uint32_t smA, const __nv_bfloat16* g, int ld,
                                           int row0, int k0, int tid)
{
    int r = tid >> 1, s0 = (tid & 1) * 4;
    const __nv_bfloat16* src = g + (long long)(row0 + r) * ld + k0 + s0 * 8;
    uint32_t offb = (uint32_t)(r * 128 + s0 * 16);
    #pragma unroll
    for (int j = 0; j < 4; j++){
        uint32_t off = offb + j * 16;
        uint32_t sw = off ^ ((off >> 3) & 0x70u);
        cpa16(smA + sw, src + j * 8);
    }
}
// 512-thread version (4 threads per row, 2x16B each)
__device__ __forceinline__ void stage_tile512(uint32_t smA, const __nv_bfloat16* g, int ld,
                                              int row0, int k0, int tid)
{
    int r = tid >> 2, s0 = (tid & 3) * 2;
    const __nv_bfloat16* src = g + (long long)(row0 + r) * ld + k0 + s0 * 8;
    uint32_t offb = (uint32_t)(r * 128 + s0 * 16);
    #pragma unroll
    for (int j = 0; j < 2; j++){
        uint32_t off = offb + j * 16;
        uint32_t sw = off ^ ((off >> 3) & 0x70u);
        cpa16(smA + sw, src + j * 8);
    }
}

struct OutD {
    float* f;
    __nv_bfloat16* h;
    __nv_bfloat16* l;
    const float* rowscale;
    float factor;
    int ldc;
    int colsub;
    int relu;
    long long sC;
};

#define SMEM_FLASH 131072
#define SMEM_GEMM  196608   // 3 stages x 64KB

// ================= dense GEMM: 512 threads, 16 warps, warp 32x32, block 128x128, 3-stage =================
__global__ __launch_bounds__(512, 1)
void bf_gemm(const __nv_bfloat16* __restrict__ Ah1, const __nv_bfloat16* __restrict__ Al1, int lda1, int K1,
             const __nv_bfloat16* __restrict__ Ah2, const __nv_bfloat16* __restrict__ Al2, int lda2, int Ktot,
             const __nv_bfloat16* __restrict__ Bh,  const __nv_bfloat16* __restrict__ Bl,  int ldb,
             const float* __restrict__ bias, long long sA1, long long sB,
             OutD o0, OutD o1)
{
    extern __shared__ __align__(1024) char smraw[];
    const uint32_t smb = smem_u32(smraw);
    const int tid = threadIdx.x, wid = tid >> 5, lane = tid & 31;
    const int wm = wid >> 2, wn = wid & 3;
    const int row0 = blockIdx.y * 128, col0 = blockIdx.x * 128;
    const int z = blockIdx.z;
    Ah1 += (long long)z * sA1; Al1 += (long long)z * sA1;
    Bh  += (long long)z * sB;  Bl  += (long long)z * sB;

    const int arow = ((lane >> 3) & 1) * 8 + (lane & 7);
    const int ak8  = ((lane >> 4) & 1) * 8;
    const int brow = ((lane >> 4) & 1) * 8 + (lane & 7);
    const int bk8  = ((lane >> 3) & 1) * 8;

    float acc[2][4][4];
    #pragma unroll
    for (int i = 0; i < 2; i++)
        #pragma unroll
        for (int j = 0; j < 4; j++)
            #pragma unroll
            for (int k = 0; k < 4; k++) acc[i][j][k] = 0.f;

    const int T = Ktot / 64;
    auto do_stage = [&](int t, int buf){
        int k0 = t * 64;
        const __nv_bfloat16 *h, *l; int ld, ka;
        if (k0 < K1){ h = Ah1; l = Al1; ld = lda1; ka = k0; }
        else        { h = Ah2; l = Al2; ld = lda2; ka = k0 - K1; }
        uint32_t sb = smb + buf * 65536;
        stage_tile512(sb + 0,     h,  ld,  row0, ka, tid);
        stage_tile512(sb + 16384, l,  ld,  row0, ka, tid);
        stage_tile512(sb + 32768, Bh, ldb, col0, k0, tid);
        stage_tile512(sb + 49152, Bl, ldb, col0, k0, tid);
        cpa_commit();
    };

    do_stage(0, 0);
    if (T > 1) do_stage(1, 1);
    for (int t = 0; t < T; t++){
        if (t + 2 < T) do_stage(t + 2, (t + 2) % 3);
        int lastIssued = (T - 1 < t + 2) ? T - 1 : t + 2;
        int inflight = lastIssued - t + 1;
        if (inflight >= 3)      cpa_wait2();
        else if (inflight == 2) cpa_wait1();
        else                    cpa_wait0();
        __syncthreads();
        uint32_t sm = smb + (t % 3) * 65536;
        #pragma unroll
        for (int ks = 0; ks < 4; ks++){
            const int kk = ks * 16;
            uint32_t ah[2][4], al[2][4], bh[4][2], bl[4][2], t4[4];
            #pragma unroll
            for (int mt = 0; mt < 2; mt++){
                uint32_t off = (uint32_t)((wm*32 + mt*16 + arow) * 128 + (kk + ak8) * 2);
                uint32_t sw = off ^ ((off >> 3) & 0x70u);
                ldsm4(ah[mt], sm + 0     + sw);
                ldsm4(al[mt], sm + 16384 + sw);
            }
            #pragma unroll
            for (int np = 0; np < 2; np++){
                uint32_t off = (uint32_t)((wn*32 + np*16 + brow) * 128 + (kk + bk8) * 2);
                uint32_t sw = off ^ ((off >> 3) & 0x70u);
                ldsm4(t4, sm + 32768 + sw);
                bh[np*2][0]=t4[0]; bh[np*2][1]=t4[1]; bh[np*2+1][0]=t4[2]; bh[np*2+1][1]=t4[3];
                ldsm4(t4, sm + 49152 + sw);
                bl[np*2][0]=t4[0]; bl[np*2][1]=t4[1]; bl[np*2+1][0]=t4[2]; bl[np*2+1][1]=t4[3];
            }
            #pragma unroll
            for (int mt = 0; mt < 2; mt++)
                #pragma unroll
                for (int nt = 0; nt < 4; nt++){
                    mma16816(acc[mt][nt], ah[mt], bh[nt]);
                    mma16816(acc[mt][nt], ah[mt], bl[nt]);
                    mma16816(acc[mt][nt], al[mt], bh[nt]);
                }
        }
        __syncthreads();
    }

    const OutD& od = (blockIdx.x == 0) ? o0 : o1;
    const int lq = lane >> 2, le = (lane & 3) * 2;
    #pragma unroll
    for (int mt = 0; mt < 2; mt++){
        int gr0 = row0 + wm*32 + mt*16 + lq;
        float rs0 = od.rowscale ? od.rowscale[gr0]   * od.factor : od.factor;
        float rs1 = od.rowscale ? od.rowscale[gr0+8] * od.factor : od.factor;
        #pragma unroll
        for (int nt = 0; nt < 4; nt++){
            int gc = col0 + wn*32 + nt*8 + le;
            float b0 = bias ? bias[gc] : 0.f, b1 = bias ? bias[gc+1] : 0.f;
            float v00 = (acc[mt][nt][0] + b0) * rs0, v01 = (acc[mt][nt][1] + b1) * rs0;
            float v10 = (acc[mt][nt][2] + b0) * rs1, v11 = (acc[mt][nt][3] + b1) * rs1;
            if (od.relu){
                v00 = fmaxf(v00, 0.f); v01 = fmaxf(v01, 0.f);
                v10 = fmaxf(v10, 0.f); v11 = fmaxf(v11, 0.f);
            }
            long long i0 = od.sC * z + (long long)gr0 * od.ldc + (gc - od.colsub);
            long long i1 = od.sC * z + (long long)(gr0 + 8) * od.ldc + (gc - od.colsub);
            if (od.f){
                *(float2*)(od.f + i0) = make_float2(v00, v01);
                *(float2*)(od.f + i1) = make_float2(v10, v11);
            }
            if (od.h){
                __nv_bfloat162 ph, pl;
                bsplit(v00, ph.x, pl.x); bsplit(v01, ph.y, pl.y);
                *(__nv_bfloat162*)(od.h + i0) = ph; *(__nv_bfloat162*)(od.l + i0) = pl;
                bsplit(v10, ph.x, pl.x); bsplit(v11, ph.y, pl.y);
                *(__nv_bfloat162*)(od.h + i1) = ph; *(__nv_bfloat162*)(od.l + i1) = pl;
            }
        }
    }
}

// ================= flash attention: 256 threads =================
__global__ __launch_bounds__(256, 1)
void flash_kernel(const __nv_bfloat16* __restrict__ Qh, const __nv_bfloat16* __restrict__ Ql,
                  const __nv_bfloat16* __restrict__ Kh, const __nv_bfloat16* __restrict__ Kl,
                  const __nv_bfloat16* __restrict__ Oh, const __nv_bfloat16* __restrict__ Ol,
                  const __nv_bfloat16* __restrict__ Vh, const __nv_bfloat16* __restrict__ Vl,
                  __nv_bfloat16* __restrict__ aggh, __nv_bfloat16* __restrict__ aggl)
{
    extern __shared__ __align__(1024) char smraw[];
    const uint32_t smb = smem_u32(smraw);
    const int tid = threadIdx.x, w = tid >> 5, lane = tid & 31;
    const int q0 = blockIdx.x * 128;
    const int b = blockIdx.y;
    const int gr = b * NAG;
    const long long vbase = (long long)b * MSG * NAG;

    const int arow = ((lane >> 3) & 1) * 8 + (lane & 7);
    const int ak8  = ((lane >> 4) & 1) * 8;
    const int brow = ((lane >> 4) & 1) * 8 + (lane & 7);
    const int bk8  = ((lane >> 3) & 1) * 8;
    const int lq = lane >> 2;

    float O[16][4];
    #pragma unroll
    for (int nt = 0; nt < 16; nt++)
        #pragma unroll
        for (int j = 0; j < 4; j++) O[nt][j] = 0.f;
    float m0 = -1e30f, m1 = -1e30f, sum0 = 0.f, sum1 = 0.f;

    for (int kt = 0; kt < 4; kt++){
        const int k0 = kt * 128;

        float S[16][4];
        #pragma unroll
        for (int nt = 0; nt < 16; nt++)
            #pragma unroll
            for (int j = 0; j < 4; j++) S[nt][j] = 0.f;

        auto do_stage = [&](int t, int buf){
            uint32_t sb = smb + buf * 65536;
            if (t < 2){
                stage_tile(sb + 0,     Qh, 256, gr + q0, t*64, tid);
                stage_tile(sb + 16384, Ql, 256, gr + q0, t*64, tid);
                stage_tile(sb + 32768, Kh, 128, gr + k0, t*64, tid);
                stage_tile(sb + 49152, Kl, 128, gr + k0, t*64, tid);
            } else {
                stage_tile(sb + 0,     Oh, 128, gr + q0, (t-2)*64, tid);
                stage_tile(sb + 16384, Ol, 128, gr + q0, (t-2)*64, tid);
                stage_tile(sb + 32768, Oh, 128, gr + k0, (t-2)*64, tid);
                stage_tile(sb + 49152, Ol, 128, gr + k0, (t-2)*64, tid);
            }
            cpa_commit();
        };

        do_stage(0, 0);
        for (int t = 0; t < 4; t++){
            if (t + 1 < 4){ do_stage(t + 1, (t + 1) & 1); cpa_wait1(); }
            else          { cpa_wait0(); }
            __syncthreads();
            uint32_t sm = smb + (t & 1) * 65536;
            #pragma unroll
            for (int ks = 0; ks < 4; ks++){
                const int kk = ks * 16;
                uint32_t ah[4], al[4], th[4], tl[4];
                {
                    uint32_t off = (uint32_t)((w*16 + arow) * 128 + (kk + ak8) * 2);
                    uint32_t sw = off ^ ((off >> 3) & 0x70u);
                    ldsm4(ah, sm + 0     + sw);
                    ldsm4(al, sm + 16384 + sw);
                }
                #pragma unroll
                for (int np = 0; np < 8; np++){
                    uint32_t off = (uint32_t)((np*16 + brow) * 128 + (kk + bk8) * 2);
                    uint32_t sw = off ^ ((off >> 3) & 0x70u);
                    ldsm4(th, sm + 32768 + sw);
                    ldsm4(tl, sm + 49152 + sw);
                    uint32_t b0[2] = {th[0], th[1]}, b1[2] = {th[2], th[3]};
                    uint32_t c0[2] = {tl[0], tl[1]}, c1[2] = {tl[2], tl[3]};
                    mma16816(S[np*2],   ah, b0);
                    mma16816(S[np*2],   ah, c0);
                    mma16816(S[np*2],   al, b0);
                    mma16816(S[np*2+1], ah, b1);
                    mma16816(S[np*2+1], ah, c1);
                    mma16816(S[np*2+1], al, b1);
                }
            }
            __syncthreads();
        }

        float mx0 = -1e30f, mx1 = -1e30f;
        #pragma unroll
        for (int nt = 0; nt < 16; nt++){
            mx0 = fmaxf(mx0, fmaxf(S[nt][0], S[nt][1]));
            mx1 = fmaxf(mx1, fmaxf(S[nt][2], S[nt][3]));
        }
        mx0 = fmaxf(mx0, __shfl_xor_sync(0xffffffffu, mx0, 1));
        mx0 = fmaxf(mx0, __shfl_xor_sync(0xffffffffu, mx0, 2));
        mx1 = fmaxf(mx1, __shfl_xor_sync(0xffffffffu, mx1, 1));
        mx1 = fmaxf(mx1, __shfl_xor_sync(0xffffffffu, mx1, 2));
        float M0 = fmaxf(m0, mx0), M1 = fmaxf(m1, mx1);
        float f0 = __expf(m0 - M0), f1 = __expf(m1 - M1);
        float rs0 = 0.f, rs1 = 0.f;
        #pragma unroll
        for (int nt = 0; nt < 16; nt++){
            float p0 = __expf(S[nt][0] - M0); S[nt][0] = p0; rs0 += p0;
            float p1 = __expf(S[nt][1] - M0); S[nt][1] = p1; rs0 += p1;
            float p2 = __expf(S[nt][2] - M1); S[nt][2] = p2; rs1 += p2;
            float p3 = __expf(S[nt][3] - M1); S[nt][3] = p3; rs1 += p3;
        }
        rs0 += __shfl_xor_sync(0xffffffffu, rs0, 1);
        rs0 += __shfl_xor_sync(0xffffffffu, rs0, 2);
        rs1 += __shfl_xor_sync(0xffffffffu, rs1, 1);
        rs1 += __shfl_xor_sync(0xffffffffu, rs1, 2);
        sum0 = sum0 * f0 + rs0;
        sum1 = sum1 * f1 + rs1;
        m0 = M0; m1 = M1;
        #pragma unroll
        for (int nt = 0; nt < 16; nt++){
            O[nt][0] *= f0; O[nt][1] *= f0; O[nt][2] *= f1; O[nt][3] *= f1;
        }

        stage_tile(smb + 0,     Vh + vbase, NAG, 0, k0,      tid);
        stage_tile(smb + 16384, Vl + vbase, NAG, 0, k0,      tid);
        stage_tile(smb + 32768, Vh + vbase, NAG, 0, k0 + 64, tid);
        stage_tile(smb + 49152, Vl + vbase, NAG, 0, k0 + 64, tid);
        cpa_commit(); cpa_wait0();
        __syncthreads();

        #pragma unroll
        for (int ks = 0; ks < 8; ks++){
            uint32_t aph[4], apl[4];
            {
                float p00 = S[2*ks][0],   p01 = S[2*ks][1];
                float p10 = S[2*ks][2],   p11 = S[2*ks][3];
                float p20 = S[2*ks+1][0], p21 = S[2*ks+1][1];
                float p30 = S[2*ks+1][2], p31 = S[2*ks+1][3];
                aph[0] = packbf2(p00, p01);
                aph[1] = packbf2(p10, p11);
                aph[2] = packbf2(p20, p21);
                aph[3] = packbf2(p30, p31);
                __nv_bfloat162 h0 = *(__nv_bfloat162*)&aph[0];
                __nv_bfloat162 h1 = *(__nv_bfloat162*)&aph[1];
                __nv_bfloat162 h2 = *(__nv_bfloat162*)&aph[2];
                __nv_bfloat162 h3 = *(__nv_bfloat162*)&aph[3];
                apl[0] = packbf2(p00 - __bfloat162float(h0.x), p01 - __bfloat162float(h0.y));
                apl[1] = packbf2(p10 - __bfloat162float(h1.x), p11 - __bfloat162float(h1.y));
                apl[2] = packbf2(p20 - __bfloat162float(h2.x), p21 - __bfloat162float(h2.y));
                apl[3] = packbf2(p30 - __bfloat162float(h3.x), p31 - __bfloat162float(h3.y));
            }
            uint32_t base = (ks < 4) ? smb : smb + 32768;
            uint32_t basl = base + 16384;
            const int kk = (ks & 3) * 16;
            #pragma unroll
            for (int np = 0; np < 8; np++){
                uint32_t off = (uint32_t)((np*16 + brow) * 128 + (kk + bk8) * 2);
                uint32_t sw = off ^ ((off >> 3) & 0x70u);
                uint32_t th[4], tl[4];
                ldsm4(th, base + sw);
                ldsm4(tl, basl + sw);
                uint32_t b0[2] = {th[0], th[1]}, b1[2] = {th[2], th[3]};
                uint32_t c0[2] = {tl[0], tl[1]}, c1[2] = {tl[2], tl[3]};
                mma16816(O[np*2],   aph, b0);
                mma16816(O[np*2],   aph, c0);
                mma16816(O[np*2],   apl, b0);
                mma16816(O[np*2+1], aph, b1);
                mma16816(O[np*2+1], aph, c1);
                mma16816(O[np*2+1], apl, b1);
            }
        }
        __syncthreads();
    }

    float inv0 = 1.f / sum0, inv1 = 1.f / sum1;
    long long r0 = (long long)(gr + q0 + w*16 + lq) * MSG;
    long long r1 = r0 + 8 * MSG;
    #pragma unroll
    for (int nt = 0; nt < 16; nt++){
        int d = nt*8 + (lane & 3)*2;
        __nv_bfloat162 ph, pl;
        bsplit(O[nt][0] * inv0, ph.x, pl.x);
        bsplit(O[nt][1] * inv0, ph.y, pl.y);
        *(__nv_bfloat162*)(aggh + r0 + d) = ph;
        *(__nv_bfloat162*)(aggl + r0 + d) = pl;
        bsplit(O[nt][2] * inv1, ph.x, pl.x);
        bsplit(O[nt][3] * inv1, ph.y, pl.y);
        *(__nv_bfloat162*)(aggh + r1 + d) = ph;
        *(__nv_bfloat162*)(aggl + r1 + d) = pl;
    }
}

// ---------------- packing kernels ----------------
__global__ void pack_obs(const float* __restrict__ obs,
                         __nv_bfloat16* __restrict__ h, __nv_bfloat16* __restrict__ l)
{
    long long i = (long long)blockIdx.x * 256 + threadIdx.x;
    __nv_bfloat16 hh, ll; bsplit(obs[i], hh, ll);
    h[i] = hh; l[i] = ll;
}
__global__ void pack_we(const float* __restrict__ We,
                        __nv_bfloat16* __restrict__ hi, __nv_bfloat16* __restrict__ lo)
{
    int i = blockIdx.x * 256 + threadIdx.x;
    int n = i >> 7, k = i & 127;
    __nv_bfloat16 h, l; bsplit(We[k*256 + n], h, l);
    hi[i] = h; lo[i] = l;
}
__global__ void pack_wcat(const float* __restrict__ Wc, const float* __restrict__ Wn,
                          const float* __restrict__ Wb, const float* __restrict__ Wq,
                          const float* __restrict__ bc, const float* __restrict__ bn,
                          const float* __restrict__ bbp, const float* __restrict__ bq,
                          __nv_bfloat16* __restrict__ hi, __nv_bfloat16* __restrict__ lo,
                          float* __restrict__ bcat)
{
    int i = blockIdx.x * 256 + threadIdx.x;
    int n = i >> 8, k = i & 255;
    float v;
    if (n < 32)       v = Wc[k*32 + n];
    else if (n < 96)  v = Wn[k*64 + (n-32)];
    else if (n < 128) v = Wb[k*32 + (n-96)];
    else              v = Wq[k*128 + (n-128)];
    __nv_bfloat16 h, l; bsplit(v, h, l);
    hi[i] = h; lo[i] = l;
    if (k == 0)
        bcat[n] = (n < 32) ? bc[n] : (n < 96) ? bn[n-32] : (n < 128) ? bbp[n-96] : bq[n-128];
}
__global__ void pack_wkv(const float* __restrict__ Wk, const float* __restrict__ Wv,
                         const float* __restrict__ bk, const float* __restrict__ bv,
                         __nv_bfloat16* __restrict__ hi, __nv_bfloat16* __restrict__ lo,
                         float* __restrict__ bkv)
{
    int i = blockIdx.x * 256 + threadIdx.x;
    int n = i >> 7, k = i & 127;
    float v = (n < 128) ? Wk[k*128 + n] : Wv[k*128 + (n-128)];
    __nv_bfloat16 h, l; bsplit(v, h, l);
    hi[i] = h; lo[i] = l;
    if (k == 0) bkv[n] = (n < 128) ? bk[n] : bv[n-128];
}
__global__ void pack_wp(const float* __restrict__ Wp,
                        __nv_bfloat16* __restrict__ hi, __nv_bfloat16* __restrict__ lo)
{
    int i = blockIdx.x * 256 + threadIdx.x;
    int n = i / 384, k = i % 384;
    __nv_bfloat16 h, l; bsplit(Wp[k*256 + n], h, l);
    hi[i] = h; lo[i] = l;
}
__global__ void pack_vT(const float* __restrict__ v,
                        __nv_bfloat16* __restrict__ hi, __nv_bfloat16* __restrict__ lo)
{
    __shared__ float t[32][33];
    int b = blockIdx.z;
    int k0 = blockIdx.x * 32, d0 = blockIdx.y * 32;
    for (int i = threadIdx.y; i < 32; i += 8)
        t[i][threadIdx.x] = v[((long long)(b*512 + k0 + i))*128 + d0 + threadIdx.x];
    __syncthreads();
    for (int i = threadIdx.y; i < 32; i += 8){
        __nv_bfloat16 h, l; bsplit(t[threadIdx.x][i], h, l);
        long long o = ((long long)(b*128 + d0 + i))*512 + k0 + threadIdx.x;
        hi[o] = h; lo[o] = l;
    }
}

// ---------------- importance + obs norm + scaled obs pack (fused) ----------------
__global__ void impnorm_kernel(const __nv_bfloat16* __restrict__ eh,
                               const __nv_bfloat16* __restrict__ el,
                               const float* __restrict__ obs,
                               const float* __restrict__ Wi,
                               const float* __restrict__ bi,
                               float* __restrict__ imp,
                               __nv_bfloat16* __restrict__ osh,
                               __nv_bfloat16* __restrict__ osl)
{
    int row = blockIdx.x * 8 + threadIdx.y;
    int lane = threadIdx.x;
    const __nv_bfloat16* ph = eh + (long long)row * HID;
    const __nv_bfloat16* pl = el + (long long)row * HID;
    const float* o = obs + (long long)row * OBS;
    float d = 0.f, ss = 0.f;
    float ov[4];
    #pragma unroll
    for (int i = 0; i < HID/32; i++){
        int k = lane + 32*i;
        float e = __bfloat162float(ph[k]) + __bfloat162float(pl[k]);
        d += e * Wi[k];
    }
    #pragma unroll
    for (int i = 0; i < OBS/32; i++){ ov[i] = o[lane + 32*i]; ss += ov[i]*ov[i]; }
    #pragma unroll
    for (int off = 16; off; off >>= 1){
        d  += __shfl_xor_sync(0xffffffffu, d, off);
        ss += __shfl_xor_sync(0xffffffffu, ss, off);
    }
    if (lane == 0)
        imp[row] = 1.f / (1.f + expf(-(d + bi[0])));
    float s = 0.7071067811865476f / (sqrtf(ss) + 1e-8f);
    #pragma unroll
    for (int i = 0; i < OBS/32; i++){
        int k = lane + 32*i;
        __nv_bfloat16 hh, ll; bsplit(ov[i] * s, hh, ll);
        osh[(long long)row * OBS + k] = hh;
        osl[(long long)row * OBS + k] = ll;
    }
}

// ---------------- head ----------------
__global__ void head_kernel(const float* __restrict__ x,
                            const float* __restrict__ Wa,
                            const float* __restrict__ ba,
                            const float* __restrict__ Wcr,
                            const float* __restrict__ bcr,
                            float* __restrict__ out)
{
    int row = blockIdx.x * 8 + threadIdx.y;
    int lane = threadIdx.x;
    const float* xr = x + (long long)row * HID;
    float xv[8];
    #pragma unroll
    for (int i = 0; i < 8; i++) xv[i] = xr[lane + 32*i];
    #pragma unroll
    for (int j = 0; j < 17; j++){
        float p = 0.f;
        #pragma unroll
        for (int i = 0; i < 8; i++){
            int k = lane + 32*i;
            float w = (j < 16) ? Wa[(long long)k * NACT + j] : Wcr[k];
            p += xv[i] * w;
        }
        #pragma unroll
        for (int off = 16; off; off >>= 1) p += __shfl_down_sync(0xffffffffu, p, off);
        if (lane == 0){
            if (j < 16) out[(long long)row * NACT + j] = p + ba[j];
            else        out[(long long)ROWS * NACT + row] = p + bcr[0];
        }
    }
}

// ---------------- launch ----------------
extern "C" void kernel_launch(void* const* d_in, const int* in_sizes, int n_in,
                              void* d_out, int out_size)
{
    const float* obs = (const float*)d_in[0];
    const float* We  = (const float*)d_in[2];   const float* be  = (const float*)d_in[3];
    const float* Wc  = (const float*)d_in[4];   const float* bc  = (const float*)d_in[5];
    const float* Wn  = (const float*)d_in[6];   const float* bn  = (const float*)d_in[7];
    const float* Wb  = (const float*)d_in[8];   const float* bbp = (const float*)d_in[9];
    const float* Wi  = (const float*)d_in[10];  const float* bi  = (const float*)d_in[11];
    const float* Wq  = (const float*)d_in[12];  const float* bq  = (const float*)d_in[13];
    const float* Wk  = (const float*)d_in[14];  const float* bk  = (const float*)d_in[15];
    const float* Wv  = (const float*)d_in[16];  const float* bv  = (const float*)d_in[17];
    const float* Wp  = (const float*)d_in[18];  const float* bp  = (const float*)d_in[19];
    const float* Wa  = (const float*)d_in[20];  const float* ba  = (const float*)d_in[21];
    const float* Wcr = (const float*)d_in[22];  const float* bcr = (const float*)d_in[23];
    float* out = (float*)d_out;

    #define GA(p, sym) cudaGetSymbolAddress((void**)&p, sym)
    __nv_bfloat16 *ench,*encl,*mqh,*mql,*ksh,*ksl,*obh,*obl,*osh,*osl,*vth,*vtl,*agh,*agl;
    __nv_bfloat16 *WeTh,*WeTl,*WcTh,*WcTl,*WkvTh,*WkvTl,*WpTh,*WpTl;
    float *vbuf,*imp,*xb,*bcat,*bkv;
    GA(ench,g_enc_h); GA(encl,g_enc_l); GA(mqh,g_msgq_h); GA(mql,g_msgq_l);
    GA(ksh,g_ks_h); GA(ksl,g_ks_l); GA(obh,g_obs_h); GA(obl,g_obs_l);
    GA(osh,g_obss_h); GA(osl,g_obss_l);
    GA(vth,g_vT_h); GA(vtl,g_vT_l); GA(agh,g_agg_h); GA(agl,g_agg_l);
    GA(vbuf,g_v); GA(imp,g_imp); GA(xb,g_x);
    GA(bcat,g_bcat); GA(bkv,g_bkv);
    GA(WeTh,g_WeT_h); GA(WeTl,g_WeT_l); GA(WcTh,g_WcatT_h); GA(WcTl,g_WcatT_l);
    GA(WkvTh,g_WkvT_h); GA(WkvTl,g_WkvT_l); GA(WpTh,g_WpT_h); GA(WpTl,g_WpT_l);
    #undef GA

    cudaFuncSetAttribute(bf_gemm,      cudaFuncAttributeMaxDynamicSharedMemorySize, SMEM_GEMM);
    cudaFuncSetAttribute(flash_kernel, cudaFuncAttributeMaxDynamicSharedMemorySize, SMEM_FLASH);

    OutD z = {};

    // 1-3: input/weight packs needed by the first two gemms
    pack_obs <<<ROWS*OBS/256, 256>>>(obs, obh, obl);
    pack_we  <<<128, 256>>>(We, WeTh, WeTl);
    pack_wcat<<<256, 256>>>(Wc, Wn, Wb, Wq, bc, bn, bbp, bq, WcTh, WcTl, bcat);

    // 4: enc = relu(obs @ We + be) -> hi/lo   [ncu target slot]
    {
        OutD o = z; o.h = ench; o.l = encl; o.factor = 1.f; o.ldc = 256; o.relu = 1;
        bf_gemm<<<dim3(2,256,1), 512, SMEM_GEMM>>>(obh, obl, OBS, OBS, nullptr, nullptr, 0, OBS,
                                                   WeTh, WeTl, OBS, be, 0, 0, o, o);
    }
    // 5: imp + scaled obs pack (fused)
    impnorm_kernel<<<ROWS/8, dim3(32,8)>>>(ench, encl, obs, Wi, bi, imp, osh, osl);
    // 6: msgq = enc @ Wcat + bcat; Q scaled by imp/sqrt(128)   [ncu target slot]
    {
        OutD o0 = z; o0.h = mqh; o0.l = mql; o0.factor = 1.f; o0.ldc = 256;
        OutD o1 = o0; o1.rowscale = imp; o1.factor = 0.08838834764831845f;
        bf_gemm<<<dim3(2,256,1), 512, SMEM_GEMM>>>(ench, encl, 256, 256, nullptr, nullptr, 0, 256,
                                                   WcTh, WcTl, 256, bcat, 0, 0, o0, o1);
    }
    // 7: pack KV weights
    pack_wkv <<<128, 256>>>(Wk, Wv, bk, bv, WkvTh, WkvTl, bkv);
    // 8: kv: K scaled by imp -> hi/lo; V -> fp32
    {
        OutD o0 = z; o0.h = ksh; o0.l = ksl; o0.rowscale = imp; o0.factor = 1.f; o0.ldc = 128;
        OutD o1 = z; o1.f = vbuf; o1.factor = 1.f; o1.ldc = 128; o1.colsub = 128;
        bf_gemm<<<dim3(2,256,1), 512, SMEM_GEMM>>>(mqh, mql, 256, 128, nullptr, nullptr, 0, 128,
                                                   WkvTh, WkvTl, 128, bkv, 0, 0, o0, o1);
    }
    // 9: V transpose + split
    pack_vT<<<dim3(16,4,BSZ), dim3(32,8)>>>(vbuf, vth, vtl);
    // 10: pack Wp (independent; fills gap before flash)
    pack_wp  <<<384, 256>>>(Wp, WpTh, WpTl);
    // 11: flash attention -> agg hi/lo
    flash_kernel<<<dim3(4, BSZ), 256, SMEM_FLASH>>>(mqh + 128, mql + 128, ksh, ksl,
                                                    osh, osl, vth, vtl, agh, agl);
    // 12: x = relu([enc|agg] @ Wp + bp) -> fp32
    {
        OutD o = z; o.f = xb; o.factor = 1.f; o.ldc = 256; o.relu = 1;
        bf_gemm<<<dim3(2,256,1), 512, SMEM_GEMM>>>(ench, encl, 256, 256, agh, agl, 128, 384,
                                                   WpTh, WpTl, 384, bp, 0, 0, o, o);
    }
    // 13: heads
    head_kernel<<<ROWS/8, dim3(32,8)>>>(xb, Wa, ba, Wcr, bcr, out);
}

// round 11
// speedup vs baseline: 2.8053x; 1.0044x over previous
#include <cuda_runtime.h>
#include <cuda_bf16.h>
#include <stdint.h>
#include <math.h>

#define BSZ 64
#define NAG 512
#define OBS 128
#define HID 256
#define MSG 128
#define NACT 16
#define ROWS (BSZ*NAG)   // 32768

// ---------------- scratch (device globals) ----------------
__device__ __align__(16) __nv_bfloat16 g_enc_h[(size_t)ROWS*HID],  g_enc_l[(size_t)ROWS*HID];
__device__ __align__(16) __nv_bfloat16 g_msgq_h[(size_t)ROWS*256], g_msgq_l[(size_t)ROWS*256]; // 0-127 msg, 128-255 Q(scaled)
__device__ __align__(16) __nv_bfloat16 g_ks_h[(size_t)ROWS*MSG],   g_ks_l[(size_t)ROWS*MSG];   // K scaled by imp
__device__ __align__(16) __nv_bfloat16 g_obs_h[(size_t)ROWS*OBS],  g_obs_l[(size_t)ROWS*OBS];
__device__ __align__(16) __nv_bfloat16 g_obss_h[(size_t)ROWS*OBS], g_obss_l[(size_t)ROWS*OBS]; // scaled sqrt(.5)/nrm
__device__ float g_imp[ROWS];
__device__ __align__(16) __nv_bfloat16 g_vT_h[(size_t)BSZ*MSG*NAG], g_vT_l[(size_t)BSZ*MSG*NAG]; // [b][d][k]
__device__ __align__(16) __nv_bfloat16 g_agg_h[(size_t)ROWS*MSG],  g_agg_l[(size_t)ROWS*MSG];
__device__ float g_x[(size_t)ROWS*HID];
__device__ float g_bcat[256];
__device__ float g_bkv[256];
__device__ __align__(16) __nv_bfloat16 g_WeT_h[256*128],  g_WeT_l[256*128];
__device__ __align__(16) __nv_bfloat16 g_WcatT_h[256*256],g_WcatT_l[256*256];
__device__ __align__(16) __nv_bfloat16 g_WkvT_h[256*128], g_WkvT_l[256*128];
__device__ __align__(16) __nv_bfloat16 g_WpT_h[256*384],  g_WpT_l[256*384];

// ---------------- helpers ----------------
__device__ __forceinline__ void bsplit(float x, __nv_bfloat16& h, __nv_bfloat16& l){
    h = __float2bfloat16(x);
    l = __float2bfloat16(x - __bfloat162float(h));
}
__device__ __forceinline__ uint32_t smem_u32(const void* p){
    uint32_t a;
    asm("{ .reg .u64 t; cvta.to.shared.u64 t, %1; cvt.u32.u64 %0, t; }" : "=r"(a) : "l"(p));
    return a;
}
__device__ __forceinline__ void cpa16(uint32_t d, const void* s){
    asm volatile("cp.async.cg.shared.global [%0], [%1], 16;" :: "r"(d), "l"(s));
}
__device__ __forceinline__ void cpa_commit(){ asm volatile("cp.async.commit_group;" ::: "memory"); }
__device__ __forceinline__ void cpa_wait0(){ asm volatile("cp.async.wait_group 0;" ::: "memory"); }
__device__ __forceinline__ void cpa_wait1(){ asm volatile("cp.async.wait_group 1;" ::: "memory"); }
__device__ __forceinline__ void cpa_wait2(){ asm volatile("cp.async.wait_group 2;" ::: "memory"); }
__device__ __forceinline__ void ldsm4(uint32_t* r, uint32_t a){
    asm volatile("ldmatrix.sync.aligned.m8n8.x4.shared.b16 {%0,%1,%2,%3}, [%4];"
        : "=r"(r[0]), "=r"(r[1]), "=r"(r[2]), "=r"(r[3]) : "r"(a));
}
__device__ __forceinline__ void mma16816(float* d, const uint32_t* a, const uint32_t* b){
    asm volatile(
        "mma.sync.aligned.m16n8k16.row.col.f32.bf16.bf16.f32 "
        "{%0,%1,%2,%3}, {%4,%5,%6,%7}, {%8,%9}, {%0,%1,%2,%3};"
        : "+f"(d[0]), "+f"(d[1]), "+f"(d[2]), "+f"(d[3])
        : "r"(a[0]), "r"(a[1]), "r"(a[2]), "r"(a[3]), "r"(b[0]), "r"(b[1]));
}
__device__ __forceinline__ uint32_t packbf2(float x, float y){
    __nv_bfloat162 p; p.x = __float2bfloat16(x); p.y = __float2bfloat16(y);
    return *(uint32_t*)&p;
}

// stage one [128 rows][64 k] bf16 tile, SW128 swizzle, cp.async — 256-thread version
__device__ __forceinline__ void stage_tile(uint32_t smA, const __nv_bfloat16* g, int ld,
                                           int row0, int k0, int tid)
{
    int r = tid >> 1, s0 = (tid & 1) * 4;
    const __nv_bfloat16* src = g + (long long)(row0 + r) * ld + k0 + s0 * 8;
    uint32_t offb = (uint32_t)(r * 128 + s0 * 16);
    #pragma unroll
    for (int j = 0; j < 4; j++){
        uint32_t off = offb + j * 16;
        uint32_t sw = off ^ ((off >> 3) & 0x70u);
        cpa16(smA + sw, src + j * 8);
    }
}
// 512-thread version (4 threads per row, 2x16B each)
__device__ __forceinline__ void stage_tile512(uint32_t smA, const __nv_bfloat16* g, int ld,
                                              int row0, int k0, int tid)
{
    int r = tid >> 2, s0 = (tid & 3) * 2;
    const __nv_bfloat16* src = g + (long long)(row0 + r) * ld + k0 + s0 * 8;
    uint32_t offb = (uint32_t)(r * 128 + s0 * 16);
    #pragma unroll
    for (int j = 0; j < 2; j++){
        uint32_t off = offb + j * 16;
        uint32_t sw = off ^ ((off >> 3) & 0x70u);
        cpa16(smA + sw, src + j * 8);
    }
}

struct OutD {
    float* f;
    __nv_bfloat16* h;
    __nv_bfloat16* l;
    const float* rowscale;
    float factor;
    int ldc;
    int colsub;
    int relu;
    int vtrans;      // write transposed into [b][d][512] hi/lo
    long long sC;
};

#define SMEM_FLASH 196608   // 2 S-stages (128KB) + V (64KB)
#define SMEM_GEMM  196608   // 3 stages x 64KB

// ================= dense GEMM: 512 threads, 16 warps, warp 32x32, block 128x128, 3-stage =================
__global__ __launch_bounds__(512, 1)
void bf_gemm(const __nv_bfloat16* __restrict__ Ah1, const __nv_bfloat16* __restrict__ Al1, int lda1, int K1,
             const __nv_bfloat16* __restrict__ Ah2, const __nv_bfloat16* __restrict__ Al2, int lda2, int Ktot,
             const __nv_bfloat16* __restrict__ Bh,  const __nv_bfloat16* __restrict__ Bl,  int ldb,
             const float* __restrict__ bias, long long sA1, long long sB,
             OutD o0, OutD o1)
{
    extern __shared__ __align__(1024) char smraw[];
    const uint32_t smb = smem_u32(smraw);
    const int tid = threadIdx.x, wid = tid >> 5, lane = tid & 31;
    const int wm = wid >> 2, wn = wid & 3;
    const int row0 = blockIdx.y * 128, col0 = blockIdx.x * 128;
    const int z = blockIdx.z;
    Ah1 += (long long)z * sA1; Al1 += (long long)z * sA1;
    Bh  += (long long)z * sB;  Bl  += (long long)z * sB;

    const int arow = ((lane >> 3) & 1) * 8 + (lane & 7);
    const int ak8  = ((lane >> 4) & 1) * 8;
    const int brow = ((lane >> 4) & 1) * 8 + (lane & 7);
    const int bk8  = ((lane >> 3) & 1) * 8;

    float acc[2][4][4];
    #pragma unroll
    for (int i = 0; i < 2; i++)
        #pragma unroll
        for (int j = 0; j < 4; j++)
            #pragma unroll
            for (int k = 0; k < 4; k++) acc[i][j][k] = 0.f;

    const int T = Ktot / 64;
    auto do_stage = [&](int t, int buf){
        int k0 = t * 64;
        const __nv_bfloat16 *h, *l; int ld, ka;
        if (k0 < K1){ h = Ah1; l = Al1; ld = lda1; ka = k0; }
        else        { h = Ah2; l = Al2; ld = lda2; ka = k0 - K1; }
        uint32_t sb = smb + buf * 65536;
        stage_tile512(sb + 0,     h,  ld,  row0, ka, tid);
        stage_tile512(sb + 16384, l,  ld,  row0, ka, tid);
        stage_tile512(sb + 32768, Bh, ldb, col0, k0, tid);
        stage_tile512(sb + 49152, Bl, ldb, col0, k0, tid);
        cpa_commit();
    };

    do_stage(0, 0);
    if (T > 1) do_stage(1, 1);
    for (int t = 0; t < T; t++){
        if (t + 2 < T) do_stage(t + 2, (t + 2) % 3);
        int lastIssued = (T - 1 < t + 2) ? T - 1 : t + 2;
        int inflight = lastIssued - t + 1;
        if (inflight >= 3)      cpa_wait2();
        else if (inflight == 2) cpa_wait1();
        else                    cpa_wait0();
        __syncthreads();
        uint32_t sm = smb + (t % 3) * 65536;
        #pragma unroll
        for (int ks = 0; ks < 4; ks++){
            const int kk = ks * 16;
            uint32_t ah[2][4], al[2][4], bh[4][2], bl[4][2], t4[4];
            #pragma unroll
            for (int mt = 0; mt < 2; mt++){
                uint32_t off = (uint32_t)((wm*32 + mt*16 + arow) * 128 + (kk + ak8) * 2);
                uint32_t sw = off ^ ((off >> 3) & 0x70u);
                ldsm4(ah[mt], sm + 0     + sw);
                ldsm4(al[mt], sm + 16384 + sw);
            }
            #pragma unroll
            for (int np = 0; np < 2; np++){
                uint32_t off = (uint32_t)((wn*32 + np*16 + brow) * 128 + (kk + bk8) * 2);
                uint32_t sw = off ^ ((off >> 3) & 0x70u);
                ldsm4(t4, sm + 32768 + sw);
                bh[np*2][0]=t4[0]; bh[np*2][1]=t4[1]; bh[np*2+1][0]=t4[2]; bh[np*2+1][1]=t4[3];
                ldsm4(t4, sm + 49152 + sw);
                bl[np*2][0]=t4[0]; bl[np*2][1]=t4[1]; bl[np*2+1][0]=t4[2]; bl[np*2+1][1]=t4[3];
            }
            #pragma unroll
            for (int mt = 0; mt < 2; mt++)
                #pragma unroll
                for (int nt = 0; nt < 4; nt++){
                    mma16816(acc[mt][nt], ah[mt], bh[nt]);
                    mma16816(acc[mt][nt], ah[mt], bl[nt]);
                    mma16816(acc[mt][nt], al[mt], bh[nt]);
                }
        }
        __syncthreads();
    }

    const OutD& od = (blockIdx.x == 0) ? o0 : o1;
    const int lq = lane >> 2, le = (lane & 3) * 2;
    #pragma unroll
    for (int mt = 0; mt < 2; mt++){
        int gr0 = row0 + wm*32 + mt*16 + lq;
        float rs0 = od.rowscale ? od.rowscale[gr0]   * od.factor : od.factor;
        float rs1 = od.rowscale ? od.rowscale[gr0+8] * od.factor : od.factor;
        #pragma unroll
        for (int nt = 0; nt < 4; nt++){
            int gc = col0 + wn*32 + nt*8 + le;
            float b0 = bias ? bias[gc] : 0.f, b1 = bias ? bias[gc+1] : 0.f;
            float v00 = (acc[mt][nt][0] + b0) * rs0, v01 = (acc[mt][nt][1] + b1) * rs0;
            float v10 = (acc[mt][nt][2] + b0) * rs1, v11 = (acc[mt][nt][3] + b1) * rs1;
            if (od.relu){
                v00 = fmaxf(v00, 0.f); v01 = fmaxf(v01, 0.f);
                v10 = fmaxf(v10, 0.f); v11 = fmaxf(v11, 0.f);
            }
            if (od.vtrans){
                // write into vT [b][d][512], d = gc - colsub, k = token index
                int d = gc - od.colsub;
                int bidx = gr0 >> 9, kt0 = gr0 & 511;
                long long o00 = ((long long)bidx * MSG + d) * NAG + kt0;
                __nv_bfloat16 h, l;
                bsplit(v00, h, l); od.h[o00]           = h; od.l[o00]           = l;
                bsplit(v01, h, l); od.h[o00 + NAG]     = h; od.l[o00 + NAG]     = l;
                bsplit(v10, h, l); od.h[o00 + 8]       = h; od.l[o00 + 8]       = l;
                bsplit(v11, h, l); od.h[o00 + NAG + 8] = h; od.l[o00 + NAG + 8] = l;
                continue;
            }
            long long i0 = od.sC * z + (long long)gr0 * od.ldc + (gc - od.colsub);
            long long i1 = od.sC * z + (long long)(gr0 + 8) * od.ldc + (gc - od.colsub);
            if (od.f){
                *(float2*)(od.f + i0) = make_float2(v00, v01);
                *(float2*)(od.f + i1) = make_float2(v10, v11);
            }
            if (od.h){
                __nv_bfloat162 ph, pl;
                bsplit(v00, ph.x, pl.x); bsplit(v01, ph.y, pl.y);
                *(__nv_bfloat162*)(od.h + i0) = ph; *(__nv_bfloat162*)(od.l + i0) = pl;
                bsplit(v10, ph.x, pl.x); bsplit(v11, ph.y, pl.y);
                *(__nv_bfloat162*)(od.h + i1) = ph; *(__nv_bfloat162*)(od.l + i1) = pl;
            }
        }
    }
}

// ================= flash attention: 256 threads, V prefetched under S phase =================
__global__ __launch_bounds__(256, 1)
void flash_kernel(const __nv_bfloat16* __restrict__ Qh, const __nv_bfloat16* __restrict__ Ql,
                  const __nv_bfloat16* __restrict__ Kh, const __nv_bfloat16* __restrict__ Kl,
                  const __nv_bfloat16* __restrict__ Oh, const __nv_bfloat16* __restrict__ Ol,
                  const __nv_bfloat16* __restrict__ Vh, const __nv_bfloat16* __restrict__ Vl,
                  __nv_bfloat16* __restrict__ aggh, __nv_bfloat16* __restrict__ aggl)
{
    extern __shared__ __align__(1024) char smraw[];
    const uint32_t smb = smem_u32(smraw);
    const uint32_t smv = smb + 131072;           // V region: 64KB
    const int tid = threadIdx.x, w = tid >> 5, lane = tid & 31;
    const int q0 = blockIdx.x * 128;
    const int b = blockIdx.y;
    const int gr = b * NAG;
    const long long vbase = (long long)b * MSG * NAG;

    const int arow = ((lane >> 3) & 1) * 8 + (lane & 7);
    const int ak8  = ((lane >> 4) & 1) * 8;
    const int brow = ((lane >> 4) & 1) * 8 + (lane & 7);
    const int bk8  = ((lane >> 3) & 1) * 8;
    const int lq = lane >> 2;

    float O[16][4];
    #pragma unroll
    for (int nt = 0; nt < 16; nt++)
        #pragma unroll
        for (int j = 0; j < 4; j++) O[nt][j] = 0.f;
    float m0 = -1e30f, m1 = -1e30f, sum0 = 0.f, sum1 = 0.f;

    for (int kt = 0; kt < 4; kt++){
        const int k0 = kt * 128;

        float S[16][4];
        #pragma unroll
        for (int nt = 0; nt < 16; nt++)
            #pragma unroll
            for (int j = 0; j < 4; j++) S[nt][j] = 0.f;

        auto do_stage = [&](int t, int buf){
            uint32_t sb = smb + buf * 65536;
            if (t < 2){
                stage_tile(sb + 0,     Qh, 256, gr + q0, t*64, tid);
                stage_tile(sb + 16384, Ql, 256, gr + q0, t*64, tid);
                stage_tile(sb + 32768, Kh, 128, gr + k0, t*64, tid);
                stage_tile(sb + 49152, Kl, 128, gr + k0, t*64, tid);
            } else {
                stage_tile(sb + 0,     Oh, 128, gr + q0, (t-2)*64, tid);
                stage_tile(sb + 16384, Ol, 128, gr + q0, (t-2)*64, tid);
                stage_tile(sb + 32768, Oh, 128, gr + k0, (t-2)*64, tid);
                stage_tile(sb + 49152, Ol, 128, gr + k0, (t-2)*64, tid);
            }
            cpa_commit();
        };

        // S0 committed first; S1 + V committed at t=0 so V hides under S compute
        do_stage(0, 0);
        for (int t = 0; t < 4; t++){
            if (t == 0){
                do_stage(1, 1);
                // V prefetch for this kt: 4 tiles into dedicated region
                stage_tile(smv + 0,     Vh + vbase, NAG, 0, k0,      tid);
                stage_tile(smv + 16384, Vl + vbase, NAG, 0, k0,      tid);
                stage_tile(smv + 32768, Vh + vbase, NAG, 0, k0 + 64, tid);
                stage_tile(smv + 49152, Vl + vbase, NAG, 0, k0 + 64, tid);
                cpa_commit();
            } else if (t + 1 < 4){
                do_stage(t + 1, (t + 1) & 1);
            }
            // wait schedule: {2,2,1,0} — S(t) ready; V forced complete by t=2
            if (t <= 1)      cpa_wait2();
            else if (t == 2) cpa_wait1();
            else             cpa_wait0();
            __syncthreads();
            uint32_t sm = smb + (t & 1) * 65536;
            #pragma unroll
            for (int ks = 0; ks < 4; ks++){
                const int kk = ks * 16;
                uint32_t ah[4], al[4], th[4], tl[4];
                {
                    uint32_t off = (uint32_t)((w*16 + arow) * 128 + (kk + ak8) * 2);
                    uint32_t sw = off ^ ((off >> 3) & 0x70u);
                    ldsm4(ah, sm + 0     + sw);
                    ldsm4(al, sm + 16384 + sw);
                }
                #pragma unroll
                for (int np = 0; np < 8; np++){
                    uint32_t off = (uint32_t)((np*16 + brow) * 128 + (kk + bk8) * 2);
                    uint32_t sw = off ^ ((off >> 3) & 0x70u);
                    ldsm4(th, sm + 32768 + sw);
                    ldsm4(tl, sm + 49152 + sw);
                    uint32_t b0[2] = {th[0], th[1]}, b1[2] = {th[2], th[3]};
                    uint32_t c0[2] = {tl[0], tl[1]}, c1[2] = {tl[2], tl[3]};
                    mma16816(S[np*2],   ah, b0);
                    mma16816(S[np*2],   ah, c0);
                    mma16816(S[np*2],   al, b0);
                    mma16816(S[np*2+1], ah, b1);
                    mma16816(S[np*2+1], ah, c1);
                    mma16816(S[np*2+1], al, b1);
                }
            }
            __syncthreads();
        }

        // ---- online softmax ----
        float mx0 = -1e30f, mx1 = -1e30f;
        #pragma unroll
        for (int nt = 0; nt < 16; nt++){
            mx0 = fmaxf(mx0, fmaxf(S[nt][0], S[nt][1]));
            mx1 = fmaxf(mx1, fmaxf(S[nt][2], S[nt][3]));
        }
        mx0 = fmaxf(mx0, __shfl_xor_sync(0xffffffffu, mx0, 1));
        mx0 = fmaxf(mx0, __shfl_xor_sync(0xffffffffu, mx0, 2));
        mx1 = fmaxf(mx1, __shfl_xor_sync(0xffffffffu, mx1, 1));
        mx1 = fmaxf(mx1, __shfl_xor_sync(0xffffffffu, mx1, 2));
        float M0 = fmaxf(m0, mx0), M1 = fmaxf(m1, mx1);
        float f0 = __expf(m0 - M0), f1 = __expf(m1 - M1);
        float rs0 = 0.f, rs1 = 0.f;
        #pragma unroll
        for (int nt = 0; nt < 16; nt++){
            float p0 = __expf(S[nt][0] - M0); S[nt][0] = p0; rs0 += p0;
            float p1 = __expf(S[nt][1] - M0); S[nt][1] = p1; rs0 += p1;
            float p2 = __expf(S[nt][2] - M1); S[nt][2] = p2; rs1 += p2;
            float p3 = __expf(S[nt][3] - M1); S[nt][3] = p3; rs1 += p3;
        }
        rs0 += __shfl_xor_sync(0xffffffffu, rs0, 1);
        rs0 += __shfl_xor_sync(0xffffffffu, rs0, 2);
        rs1 += __shfl_xor_sync(0xffffffffu, rs1, 1);
        rs1 += __shfl_xor_sync(0xffffffffu, rs1, 2);
        sum0 = sum0 * f0 + rs0;
        sum1 = sum1 * f1 + rs1;
        m0 = M0; m1 = M1;
        #pragma unroll
        for (int nt = 0; nt < 16; nt++){
            O[nt][0] *= f0; O[nt][1] *= f0; O[nt][2] *= f1; O[nt][3] *= f1;
        }

        // ---- P·V: V already resident in smv ----
        #pragma unroll
        for (int ks = 0; ks < 8; ks++){
            uint32_t aph[4], apl[4];
            {
                float p00 = S[2*ks][0],   p01 = S[2*ks][1];
                float p10 = S[2*ks][2],   p11 = S[2*ks][3];
                float p20 = S[2*ks+1][0], p21 = S[2*ks+1][1];
                float p30 = S[2*ks+1][2], p31 = S[2*ks+1][3];
                aph[0] = packbf2(p00, p01);
                aph[1] = packbf2(p10, p11);
                aph[2] = packbf2(p20, p21);
                aph[3] = packbf2(p30, p31);
                __nv_bfloat162 h0 = *(__nv_bfloat162*)&aph[0];
                __nv_bfloat162 h1 = *(__nv_bfloat162*)&aph[1];
                __nv_bfloat162 h2 = *(__nv_bfloat162*)&aph[2];
                __nv_bfloat162 h3 = *(__nv_bfloat162*)&aph[3];
                apl[0] = packbf2(p00 - __bfloat162float(h0.x), p01 - __bfloat162float(h0.y));
                apl[1] = packbf2(p10 - __bfloat162float(h1.x), p11 - __bfloat162float(h1.y));
                apl[2] = packbf2(p20 - __bfloat162float(h2.x), p21 - __bfloat162float(h2.y));
                apl[3] = packbf2(p30 - __bfloat162float(h3.x), p31 - __bfloat162float(h3.y));
            }
            uint32_t base = (ks < 4) ? smv : smv + 32768;
            uint32_t basl = base + 16384;
            const int kk = (ks & 3) * 16;
            #pragma unroll
            for (int np = 0; np < 8; np++){
                uint32_t off = (uint32_t)((np*16 + brow) * 128 + (kk + bk8) * 2);
                uint32_t sw = off ^ ((off >> 3) & 0x70u);
                uint32_t th[4], tl[4];
                ldsm4(th, base + sw);
                ldsm4(tl, basl + sw);
                uint32_t b0[2] = {th[0], th[1]}, b1[2] = {th[2], th[3]};
                uint32_t c0[2] = {tl[0], tl[1]}, c1[2] = {tl[2], tl[3]};
                mma16816(O[np*2],   aph, b0);
                mma16816(O[np*2],   aph, c0);
                mma16816(O[np*2],   apl, b0);
                mma16816(O[np*2+1], aph, b1);
                mma16816(O[np*2+1], aph, c1);
                mma16816(O[np*2+1], apl, b1);
            }
        }
        __syncthreads();
    }

    float inv0 = 1.f / sum0, inv1 = 1.f / sum1;
    long long r0 = (long long)(gr + q0 + w*16 + lq) * MSG;
    long long r1 = r0 + 8 * MSG;
    #pragma unroll
    for (int nt = 0; nt < 16; nt++){
        int d = nt*8 + (lane & 3)*2;
        __nv_bfloat162 ph, pl;
        bsplit(O[nt][0] * inv0, ph.x, pl.x);
        bsplit(O[nt][1] * inv0, ph.y, pl.y);
        *(__nv_bfloat162*)(aggh + r0 + d) = ph;
        *(__nv_bfloat162*)(aggl + r0 + d) = pl;
        bsplit(O[nt][2] * inv1, ph.x, pl.x);
        bsplit(O[nt][3] * inv1, ph.y, pl.y);
        *(__nv_bfloat162*)(aggh + r1 + d) = ph;
        *(__nv_bfloat162*)(aggl + r1 + d) = pl;
    }
}

// ---------------- packing kernels ----------------
__global__ void pack_obs(const float* __restrict__ obs,
                         __nv_bfloat16* __restrict__ h, __nv_bfloat16* __restrict__ l)
{
    long long i = (long long)blockIdx.x * 256 + threadIdx.x;
    __nv_bfloat16 hh, ll; bsplit(obs[i], hh, ll);
    h[i] = hh; l[i] = ll;
}
__global__ void pack_we(const float* __restrict__ We,
                        __nv_bfloat16* __restrict__ hi, __nv_bfloat16* __restrict__ lo)
{
    int i = blockIdx.x * 256 + threadIdx.x;
    int n = i >> 7, k = i & 127;
    __nv_bfloat16 h, l; bsplit(We[k*256 + n], h, l);
    hi[i] = h; lo[i] = l;
}
__global__ void pack_wcat(const float* __restrict__ Wc, const float* __restrict__ Wn,
                          const float* __restrict__ Wb, const float* __restrict__ Wq,
                          const float* __restrict__ bc, const float* __restrict__ bn,
                          const float* __restrict__ bbp, const float* __restrict__ bq,
                          __nv_bfloat16* __restrict__ hi, __nv_bfloat16* __restrict__ lo,
                          float* __restrict__ bcat)
{
    int i = blockIdx.x * 256 + threadIdx.x;
    int n = i >> 8, k = i & 255;
    float v;
    if (n < 32)       v = Wc[k*32 + n];
    else if (n < 96)  v = Wn[k*64 + (n-32)];
    else if (n < 128) v = Wb[k*32 + (n-96)];
    else              v = Wq[k*128 + (n-128)];
    __nv_bfloat16 h, l; bsplit(v, h, l);
    hi[i] = h; lo[i] = l;
    if (k == 0)
        bcat[n] = (n < 32) ? bc[n] : (n < 96) ? bn[n-32] : (n < 128) ? bbp[n-96] : bq[n-128];
}
__global__ void pack_wkv(const float* __restrict__ Wk, const float* __restrict__ Wv,
                         const float* __restrict__ bk, const float* __restrict__ bv,
                         __nv_bfloat16* __restrict__ hi, __nv_bfloat16* __restrict__ lo,
                         float* __restrict__ bkv)
{
    int i = blockIdx.x * 256 + threadIdx.x;
    int n = i >> 7, k = i & 127;
    float v = (n < 128) ? Wk[k*128 + n] : Wv[k*128 + (n-128)];
    __nv_bfloat16 h, l; bsplit(v, h, l);
    hi[i] = h; lo[i] = l;
    if (k == 0) bkv[n] = (n < 128) ? bk[n] : bv[n-128];
}
__global__ void pack_wp(const float* __restrict__ Wp,
                        __nv_bfloat16* __restrict__ hi, __nv_bfloat16* __restrict__ lo)
{
    int i = blockIdx.x * 256 + threadIdx.x;
    int n = i / 384, k = i % 384;
    __nv_bfloat16 h, l; bsplit(Wp[k*256 + n], h, l);
    hi[i] = h; lo[i] = l;
}

// ---------------- importance + obs norm + scaled obs pack (fused) ----------------
__global__ void impnorm_kernel(const __nv_bfloat16* __restrict__ eh,
                               const __nv_bfloat16* __restrict__ el,
                               const float* __restrict__ obs,
                               const float* __restrict__ Wi,
                               const float* __restrict__ bi,
                               float* __restrict__ imp,
                               __nv_bfloat16* __restrict__ osh,
                               __nv_bfloat16* __restrict__ osl)
{
    int row = blockIdx.x * 8 + threadIdx.y;
    int lane = threadIdx.x;
    const __nv_bfloat16* ph = eh + (long long)row * HID;
    const __nv_bfloat16* pl = el + (long long)row * HID;
    const float* o = obs + (long long)row * OBS;
    float d = 0.f, ss = 0.f;
    float ov[4];
    #pragma unroll
    for (int i = 0; i < HID/32; i++){
        int k = lane + 32*i;
        float e = __bfloat162float(ph[k]) + __bfloat162float(pl[k]);
        d += e * Wi[k];
    }
    #pragma unroll
    for (int i = 0; i < OBS/32; i++){ ov[i] = o[lane + 32*i]; ss += ov[i]*ov[i]; }
    #pragma unroll
    for (int off = 16; off; off >>= 1){
        d  += __shfl_xor_sync(0xffffffffu, d, off);
        ss += __shfl_xor_sync(0xffffffffu, ss, off);
    }
    if (lane == 0)
        imp[row] = 1.f / (1.f + expf(-(d + bi[0])));
    float s = 0.7071067811865476f / (sqrtf(ss) + 1e-8f);
    #pragma unroll
    for (int i = 0; i < OBS/32; i++){
        int k = lane + 32*i;
        __nv_bfloat16 hh, ll; bsplit(ov[i] * s, hh, ll);
        osh[(long long)row * OBS + k] = hh;
        osl[(long long)row * OBS + k] = ll;
    }
}

// ---------------- head ----------------
__global__ void head_kernel(const float* __restrict__ x,
                            const float* __restrict__ Wa,
                            const float* __restrict__ ba,
                            const float* __restrict__ Wcr,
                            const float* __restrict__ bcr,
                            float* __restrict__ out)
{
    int row = blockIdx.x * 8 + threadIdx.y;
    int lane = threadIdx.x;
    const float* xr = x + (long long)row * HID;
    float xv[8];
    #pragma unroll
    for (int i = 0; i < 8; i++) xv[i] = xr[lane + 32*i];
    #pragma unroll
    for (int j = 0; j < 17; j++){
        float p = 0.f;
        #pragma unroll
        for (int i = 0; i < 8; i++){
            int k = lane + 32*i;
            float w = (j < 16) ? Wa[(long long)k * NACT + j] : Wcr[k];
            p += xv[i] * w;
        }
        #pragma unroll
        for (int off = 16; off; off >>= 1) p += __shfl_down_sync(0xffffffffu, p, off);
        if (lane == 0){
            if (j < 16) out[(long long)row * NACT + j] = p + ba[j];
            else        out[(long long)ROWS * NACT + row] = p + bcr[0];
        }
    }
}

// ---------------- launch ----------------
extern "C" void kernel_launch(void* const* d_in, const int* in_sizes, int n_in,
                              void* d_out, int out_size)
{
    const float* obs = (const float*)d_in[0];
    const float* We  = (const float*)d_in[2];   const float* be  = (const float*)d_in[3];
    const float* Wc  = (const float*)d_in[4];   const float* bc  = (const float*)d_in[5];
    const float* Wn  = (const float*)d_in[6];   const float* bn  = (const float*)d_in[7];
    const float* Wb  = (const float*)d_in[8];   const float* bbp = (const float*)d_in[9];
    const float* Wi  = (const float*)d_in[10];  const float* bi  = (const float*)d_in[11];
    const float* Wq  = (const float*)d_in[12];  const float* bq  = (const float*)d_in[13];
    const float* Wk  = (const float*)d_in[14];  const float* bk  = (const float*)d_in[15];
    const float* Wv  = (const float*)d_in[16];  const float* bv  = (const float*)d_in[17];
    const float* Wp  = (const float*)d_in[18];  const float* bp  = (const float*)d_in[19];
    const float* Wa  = (const float*)d_in[20];  const float* ba  = (const float*)d_in[21];
    const float* Wcr = (const float*)d_in[22];  const float* bcr = (const float*)d_in[23];
    float* out = (float*)d_out;

    #define GA(p, sym) cudaGetSymbolAddress((void**)&p, sym)
    __nv_bfloat16 *ench,*encl,*mqh,*mql,*ksh,*ksl,*obh,*obl,*osh,*osl,*vth,*vtl,*agh,*agl;
    __nv_bfloat16 *WeTh,*WeTl,*WcTh,*WcTl,*WkvTh,*WkvTl,*WpTh,*WpTl;
    float *imp,*xb,*bcat,*bkv;
    GA(ench,g_enc_h); GA(encl,g_enc_l); GA(mqh,g_msgq_h); GA(mql,g_msgq_l);
    GA(ksh,g_ks_h); GA(ksl,g_ks_l); GA(obh,g_obs_h); GA(obl,g_obs_l);
    GA(osh,g_obss_h); GA(osl,g_obss_l);
    GA(vth,g_vT_h); GA(vtl,g_vT_l); GA(agh,g_agg_h); GA(agl,g_agg_l);
    GA(imp,g_imp); GA(xb,g_x);
    GA(bcat,g_bcat); GA(bkv,g_bkv);
    GA(WeTh,g_WeT_h); GA(WeTl,g_WeT_l); GA(WcTh,g_WcatT_h); GA(WcTl,g_WcatT_l);
    GA(WkvTh,g_WkvT_h); GA(WkvTl,g_WkvT_l); GA(WpTh,g_WpT_h); GA(WpTl,g_WpT_l);
    #undef GA

    cudaFuncSetAttribute(bf_gemm,      cudaFuncAttributeMaxDynamicSharedMemorySize, SMEM_GEMM);
    cudaFuncSetAttribute(flash_kernel, cudaFuncAttributeMaxDynamicSharedMemorySize, SMEM_FLASH);

    OutD z = {};

    // 1-3: input/weight packs for first two gemms
    pack_obs <<<ROWS*OBS/256, 256>>>(obs, obh, obl);
    pack_we  <<<128, 256>>>(We, WeTh, WeTl);
    pack_wcat<<<256, 256>>>(Wc, Wn, Wb, Wq, bc, bn, bbp, bq, WcTh, WcTl, bcat);

    // 4: enc = relu(obs @ We + be) -> hi/lo
    {
        OutD o = z; o.h = ench; o.l = encl; o.factor = 1.f; o.ldc = 256; o.relu = 1;
        bf_gemm<<<dim3(2,256,1), 512, SMEM_GEMM>>>(obh, obl, OBS, OBS, nullptr, nullptr, 0, OBS,
                                                   WeTh, WeTl, OBS, be, 0, 0, o, o);
    }
    // 5: imp + scaled obs pack (fused)
    impnorm_kernel<<<ROWS/8, dim3(32,8)>>>(ench, encl, obs, Wi, bi, imp, osh, osl);
    // 6: msgq = enc @ Wcat + bcat; Q scaled by imp/sqrt(128)   [ncu slot target]
    {
        OutD o0 = z; o0.h = mqh; o0.l = mql; o0.factor = 1.f; o0.ldc = 256;
        OutD o1 = o0; o1.rowscale = imp; o1.factor = 0.08838834764831845f;
        bf_gemm<<<dim3(2,256,1), 512, SMEM_GEMM>>>(ench, encl, 256, 256, nullptr, nullptr, 0, 256,
                                                   WcTh, WcTl, 256, bcat, 0, 0, o0, o1);
    }
    // 7: pack KV weights
    pack_wkv <<<128, 256>>>(Wk, Wv, bk, bv, WkvTh, WkvTl, bkv);
    // 8: kv: K scaled by imp -> hi/lo; V -> transposed vT hi/lo (direct, no pack_vT)
    {
        OutD o0 = z; o0.h = ksh; o0.l = ksl; o0.rowscale = imp; o0.factor = 1.f; o0.ldc = 128;
        OutD o1 = z; o1.h = vth; o1.l = vtl; o1.factor = 1.f; o1.colsub = 128; o1.vtrans = 1;
        bf_gemm<<<dim3(2,256,1), 512, SMEM_GEMM>>>(mqh, mql, 256, 128, nullptr, nullptr, 0, 128,
                                                   WkvTh, WkvTl, 128, bkv, 0, 0, o0, o1);
    }
    // 9: pack Wp (independent; fills gap before flash)
    pack_wp  <<<384, 256>>>(Wp, WpTh, WpTl);
    // 10: flash attention -> agg hi/lo
    flash_kernel<<<dim3(4, BSZ), 256, SMEM_FLASH>>>(mqh + 128, mql + 128, ksh, ksl,
                                                    osh, osl, vth, vtl, agh, agl);
    // 11: x = relu([enc|agg] @ Wp + bp) -> fp32
    {
        OutD o = z; o.f = xb; o.factor = 1.f; o.ldc = 256; o.relu = 1;
        bf_gemm<<<dim3(2,256,1), 512, SMEM_GEMM>>>(ench, encl, 256, 256, agh, agl, 128, 384,
                                                   WpTh, WpTl, 384, bp, 0, 0, o, o);
    }
    // 12: heads
    head_kernel<<<ROWS/8, dim3(32,8)>>>(xb, Wa, ba, Wcr, bcr, out);
}